// round 10
// baseline (speedup 1.0000x reference)
#include <cuda_runtime.h>
#include <cuda_bf16.h>
#include <cstdint>

// ---------------------------------------------------------------------------
// SentimentGAT on GB300 (sm_103 baseline PTX): bf16x3 mma.sync GEMMs +
// CSR-gather attention. Layer-1 GEMM: BK=64 single-barrier pipeline with
// in-shadow fp32->bf16 hi/lo convert; MMAs scheduled as 3 independent passes.
// ---------------------------------------------------------------------------

#define GAT_N   30000
#define GAT_Mp  30080               // 235 * 128
#define GAT_E   480000
#define GAT_DIN 5000
#define GAT_K1P 5056                // 79 * 64 (padded K stride for W1^T)

// ---- fp32 scratch ----
__device__ float g_hA[GAT_N * 256];
__device__ float g_h3[GAT_N * 64];
__device__ float g_es[GAT_N * 4];
__device__ float g_ed[GAT_N * 4];

// ---- CSR ----
__device__ int g_rowoff[GAT_N + 1];
__device__ int g_cursor[GAT_N];
__device__ int g_csrsrc[GAT_E];

// ---- bf16 hi/lo scratch ----
__device__ __align__(128) __nv_bfloat16 g_Ah[(size_t)GAT_Mp * 256];
__device__ __align__(128) __nv_bfloat16 g_Al[(size_t)GAT_Mp * 256];
__device__ __align__(128) __nv_bfloat16 g_Bh[256 * GAT_K1P];
__device__ __align__(128) __nv_bfloat16 g_Bl[256 * GAT_K1P];

// ===========================================================================
// low-level helpers
// ===========================================================================
#define SWZ(o) ((o) ^ (((o) >> 3) & 0x70))

__device__ __forceinline__ uint32_t smem_u32(const void* p) {
    uint32_t a;
    asm("{ .reg .u64 t; cvta.to.shared.u64 t, %1; cvt.u32.u64 %0, t; }"
        : "=r"(a) : "l"(p));
    return a;
}
__device__ __forceinline__ void cp16(uint32_t d, const void* s) {
    asm volatile("cp.async.cg.shared.global [%0], [%1], 16;" :: "r"(d), "l"(s));
}
__device__ __forceinline__ void cp16z(uint32_t d, const void* s, bool pred) {
    int sz = pred ? 16 : 0;
    asm volatile("cp.async.cg.shared.global [%0], [%1], 16, %2;"
                 :: "r"(d), "l"(s), "r"(sz));
}
__device__ __forceinline__ void cp_commit() {
    asm volatile("cp.async.commit_group;" ::: "memory");
}
template <int Ng>
__device__ __forceinline__ void cp_wait() {
    asm volatile("cp.async.wait_group %0;" :: "n"(Ng) : "memory");
}
__device__ __forceinline__ void ldsm4(uint32_t (&r)[4], uint32_t addr) {
    asm volatile("ldmatrix.sync.aligned.m8n8.x4.shared.b16 {%0,%1,%2,%3}, [%4];"
                 : "=r"(r[0]), "=r"(r[1]), "=r"(r[2]), "=r"(r[3]) : "r"(addr));
}
__device__ __forceinline__ void mma16816(float (&d)[4], const uint32_t (&a)[4],
                                         uint32_t b0, uint32_t b1) {
    asm volatile("mma.sync.aligned.m16n8k16.row.col.f32.bf16.bf16.f32 "
                 "{%0,%1,%2,%3}, {%4,%5,%6,%7}, {%8,%9}, {%0,%1,%2,%3};"
                 : "+f"(d[0]), "+f"(d[1]), "+f"(d[2]), "+f"(d[3])
                 : "r"(a[0]), "r"(a[1]), "r"(a[2]), "r"(a[3]), "r"(b0), "r"(b1));
}
__device__ __forceinline__ uint32_t bfpack(float a, float b) {
    return (uint32_t)__bfloat16_as_ushort(__float2bfloat16_rn(a)) |
           ((uint32_t)__bfloat16_as_ushort(__float2bfloat16_rn(b)) << 16);
}
__device__ __forceinline__ float bfhi(float x) {
    return __bfloat162float(__float2bfloat16_rn(x));
}
__device__ __forceinline__ float sel4(float4 v, int i) {
    float a = (i & 1) ? v.y : v.x;
    float b = (i & 1) ? v.w : v.z;
    return (i & 2) ? b : a;
}

// ===========================================================================
// CSR build
// ===========================================================================
__global__ void csr_zero(int* cur, int n) {
    int i = blockIdx.x * blockDim.x + threadIdx.x;
    if (i < n) cur[i] = 0;
}
__global__ void csr_hist(const int* __restrict__ dst, int* cur, int E_) {
    int i = blockIdx.x * blockDim.x + threadIdx.x;
    if (i < E_) atomicAdd(&cur[dst[i]], 1);
}
__global__ void csr_scan(int* degcur, int* rowoff, int n) {
    __shared__ int sh[1024];
    __shared__ int carry_s;
    int tid = threadIdx.x;
    if (tid == 0) carry_s = 0;
    __syncthreads();
    for (int base = 0; base < n; base += 1024) {
        int i = base + tid;
        int v = (i < n) ? degcur[i] : 0;
        sh[tid] = v;
        __syncthreads();
#pragma unroll
        for (int o = 1; o < 1024; o <<= 1) {
            int t = (tid >= o) ? sh[tid - o] : 0;
            __syncthreads();
            sh[tid] += t;
            __syncthreads();
        }
        int excl = sh[tid] - v + carry_s;
        if (i < n) { rowoff[i] = excl; degcur[i] = excl; }
        __syncthreads();
        if (tid == 1023) carry_s += sh[1023];
        __syncthreads();
    }
    if (tid == 0) rowoff[n] = carry_s;
}
__global__ void csr_fill(const int* __restrict__ src, const int* __restrict__ dst,
                         int* cur, int* csrsrc, int E_) {
    int i = blockIdx.x * blockDim.x + threadIdx.x;
    if (i < E_) {
        int p = atomicAdd(&cur[dst[i]], 1);
        csrsrc[p] = src[i];
    }
}

// ===========================================================================
// FUSED layer-1 GEMM, BK=64, single-barrier pipeline, self-consistent convert.
// Each K64 tile is stored as two 32-k panels so all SWZ/ldmatrix math is
// unchanged per panel.
// smem: AF 2x32K [0,64K) | AHL 2x32K [64K,128K) | BHL 3x32K [128K,224K)
//   AHL stage: AHp0 8K | AHp1 8K | ALp0 8K | ALp1 8K
//   BHL stage: BHp0 8K | BHp1 8K | BLp0 8K | BLp1 8K
// iter c: sync | mma(c) | wait loads(c+1) | convert-own(c+1) | issue(c+2)
// ===========================================================================
__global__ __launch_bounds__(256)
void gemm_fused(const float* __restrict__ X,
                const __nv_bfloat16* __restrict__ Bh, const __nv_bfloat16* __restrict__ Bl,
                float* __restrict__ C, int M, int K, int KpB) {
    extern __shared__ char smem[];
    const uint32_t sb = smem_u32(smem);

    const int tid = threadIdx.x;
    const int wid = tid >> 5, lane = tid & 31;
    const int wm = wid & 3, wn = wid >> 2;
    const int bm0 = blockIdx.y * 128;
    const int bn0 = blockIdx.x * 128;

    float acc[2][8][4];
#pragma unroll
    for (int i = 0; i < 2; i++)
#pragma unroll
        for (int j = 0; j < 8; j++)
#pragma unroll
            for (int k = 0; k < 4; k++) acc[i][j][k] = 0.f;

    const int NC = (K + 63) >> 6;   // K64 tiles

    // A: 2048 chunks/tile; thread owns (row=i>>4, q=i&15), q*4 = k offset.
    auto load_tile = [&](int c) {   // A -> AF[c%2] (linear 256B rows), B -> BHL[c%3]
        const uint32_t af = sb + (c & 1) * 32768;
        const uint32_t bb = sb + 131072 + (c % 3) * 32768;
        const int k0 = c * 64;
#pragma unroll
        for (int t = 0; t < 8; t++) {
            int i = tid + t * 256;
            int row = i >> 4, q = i & 15;
            int gm = bm0 + row, gk = k0 + q * 4;
            bool p = (gm < M) && (gk < K);
            cp16z(af + row * 256 + q * 16, X + (p ? ((size_t)gm * K + gk) : 0), p);
        }
        // B: 2048 chunks/tile: kpanel, half(hi/lo), row, ch
#pragma unroll
        for (int t = 0; t < 8; t++) {
            int i = tid + t * 256;
            int kp = i >> 10;
            int rem = i & 1023;
            int half = rem >> 9;
            int rem2 = rem & 511;
            int row = rem2 >> 2, ch = rem2 & 3;
            const __nv_bfloat16* src =
                (half ? Bl : Bh) + (size_t)(bn0 + row) * KpB + k0 + kp * 32 + ch * 8;
            cp16(bb + half * 16384 + kp * 8192 + SWZ(row * 64 + ch * 16), src);
        }
    };

    auto convert = [&](int c) {     // AF[c%2] -> AHL[c%2], own data only
        const char* afp = smem + (c & 1) * 32768;
        char* ahp = smem + 65536 + (c & 1) * 32768;
#pragma unroll
        for (int t = 0; t < 8; t++) {
            int i = tid + t * 256;
            int row = i >> 4, q = i & 15;
            float4 v = *(const float4*)(afp + row * 256 + q * 16);
            uint32_t h0 = bfpack(v.x, v.y);
            uint32_t h1 = bfpack(v.z, v.w);
            uint32_t l0 = bfpack(v.x - bfhi(v.x), v.y - bfhi(v.y));
            uint32_t l1 = bfpack(v.z - bfhi(v.z), v.w - bfhi(v.w));
            // panel = q>>3; 8B store inside one 16B swizzle unit
            uint32_t off = (q >> 3) * 8192 + SWZ(row * 64 + (q & 6) * 8) + (q & 1) * 8;
            *(uint2*)(ahp + off)         = make_uint2(h0, h1);
            *(uint2*)(ahp + 16384 + off) = make_uint2(l0, l1);
        }
    };

    const int a_row = wm * 32 + (lane & 15);
    const int a_chb = lane >> 4;
    const int b_row = wn * 64 + ((lane >> 4) & 1) * 8 + (lane & 7);
    const int b_chb = (lane >> 3) & 1;

    // prologue
    load_tile(0); cp_commit();
    if (NC > 1) { load_tile(1); cp_commit(); }
    cp_wait<1>();            // tile 0 (own copies) complete
    convert(0);

    for (int c = 0; c < NC; c++) {
        __syncthreads();     // publish convert(c) + B(c) to all warps

        const uint32_t aBase = sb + 65536 + (c & 1) * 32768;
        const uint32_t bBase = sb + 131072 + (c % 3) * 32768;
#pragma unroll
        for (int ks = 0; ks < 4; ks++) {
            const int kp = ks >> 1, ki = ks & 1;
            const uint32_t aH = aBase + kp * 8192;
            const uint32_t aL = aH + 16384;
            const uint32_t bH = bBase + kp * 8192;
            const uint32_t bL = bH + 16384;
            uint32_t ah[2][4], al[2][4];
#pragma unroll
            for (int mf = 0; mf < 2; mf++) {
                uint32_t off = SWZ((a_row + mf * 16) * 64 + (ki * 2 + a_chb) * 16);
                ldsm4(ah[mf], aH + off);
                ldsm4(al[mf], aL + off);
            }
            uint32_t bh[4][4], bl[4][4];
#pragma unroll
            for (int p = 0; p < 4; p++) {
                uint32_t off = SWZ((b_row + p * 16) * 64 + (ki * 2 + b_chb) * 16);
                ldsm4(bh[p], bH + off);
                ldsm4(bl[p], bL + off);
            }
            // 3 passes of 16 independent MMAs; per-acc order hh,hl,lh (bit-identical)
#pragma unroll
            for (int mf = 0; mf < 2; mf++)
#pragma unroll
                for (int p = 0; p < 4; p++) {
                    mma16816(acc[mf][2 * p],     ah[mf], bh[p][0], bh[p][1]);
                    mma16816(acc[mf][2 * p + 1], ah[mf], bh[p][2], bh[p][3]);
                }
#pragma unroll
            for (int mf = 0; mf < 2; mf++)
#pragma unroll
                for (int p = 0; p < 4; p++) {
                    mma16816(acc[mf][2 * p],     ah[mf], bl[p][0], bl[p][1]);
                    mma16816(acc[mf][2 * p + 1], ah[mf], bl[p][2], bl[p][3]);
                }
#pragma unroll
            for (int mf = 0; mf < 2; mf++)
#pragma unroll
                for (int p = 0; p < 4; p++) {
                    mma16816(acc[mf][2 * p],     al[mf], bh[p][0], bh[p][1]);
                    mma16816(acc[mf][2 * p + 1], al[mf], bh[p][2], bh[p][3]);
                }
        }

        // convert(c+1): own cp.async data, ordered by wait_group
        if (c + 1 < NC) {
            cp_wait<0>();
            convert(c + 1);
        }
        // prefetch tile c+2 (AF[c%2] own-reused; BHL[(c+2)%3] disjoint)
        if (c + 2 < NC) {
            load_tile(c + 2);
            cp_commit();
        }
    }

#pragma unroll
    for (int mf = 0; mf < 2; mf++) {
        int r0 = bm0 + wm * 32 + mf * 16 + (lane >> 2);
#pragma unroll
        for (int nf = 0; nf < 8; nf++) {
            int col = bn0 + wn * 64 + nf * 8 + (lane & 3) * 2;
            if (r0 < M)
                *(float2*)(C + (size_t)r0 * 256 + col) =
                    make_float2(acc[mf][nf][0], acc[mf][nf][1]);
            if (r0 + 8 < M)
                *(float2*)(C + (size_t)(r0 + 8) * 256 + col) =
                    make_float2(acc[mf][nf][2], acc[mf][nf][3]);
        }
    }
}

// ===========================================================================
// pre-split GEMM for layers 2/3 (R7-proven, MMAs re-ordered into 3 passes)
// ===========================================================================
template <int BN>
__global__ __launch_bounds__(256)
void gemm_mma(const __nv_bfloat16* __restrict__ Ah, const __nv_bfloat16* __restrict__ Al,
              const __nv_bfloat16* __restrict__ Bh, const __nv_bfloat16* __restrict__ Bl,
              float* __restrict__ C, int M, int N, int Kp) {
    constexpr int WNCOL = BN / 2;
    constexpr int NFRAG = WNCOL / 8;
    constexpr int NPAIR = NFRAG / 2;
    constexpr int ABH = 8192;
    constexpr int BBH = BN * 64;
    constexpr int STAGE = 2 * ABH + 2 * BBH;

    extern __shared__ char smem[];
    const uint32_t sb = smem_u32(smem);

    const int tid = threadIdx.x;
    const int wid = tid >> 5, lane = tid & 31;
    const int wm = wid & 3, wn = wid >> 2;
    const int bm0 = blockIdx.y * 128;
    const int bn0 = blockIdx.x * BN;

    float acc[2][NFRAG][4];
#pragma unroll
    for (int i = 0; i < 2; i++)
#pragma unroll
        for (int j = 0; j < NFRAG; j++)
#pragma unroll
            for (int k = 0; k < 4; k++) acc[i][j][k] = 0.f;

    const int NC = Kp >> 5;

    auto load_stage = [&](int c, int stg) {
        const uint32_t base = sb + stg * STAGE;
        const size_t koff = (size_t)c * 32;
#pragma unroll
        for (int t = 0; t < 4; t++) {
            int i = tid + t * 256;
            int half = i >> 9;
            int rem = i & 511;
            int row = rem >> 2, ch = rem & 3;
            const __nv_bfloat16* src =
                (half ? Al : Ah) + (size_t)(bm0 + row) * Kp + koff + ch * 8;
            cp16(base + half * ABH + SWZ(row * 64 + ch * 16), src);
        }
#pragma unroll
        for (int t = 0; t < BN / 32; t++) {
            int i = tid + t * 256;
            int half = i / (BN * 4);
            int rem = i % (BN * 4);
            int row = rem >> 2, ch = rem & 3;
            const __nv_bfloat16* src =
                (half ? Bl : Bh) + (size_t)(bn0 + row) * Kp + koff + ch * 8;
            cp16(base + 2 * ABH + half * BBH + SWZ(row * 64 + ch * 16), src);
        }
    };

    const int a_row = wm * 32 + (lane & 15);
    const int a_chb = lane >> 4;
    const int b_row = wn * WNCOL + ((lane >> 4) & 1) * 8 + (lane & 7);
    const int b_chb = (lane >> 3) & 1;

    load_stage(0, 0);
    cp_commit();

    for (int c = 0; c < NC; c++) {
        if (c + 1 < NC) {
            load_stage(c + 1, (c + 1) & 1);
            cp_commit();
            cp_wait<1>();
        } else {
            cp_wait<0>();
        }
        __syncthreads();

        const uint32_t base = sb + (c & 1) * STAGE;
        const uint32_t aH = base, aL = base + ABH;
        const uint32_t bH = base + 2 * ABH, bL = bH + BBH;

#pragma unroll
        for (int ks = 0; ks < 2; ks++) {
            uint32_t ah[2][4], al[2][4];
#pragma unroll
            for (int mf = 0; mf < 2; mf++) {
                uint32_t off = SWZ((a_row + mf * 16) * 64 + (ks * 2 + a_chb) * 16);
                ldsm4(ah[mf], aH + off);
                ldsm4(al[mf], aL + off);
            }
            uint32_t bh[NPAIR][4], bl[NPAIR][4];
#pragma unroll
            for (int p = 0; p < NPAIR; p++) {
                uint32_t off = SWZ((b_row + p * 16) * 64 + (ks * 2 + b_chb) * 16);
                ldsm4(bh[p], bH + off);
                ldsm4(bl[p], bL + off);
            }
#pragma unroll
            for (int mf = 0; mf < 2; mf++)
#pragma unroll
                for (int p = 0; p < NPAIR; p++) {
                    mma16816(acc[mf][2 * p],     ah[mf], bh[p][0], bh[p][1]);
                    mma16816(acc[mf][2 * p + 1], ah[mf], bh[p][2], bh[p][3]);
                }
#pragma unroll
            for (int mf = 0; mf < 2; mf++)
#pragma unroll
                for (int p = 0; p < NPAIR; p++) {
                    mma16816(acc[mf][2 * p],     ah[mf], bl[p][0], bl[p][1]);
                    mma16816(acc[mf][2 * p + 1], ah[mf], bl[p][2], bl[p][3]);
                }
#pragma unroll
            for (int mf = 0; mf < 2; mf++)
#pragma unroll
                for (int p = 0; p < NPAIR; p++) {
                    mma16816(acc[mf][2 * p],     al[mf], bh[p][0], bh[p][1]);
                    mma16816(acc[mf][2 * p + 1], al[mf], bh[p][2], bh[p][3]);
                }
        }
        __syncthreads();
    }

#pragma unroll
    for (int mf = 0; mf < 2; mf++) {
        int r0 = bm0 + wm * 32 + mf * 16 + (lane >> 2);
#pragma unroll
        for (int nf = 0; nf < NFRAG; nf++) {
            int col = bn0 + wn * WNCOL + nf * 8 + (lane & 3) * 2;
            if (r0 < M)
                *(float2*)(C + (size_t)r0 * N + col) =
                    make_float2(acc[mf][nf][0], acc[mf][nf][1]);
            if (r0 + 8 < M)
                *(float2*)(C + (size_t)(r0 + 8) * N + col) =
                    make_float2(acc[mf][nf][2], acc[mf][nf][3]);
        }
    }
}

// ===========================================================================
// es/ed logits (one warp per node)
// ===========================================================================
__global__ void es_ed4(const float* __restrict__ h,
                       const float* __restrict__ a_src,
                       const float* __restrict__ a_dst,
                       float* __restrict__ es, float* __restrict__ ed, int n) {
    int w = (blockIdx.x * blockDim.x + threadIdx.x) >> 5;
    int lane = threadIdx.x & 31;
    if (w >= n) return;
    int c = lane * 8;
    const float* hp = h + (size_t)w * 256 + c;
    float4 v0 = *(const float4*)(hp);
    float4 v1 = *(const float4*)(hp + 4);
    float4 as0 = *(const float4*)(a_src + c);
    float4 as1 = *(const float4*)(a_src + c + 4);
    float4 ad0 = *(const float4*)(a_dst + c);
    float4 ad1 = *(const float4*)(a_dst + c + 4);
    float s = v0.x * as0.x + v0.y * as0.y + v0.z * as0.z + v0.w * as0.w +
              v1.x * as1.x + v1.y * as1.y + v1.z * as1.z + v1.w * as1.w;
    float d = v0.x * ad0.x + v0.y * ad0.y + v0.z * ad0.z + v0.w * ad0.w +
              v1.x * ad1.x + v1.y * ad1.y + v1.z * ad1.z + v1.w * ad1.w;
#pragma unroll
    for (int o = 4; o; o >>= 1) {
        s += __shfl_xor_sync(0xffffffffu, s, o);
        d += __shfl_xor_sync(0xffffffffu, d, o);
    }
    if ((lane & 7) == 0) {
        int head = lane >> 3;
        es[w * 4 + head] = s;
        ed[w * 4 + head] = d;
    }
}

__global__ void es_ed1(const float* __restrict__ h,
                       const float* __restrict__ a_src,
                       const float* __restrict__ a_dst,
                       float* __restrict__ es, float* __restrict__ ed, int n) {
    int w = (blockIdx.x * blockDim.x + threadIdx.x) >> 5;
    int lane = threadIdx.x & 31;
    if (w >= n) return;
    int c = lane * 2;
    float2 v = *(const float2*)(h + (size_t)w * 64 + c);
    float2 as = *(const float2*)(a_src + c);
    float2 ad = *(const float2*)(a_dst + c);
    float s = v.x * as.x + v.y * as.y;
    float d = v.x * ad.x + v.y * ad.y;
#pragma unroll
    for (int o = 16; o; o >>= 1) {
        s += __shfl_xor_sync(0xffffffffu, s, o);
        d += __shfl_xor_sync(0xffffffffu, d, o);
    }
    if (lane == 0) { es[w] = s; ed[w] = d; }
}

// ===========================================================================
// agg_gather4: one warp per dst node, register accumulate, fused
// normalize/bias/ELU/bf16-split (proven R7)
// ===========================================================================
__global__ void agg_gather4(const int* __restrict__ rowoff, const int* __restrict__ csrsrc,
                            const float* __restrict__ es, const float* __restrict__ ed,
                            const float* __restrict__ h, const float* __restrict__ b,
                            __nv_bfloat16* __restrict__ Hh, __nv_bfloat16* __restrict__ Hl,
                            int n, int Mp) {
    int w = (blockIdx.x * blockDim.x + threadIdx.x) >> 5;
    int lane = threadIdx.x & 31;
    if (w >= Mp) return;
    const int c0 = lane * 4;
    if (w >= n) {
        *(uint2*)(Hh + (size_t)w * 256 + c0) = make_uint2(0, 0);
        *(uint2*)(Hh + (size_t)w * 256 + c0 + 128) = make_uint2(0, 0);
        *(uint2*)(Hl + (size_t)w * 256 + c0) = make_uint2(0, 0);
        *(uint2*)(Hl + (size_t)w * 256 + c0 + 128) = make_uint2(0, 0);
        return;
    }
    const int myh = lane & 3;
    const int hs = (lane >> 4) & 1;
    float4 ed4 = *(const float4*)(ed + w * 4);
    float edh = sel4(ed4, myh);

    float4 es4 = *(const float4*)(es + w * 4);
    float e = sel4(es4, myh) + edh;
    e = e > 0.f ? e : 0.2f * e;
    float wv = __expf(e);
    float den = wv;
    float al0 = __shfl_sync(0xffffffffu, wv, hs);
    float al1 = __shfl_sync(0xffffffffu, wv, 2 + hs);

    const float* hp = h + (size_t)w * 256;
    float4 a0 = *(const float4*)(hp + c0);
    float4 a1 = *(const float4*)(hp + c0 + 128);
    a0.x *= al0; a0.y *= al0; a0.z *= al0; a0.w *= al0;
    a1.x *= al1; a1.y *= al1; a1.z *= al1; a1.w *= al1;

    int j0 = rowoff[w], j1 = rowoff[w + 1];
    int s = (j0 < j1) ? csrsrc[j0] : 0;
    for (int j = j0; j < j1; j++) {
        int snext = (j + 1 < j1) ? csrsrc[j + 1] : 0;
        float4 e4 = *(const float4*)(es + s * 4);
        float ee = sel4(e4, myh) + edh;
        ee = ee > 0.f ? ee : 0.2f * ee;
        float wj = __expf(ee);
        den += wj;
        float b0 = __shfl_sync(0xffffffffu, wj, hs);
        float b1 = __shfl_sync(0xffffffffu, wj, 2 + hs);
        const float* sp = h + (size_t)s * 256;
        float4 v0 = *(const float4*)(sp + c0);
        float4 v1 = *(const float4*)(sp + c0 + 128);
        a0.x += b0 * v0.x; a0.y += b0 * v0.y; a0.z += b0 * v0.z; a0.w += b0 * v0.w;
        a1.x += b1 * v1.x; a1.y += b1 * v1.y; a1.z += b1 * v1.z; a1.w += b1 * v1.w;
        s = snext;
    }
    float inv0 = __fdividef(1.f, __shfl_sync(0xffffffffu, den, hs));
    float inv1 = __fdividef(1.f, __shfl_sync(0xffffffffu, den, 2 + hs));

    float4 bb0 = *(const float4*)(b + c0);
    float4 bb1 = *(const float4*)(b + c0 + 128);
    float f0[4] = {a0.x * inv0 + bb0.x, a0.y * inv0 + bb0.y,
                   a0.z * inv0 + bb0.z, a0.w * inv0 + bb0.w};
    float f1[4] = {a1.x * inv1 + bb1.x, a1.y * inv1 + bb1.y,
                   a1.z * inv1 + bb1.z, a1.w * inv1 + bb1.w};
#pragma unroll
    for (int k = 0; k < 4; k++) {
        f0[k] = f0[k] > 0.f ? f0[k] : expm1f(f0[k]);
        f1[k] = f1[k] > 0.f ? f1[k] : expm1f(f1[k]);
    }
    uint32_t h0a = bfpack(f0[0], f0[1]), h0b = bfpack(f0[2], f0[3]);
    uint32_t h1a = bfpack(f1[0], f1[1]), h1b = bfpack(f1[2], f1[3]);
    float r0[4], r1[4];
#pragma unroll
    for (int k = 0; k < 4; k++) {
        r0[k] = f0[k] - bfhi(f0[k]);
        r1[k] = f1[k] - bfhi(f1[k]);
    }
    size_t o = (size_t)w * 256 + c0;
    *(uint2*)(Hh + o)       = make_uint2(h0a, h0b);
    *(uint2*)(Hh + o + 128) = make_uint2(h1a, h1b);
    *(uint2*)(Hl + o)       = make_uint2(bfpack(r0[0], r0[1]), bfpack(r0[2], r0[3]));
    *(uint2*)(Hl + o + 128) = make_uint2(bfpack(r1[0], r1[1]), bfpack(r1[2], r1[3]));
}

// ===========================================================================
// agg_gather1 + classifier (proven R7)
// ===========================================================================
__global__ void agg_gather1(const int* __restrict__ rowoff, const int* __restrict__ csrsrc,
                            const float* __restrict__ es, const float* __restrict__ ed,
                            const float* __restrict__ h, const float* __restrict__ b3,
                            const float* __restrict__ Wc, const float* __restrict__ bc,
                            float* __restrict__ out, int n) {
    int w = (blockIdx.x * blockDim.x + threadIdx.x) >> 5;
    int lane = threadIdx.x & 31;
    if (w >= n) return;
    float edw = ed[w];
    float e = es[w] + edw;
    e = e > 0.f ? e : 0.2f * e;
    float wv = __expf(e);
    float den = wv;
    float v0 = h[(size_t)w * 64 + lane] * wv;
    float v1 = h[(size_t)w * 64 + lane + 32] * wv;

    int j0 = rowoff[w], j1 = rowoff[w + 1];
    int s = (j0 < j1) ? csrsrc[j0] : 0;
    for (int j = j0; j < j1; j++) {
        int snext = (j + 1 < j1) ? csrsrc[j + 1] : 0;
        float ee = es[s] + edw;
        ee = ee > 0.f ? ee : 0.2f * ee;
        float wj = __expf(ee);
        den += wj;
        v0 += wj * h[(size_t)s * 64 + lane];
        v1 += wj * h[(size_t)s * 64 + lane + 32];
        s = snext;
    }
    float inv = __fdividef(1.f, den);
    v0 = v0 * inv + b3[lane];
    v0 = v0 > 0.f ? v0 : expm1f(v0);
    v1 = v1 * inv + b3[lane + 32];
    v1 = v1 > 0.f ? v1 : expm1f(v1);
#pragma unroll
    for (int j = 0; j < 3; j++) {
        float p = v0 * Wc[lane * 3 + j] + v1 * Wc[(lane + 32) * 3 + j];
#pragma unroll
        for (int o = 16; o; o >>= 1) p += __shfl_xor_sync(0xffffffffu, p, o);
        if (lane == 0) out[w * 3 + j] = p + bc[j];
    }
}

// ===========================================================================
// W [K,N] fp32 -> hi/lo bf16 [N,Kp]
// ===========================================================================
__global__ void conv_wT(const float* __restrict__ W,
                        __nv_bfloat16* __restrict__ Bh,
                        __nv_bfloat16* __restrict__ Bl,
                        int K, int N, int Kp) {
    int idx = blockIdx.x * blockDim.x + threadIdx.x;
    if (idx >= N * Kp) return;
    int n = idx / Kp, k = idx - n * Kp;
    float v = (k < K) ? W[(size_t)k * N + n] : 0.f;
    __nv_bfloat16 h = __float2bfloat16_rn(v);
    __nv_bfloat16 l = __float2bfloat16_rn(v - __bfloat162float(h));
    Bh[(size_t)n * Kp + k] = h;
    Bl[(size_t)n * Kp + k] = l;
}

// ===========================================================================
static inline int cdiv(int a, int b) { return (a + b - 1) / b; }

extern "C" void kernel_launch(void* const* d_in, const int* in_sizes, int n_in,
                              void* d_out, int out_size) {
    const float* x    = (const float*)d_in[0];
    const float* W1   = (const float*)d_in[1];
    const float* a1s  = (const float*)d_in[2];
    const float* a1d  = (const float*)d_in[3];
    const float* b1   = (const float*)d_in[4];
    const float* W2   = (const float*)d_in[5];
    const float* a2s  = (const float*)d_in[6];
    const float* a2d  = (const float*)d_in[7];
    const float* b2   = (const float*)d_in[8];
    const float* W3   = (const float*)d_in[9];
    const float* a3s  = (const float*)d_in[10];
    const float* a3d  = (const float*)d_in[11];
    const float* b3   = (const float*)d_in[12];
    const float* Wc   = (const float*)d_in[13];
    const float* bc   = (const float*)d_in[14];
    const int*   ei   = (const int*)d_in[15];
    float* out = (float*)d_out;

    const int N = GAT_N, E = GAT_E, Mp = GAT_Mp;
    const int* src = ei;
    const int* dst = ei + E;

    float *hA, *h3, *es, *ed;
    int *rowoff, *cursor, *csrsrc;
    __nv_bfloat16 *Ahp, *Alp, *Bhp, *Blp;
    cudaGetSymbolAddress((void**)&hA,     g_hA);
    cudaGetSymbolAddress((void**)&h3,     g_h3);
    cudaGetSymbolAddress((void**)&es,     g_es);
    cudaGetSymbolAddress((void**)&ed,     g_ed);
    cudaGetSymbolAddress((void**)&rowoff, g_rowoff);
    cudaGetSymbolAddress((void**)&cursor, g_cursor);
    cudaGetSymbolAddress((void**)&csrsrc, g_csrsrc);
    cudaGetSymbolAddress((void**)&Ahp,    g_Ah);
    cudaGetSymbolAddress((void**)&Alp,    g_Al);
    cudaGetSymbolAddress((void**)&Bhp,    g_Bh);
    cudaGetSymbolAddress((void**)&Blp,    g_Bl);

    const int SMF   = 229376;                          // AF 64K + AHL 64K + BHL 96K
    const int SM128 = 2 * (2 * 8192 + 2 * 128 * 64);
    const int SM64  = 2 * (2 * 8192 + 2 * 64 * 64);
    cudaFuncSetAttribute(gemm_fused,    cudaFuncAttributeMaxDynamicSharedMemorySize, SMF);
    cudaFuncSetAttribute(gemm_mma<128>, cudaFuncAttributeMaxDynamicSharedMemorySize, SM128);
    cudaFuncSetAttribute(gemm_mma<64>,  cudaFuncAttributeMaxDynamicSharedMemorySize, SM64);

    const int TB = 256;
    const int MT = Mp / 128;               // 235
    const int NPB = cdiv(N * 32, TB);      // warp-per-node blocks
    const int GPB = cdiv(Mp * 32, TB);     // warp-per-padded-node blocks

    // ---------------- CSR build ----------------
    csr_zero<<<cdiv(N, TB), TB>>>(cursor, N);
    csr_hist<<<cdiv(E, TB), TB>>>(dst, cursor, E);
    csr_scan<<<1, 1024>>>(cursor, rowoff, N);
    csr_fill<<<cdiv(E, TB), TB>>>(src, dst, cursor, csrsrc, E);

    // ---------------- layer 1 (H=4, K=5000) ----------------
    conv_wT<<<cdiv(256 * GAT_K1P, TB), TB>>>(W1, Bhp, Blp, GAT_DIN, 256, GAT_K1P);
    gemm_fused<<<dim3(2, MT), 256, SMF>>>(x, Bhp, Blp, hA, N, GAT_DIN, GAT_K1P);
    es_ed4<<<NPB, TB>>>(hA, a1s, a1d, es, ed, N);
    agg_gather4<<<GPB, TB>>>(rowoff, csrsrc, es, ed, hA, b1, Ahp, Alp, N, Mp);

    // ---------------- layer 2 (H=4, K=256) ----------------
    conv_wT<<<cdiv(256 * 256, TB), TB>>>(W2, Bhp, Blp, 256, 256, 256);
    gemm_mma<128><<<dim3(2, MT), 256, SM128>>>(Ahp, Alp, Bhp, Blp, hA, N, 256, 256);
    es_ed4<<<NPB, TB>>>(hA, a2s, a2d, es, ed, N);
    agg_gather4<<<GPB, TB>>>(rowoff, csrsrc, es, ed, hA, b2, Ahp, Alp, N, Mp);

    // ---------------- layer 3 (H=1, K=256, N=64) ----------------
    conv_wT<<<cdiv(64 * 256, TB), TB>>>(W3, Bhp, Blp, 256, 64, 256);
    gemm_mma<64><<<dim3(1, MT), 256, SM64>>>(Ahp, Alp, Bhp, Blp, h3, N, 64, 256);
    es_ed1<<<NPB, TB>>>(h3, a3s, a3d, es, ed, N);
    agg_gather1<<<NPB, TB>>>(rowoff, csrsrc, es, ed, h3, b3, Wc, bc, out, N);
}

// round 11
// speedup vs baseline: 1.1845x; 1.1845x over previous
#include <cuda_runtime.h>
#include <cuda_bf16.h>
#include <cstdint>

// ---------------------------------------------------------------------------
// SentimentGAT on GB300 (sm_103 baseline PTX): bf16x3 mma.sync GEMMs +
// CSR-gather attention; layer-1 GEMM BK=32 single-barrier pipeline (112KB smem,
// 2 CTA/SM) with in-shadow fp32->bf16 convert; MMAs as 3 independent passes.
// ---------------------------------------------------------------------------

#define GAT_N   30000
#define GAT_Mp  30080               // 235 * 128
#define GAT_E   480000
#define GAT_DIN 5000
#define GAT_K1P 5056                // 79 * 64 (padded K stride for W1^T)

// ---- fp32 scratch ----
__device__ float g_hA[GAT_N * 256];
__device__ float g_h3[GAT_N * 64];
__device__ float g_es[GAT_N * 4];
__device__ float g_ed[GAT_N * 4];

// ---- CSR ----
__device__ int g_rowoff[GAT_N + 1];
__device__ int g_cursor[GAT_N];
__device__ int g_csrsrc[GAT_E];

// ---- bf16 hi/lo scratch ----
__device__ __align__(128) __nv_bfloat16 g_Ah[(size_t)GAT_Mp * 256];
__device__ __align__(128) __nv_bfloat16 g_Al[(size_t)GAT_Mp * 256];
__device__ __align__(128) __nv_bfloat16 g_Bh[256 * GAT_K1P];
__device__ __align__(128) __nv_bfloat16 g_Bl[256 * GAT_K1P];

// ===========================================================================
// low-level helpers
// ===========================================================================
#define SWZ(o) ((o) ^ (((o) >> 3) & 0x70))

__device__ __forceinline__ uint32_t smem_u32(const void* p) {
    uint32_t a;
    asm("{ .reg .u64 t; cvta.to.shared.u64 t, %1; cvt.u32.u64 %0, t; }"
        : "=r"(a) : "l"(p));
    return a;
}
__device__ __forceinline__ void cp16(uint32_t d, const void* s) {
    asm volatile("cp.async.cg.shared.global [%0], [%1], 16;" :: "r"(d), "l"(s));
}
__device__ __forceinline__ void cp16z(uint32_t d, const void* s, bool pred) {
    int sz = pred ? 16 : 0;
    asm volatile("cp.async.cg.shared.global [%0], [%1], 16, %2;"
                 :: "r"(d), "l"(s), "r"(sz));
}
__device__ __forceinline__ void cp_commit() {
    asm volatile("cp.async.commit_group;" ::: "memory");
}
template <int Ng>
__device__ __forceinline__ void cp_wait() {
    asm volatile("cp.async.wait_group %0;" :: "n"(Ng) : "memory");
}
__device__ __forceinline__ void ldsm4(uint32_t (&r)[4], uint32_t addr) {
    asm volatile("ldmatrix.sync.aligned.m8n8.x4.shared.b16 {%0,%1,%2,%3}, [%4];"
                 : "=r"(r[0]), "=r"(r[1]), "=r"(r[2]), "=r"(r[3]) : "r"(addr));
}
__device__ __forceinline__ void mma16816(float (&d)[4], const uint32_t (&a)[4],
                                         uint32_t b0, uint32_t b1) {
    asm volatile("mma.sync.aligned.m16n8k16.row.col.f32.bf16.bf16.f32 "
                 "{%0,%1,%2,%3}, {%4,%5,%6,%7}, {%8,%9}, {%0,%1,%2,%3};"
                 : "+f"(d[0]), "+f"(d[1]), "+f"(d[2]), "+f"(d[3])
                 : "r"(a[0]), "r"(a[1]), "r"(a[2]), "r"(a[3]), "r"(b0), "r"(b1));
}
__device__ __forceinline__ uint32_t bfpack(float a, float b) {
    return (uint32_t)__bfloat16_as_ushort(__float2bfloat16_rn(a)) |
           ((uint32_t)__bfloat16_as_ushort(__float2bfloat16_rn(b)) << 16);
}
__device__ __forceinline__ float bfhi(float x) {
    return __bfloat162float(__float2bfloat16_rn(x));
}
__device__ __forceinline__ float sel4(float4 v, int i) {
    float a = (i & 1) ? v.y : v.x;
    float b = (i & 1) ? v.w : v.z;
    return (i & 2) ? b : a;
}

// ===========================================================================
// CSR build
// ===========================================================================
__global__ void csr_zero(int* cur, int n) {
    int i = blockIdx.x * blockDim.x + threadIdx.x;
    if (i < n) cur[i] = 0;
}
__global__ void csr_hist(const int* __restrict__ dst, int* cur, int E_) {
    int i = blockIdx.x * blockDim.x + threadIdx.x;
    if (i < E_) atomicAdd(&cur[dst[i]], 1);
}
__global__ void csr_scan(int* degcur, int* rowoff, int n) {
    __shared__ int sh[1024];
    __shared__ int carry_s;
    int tid = threadIdx.x;
    if (tid == 0) carry_s = 0;
    __syncthreads();
    for (int base = 0; base < n; base += 1024) {
        int i = base + tid;
        int v = (i < n) ? degcur[i] : 0;
        sh[tid] = v;
        __syncthreads();
#pragma unroll
        for (int o = 1; o < 1024; o <<= 1) {
            int t = (tid >= o) ? sh[tid - o] : 0;
            __syncthreads();
            sh[tid] += t;
            __syncthreads();
        }
        int excl = sh[tid] - v + carry_s;
        if (i < n) { rowoff[i] = excl; degcur[i] = excl; }
        __syncthreads();
        if (tid == 1023) carry_s += sh[1023];
        __syncthreads();
    }
    if (tid == 0) rowoff[n] = carry_s;
}
__global__ void csr_fill(const int* __restrict__ src, const int* __restrict__ dst,
                         int* cur, int* csrsrc, int E_) {
    int i = blockIdx.x * blockDim.x + threadIdx.x;
    if (i < E_) {
        int p = atomicAdd(&cur[dst[i]], 1);
        csrsrc[p] = src[i];
    }
}

// ===========================================================================
// FUSED layer-1 GEMM, BK=32, single-barrier pipeline, self-consistent convert.
// smem: AF 0..32K (x2 ring) | AHL 32K..64K (x2) | BHL 64K..112K (x3)
// iter c: sync | mma(c) | wait loads(c+1) | convert-own(c+1) | issue(c+2)
// 112 KB/CTA -> 2 CTAs/SM (load-bearing for latency hiding).
// ===========================================================================
__global__ __launch_bounds__(256)
void gemm_fused(const float* __restrict__ X,
                const __nv_bfloat16* __restrict__ Bh, const __nv_bfloat16* __restrict__ Bl,
                float* __restrict__ C, int M, int K, int KpB) {
    extern __shared__ char smem[];
    const uint32_t sb = smem_u32(smem);

    const int tid = threadIdx.x;
    const int wid = tid >> 5, lane = tid & 31;
    const int wm = wid & 3, wn = wid >> 2;
    const int bm0 = blockIdx.y * 128;
    const int bn0 = blockIdx.x * 128;

    float acc[2][8][4];
#pragma unroll
    for (int i = 0; i < 2; i++)
#pragma unroll
        for (int j = 0; j < 8; j++)
#pragma unroll
            for (int k = 0; k < 4; k++) acc[i][j][k] = 0.f;

    const int NC = (K + 31) >> 5;

    // thread i (plus t*256) owns (row = i>>3, q = i&7): used by BOTH the
    // cp.async A-load and the convert, so wait_group orders them per-thread.
    auto load_tile = [&](int c) {   // A -> AF[c%2], B -> BHL[c%3]
        const uint32_t af = sb + (c & 1) * 16384;
        const uint32_t bb = sb + 65536 + (c % 3) * 16384;
        const int k0 = c * 32;
#pragma unroll
        for (int t = 0; t < 4; t++) {
            int i = tid + t * 256;
            int row = i >> 3, q = i & 7;
            int gm = bm0 + row, gk = k0 + q * 4;
            bool p = (gm < M) && (gk < K);
            cp16z(af + row * 128 + q * 16, X + (p ? ((size_t)gm * K + gk) : 0), p);
        }
#pragma unroll
        for (int t = 0; t < 4; t++) {
            int i = tid + t * 256;
            int half = i >> 9;
            int rem = i & 511;
            int row = rem >> 2, ch = rem & 3;
            const __nv_bfloat16* src =
                (half ? Bl : Bh) + (size_t)(bn0 + row) * KpB + k0 + ch * 8;
            cp16(bb + half * 8192 + SWZ(row * 64 + ch * 16), src);
        }
    };

    auto convert = [&](int c) {     // AF[c%2] -> AHL[c%2], own data only
        const int s2 = c & 1;
        const char* afp = smem + s2 * 16384;
        char* ahp = smem + 32768 + s2 * 16384;
#pragma unroll
        for (int t = 0; t < 4; t++) {
            int i = tid + t * 256;
            int row = i >> 3, q = i & 7;
            float4 v = *(const float4*)(afp + row * 128 + q * 16);
            uint32_t h0 = bfpack(v.x, v.y);
            uint32_t h1 = bfpack(v.z, v.w);
            uint32_t l0 = bfpack(v.x - bfhi(v.x), v.y - bfhi(v.y));
            uint32_t l1 = bfpack(v.z - bfhi(v.z), v.w - bfhi(v.w));
            uint32_t off = SWZ(row * 64 + (q & 6) * 8) + (q & 1) * 8;
            *(uint2*)(ahp + off)        = make_uint2(h0, h1);
            *(uint2*)(ahp + 8192 + off) = make_uint2(l0, l1);
        }
    };

    const int a_row = wm * 32 + (lane & 15);
    const int a_chb = lane >> 4;
    const int b_row = wn * 64 + ((lane >> 4) & 1) * 8 + (lane & 7);
    const int b_chb = (lane >> 3) & 1;

    // prologue
    load_tile(0); cp_commit();
    if (NC > 1) { load_tile(1); cp_commit(); }
    cp_wait<1>();            // tile 0 (own copies) complete
    convert(0);              // own data only -> no barrier needed

    for (int c = 0; c < NC; c++) {
        __syncthreads();     // publish convert(c) to all warps

        // ---- mma(c) ----
        const uint32_t aH = sb + 32768 + (c & 1) * 16384;
        const uint32_t aL = aH + 8192;
        const uint32_t bH = sb + 65536 + (c % 3) * 16384;
        const uint32_t bL = bH + 8192;
#pragma unroll
        for (int ks = 0; ks < 2; ks++) {
            uint32_t ah[2][4], al[2][4];
#pragma unroll
            for (int mf = 0; mf < 2; mf++) {
                uint32_t off = SWZ((a_row + mf * 16) * 64 + (ks * 2 + a_chb) * 16);
                ldsm4(ah[mf], aH + off);
                ldsm4(al[mf], aL + off);
            }
            uint32_t bh[4][4], bl[4][4];
#pragma unroll
            for (int p = 0; p < 4; p++) {
                uint32_t off = SWZ((b_row + p * 16) * 64 + (ks * 2 + b_chb) * 16);
                ldsm4(bh[p], bH + off);
                ldsm4(bl[p], bL + off);
            }
            // 3 passes of 16 independent MMAs; per-acc order hh,hl,lh (bit-identical)
#pragma unroll
            for (int mf = 0; mf < 2; mf++)
#pragma unroll
                for (int p = 0; p < 4; p++) {
                    mma16816(acc[mf][2 * p],     ah[mf], bh[p][0], bh[p][1]);
                    mma16816(acc[mf][2 * p + 1], ah[mf], bh[p][2], bh[p][3]);
                }
#pragma unroll
            for (int mf = 0; mf < 2; mf++)
#pragma unroll
                for (int p = 0; p < 4; p++) {
                    mma16816(acc[mf][2 * p],     ah[mf], bl[p][0], bl[p][1]);
                    mma16816(acc[mf][2 * p + 1], ah[mf], bl[p][2], bl[p][3]);
                }
#pragma unroll
            for (int mf = 0; mf < 2; mf++)
#pragma unroll
                for (int p = 0; p < 4; p++) {
                    mma16816(acc[mf][2 * p],     al[mf], bh[p][0], bh[p][1]);
                    mma16816(acc[mf][2 * p + 1], al[mf], bh[p][2], bh[p][3]);
                }
        }

        // ---- convert(c+1): own cp.async data, ordered by wait_group ----
        if (c + 1 < NC) {
            cp_wait<0>();
            convert(c + 1);  // writes AHL[(c+1)%2]; mma(c) reads AHL[c%2]
        }
        // ---- prefetch tile c+2 ----
        if (c + 2 < NC) {
            load_tile(c + 2);
            cp_commit();
        }
    }

#pragma unroll
    for (int mf = 0; mf < 2; mf++) {
        int r0 = bm0 + wm * 32 + mf * 16 + (lane >> 2);
#pragma unroll
        for (int nf = 0; nf < 8; nf++) {
            int col = bn0 + wn * 64 + nf * 8 + (lane & 3) * 2;
            if (r0 < M)
                *(float2*)(C + (size_t)r0 * 256 + col) =
                    make_float2(acc[mf][nf][0], acc[mf][nf][1]);
            if (r0 + 8 < M)
                *(float2*)(C + (size_t)(r0 + 8) * 256 + col) =
                    make_float2(acc[mf][nf][2], acc[mf][nf][3]);
        }
    }
}

// ===========================================================================
// pre-split GEMM for layers 2/3 (R7-proven, 3-pass MMA order)
// ===========================================================================
template <int BN>
__global__ __launch_bounds__(256)
void gemm_mma(const __nv_bfloat16* __restrict__ Ah, const __nv_bfloat16* __restrict__ Al,
              const __nv_bfloat16* __restrict__ Bh, const __nv_bfloat16* __restrict__ Bl,
              float* __restrict__ C, int M, int N, int Kp) {
    constexpr int WNCOL = BN / 2;
    constexpr int NFRAG = WNCOL / 8;
    constexpr int NPAIR = NFRAG / 2;
    constexpr int ABH = 8192;
    constexpr int BBH = BN * 64;
    constexpr int STAGE = 2 * ABH + 2 * BBH;

    extern __shared__ char smem[];
    const uint32_t sb = smem_u32(smem);

    const int tid = threadIdx.x;
    const int wid = tid >> 5, lane = tid & 31;
    const int wm = wid & 3, wn = wid >> 2;
    const int bm0 = blockIdx.y * 128;
    const int bn0 = blockIdx.x * BN;

    float acc[2][NFRAG][4];
#pragma unroll
    for (int i = 0; i < 2; i++)
#pragma unroll
        for (int j = 0; j < NFRAG; j++)
#pragma unroll
            for (int k = 0; k < 4; k++) acc[i][j][k] = 0.f;

    const int NC = Kp >> 5;

    auto load_stage = [&](int c, int stg) {
        const uint32_t base = sb + stg * STAGE;
        const size_t koff = (size_t)c * 32;
#pragma unroll
        for (int t = 0; t < 4; t++) {
            int i = tid + t * 256;
            int half = i >> 9;
            int rem = i & 511;
            int row = rem >> 2, ch = rem & 3;
            const __nv_bfloat16* src =
                (half ? Al : Ah) + (size_t)(bm0 + row) * Kp + koff + ch * 8;
            cp16(base + half * ABH + SWZ(row * 64 + ch * 16), src);
        }
#pragma unroll
        for (int t = 0; t < BN / 32; t++) {
            int i = tid + t * 256;
            int half = i / (BN * 4);
            int rem = i % (BN * 4);
            int row = rem >> 2, ch = rem & 3;
            const __nv_bfloat16* src =
                (half ? Bl : Bh) + (size_t)(bn0 + row) * Kp + koff + ch * 8;
            cp16(base + 2 * ABH + half * BBH + SWZ(row * 64 + ch * 16), src);
        }
    };

    const int a_row = wm * 32 + (lane & 15);
    const int a_chb = lane >> 4;
    const int b_row = wn * WNCOL + ((lane >> 4) & 1) * 8 + (lane & 7);
    const int b_chb = (lane >> 3) & 1;

    load_stage(0, 0);
    cp_commit();

    for (int c = 0; c < NC; c++) {
        if (c + 1 < NC) {
            load_stage(c + 1, (c + 1) & 1);
            cp_commit();
            cp_wait<1>();
        } else {
            cp_wait<0>();
        }
        __syncthreads();

        const uint32_t base = sb + (c & 1) * STAGE;
        const uint32_t aH = base, aL = base + ABH;
        const uint32_t bH = base + 2 * ABH, bL = bH + BBH;

#pragma unroll
        for (int ks = 0; ks < 2; ks++) {
            uint32_t ah[2][4], al[2][4];
#pragma unroll
            for (int mf = 0; mf < 2; mf++) {
                uint32_t off = SWZ((a_row + mf * 16) * 64 + (ks * 2 + a_chb) * 16);
                ldsm4(ah[mf], aH + off);
                ldsm4(al[mf], aL + off);
            }
            uint32_t bh[NPAIR][4], bl[NPAIR][4];
#pragma unroll
            for (int p = 0; p < NPAIR; p++) {
                uint32_t off = SWZ((b_row + p * 16) * 64 + (ks * 2 + b_chb) * 16);
                ldsm4(bh[p], bH + off);
                ldsm4(bl[p], bL + off);
            }
#pragma unroll
            for (int mf = 0; mf < 2; mf++)
#pragma unroll
                for (int p = 0; p < NPAIR; p++) {
                    mma16816(acc[mf][2 * p],     ah[mf], bh[p][0], bh[p][1]);
                    mma16816(acc[mf][2 * p + 1], ah[mf], bh[p][2], bh[p][3]);
                }
#pragma unroll
            for (int mf = 0; mf < 2; mf++)
#pragma unroll
                for (int p = 0; p < NPAIR; p++) {
                    mma16816(acc[mf][2 * p],     ah[mf], bl[p][0], bl[p][1]);
                    mma16816(acc[mf][2 * p + 1], ah[mf], bl[p][2], bl[p][3]);
                }
#pragma unroll
            for (int mf = 0; mf < 2; mf++)
#pragma unroll
                for (int p = 0; p < NPAIR; p++) {
                    mma16816(acc[mf][2 * p],     al[mf], bh[p][0], bh[p][1]);
                    mma16816(acc[mf][2 * p + 1], al[mf], bh[p][2], bh[p][3]);
                }
        }
        __syncthreads();
    }

#pragma unroll
    for (int mf = 0; mf < 2; mf++) {
        int r0 = bm0 + wm * 32 + mf * 16 + (lane >> 2);
#pragma unroll
        for (int nf = 0; nf < NFRAG; nf++) {
            int col = bn0 + wn * WNCOL + nf * 8 + (lane & 3) * 2;
            if (r0 < M)
                *(float2*)(C + (size_t)r0 * N + col) =
                    make_float2(acc[mf][nf][0], acc[mf][nf][1]);
            if (r0 + 8 < M)
                *(float2*)(C + (size_t)(r0 + 8) * N + col) =
                    make_float2(acc[mf][nf][2], acc[mf][nf][3]);
        }
    }
}

// ===========================================================================
// es/ed logits (one warp per node)
// ===========================================================================
__global__ void es_ed4(const float* __restrict__ h,
                       const float* __restrict__ a_src,
                       const float* __restrict__ a_dst,
                       float* __restrict__ es, float* __restrict__ ed, int n) {
    int w = (blockIdx.x * blockDim.x + threadIdx.x) >> 5;
    int lane = threadIdx.x & 31;
    if (w >= n) return;
    int c = lane * 8;
    const float* hp = h + (size_t)w * 256 + c;
    float4 v0 = *(const float4*)(hp);
    float4 v1 = *(const float4*)(hp + 4);
    float4 as0 = *(const float4*)(a_src + c);
    float4 as1 = *(const float4*)(a_src + c + 4);
    float4 ad0 = *(const float4*)(a_dst + c);
    float4 ad1 = *(const float4*)(a_dst + c + 4);
    float s = v0.x * as0.x + v0.y * as0.y + v0.z * as0.z + v0.w * as0.w +
              v1.x * as1.x + v1.y * as1.y + v1.z * as1.z + v1.w * as1.w;
    float d = v0.x * ad0.x + v0.y * ad0.y + v0.z * ad0.z + v0.w * ad0.w +
              v1.x * ad1.x + v1.y * ad1.y + v1.z * ad1.z + v1.w * ad1.w;
#pragma unroll
    for (int o = 4; o; o >>= 1) {
        s += __shfl_xor_sync(0xffffffffu, s, o);
        d += __shfl_xor_sync(0xffffffffu, d, o);
    }
    if ((lane & 7) == 0) {
        int head = lane >> 3;
        es[w * 4 + head] = s;
        ed[w * 4 + head] = d;
    }
}

__global__ void es_ed1(const float* __restrict__ h,
                       const float* __restrict__ a_src,
                       const float* __restrict__ a_dst,
                       float* __restrict__ es, float* __restrict__ ed, int n) {
    int w = (blockIdx.x * blockDim.x + threadIdx.x) >> 5;
    int lane = threadIdx.x & 31;
    if (w >= n) return;
    int c = lane * 2;
    float2 v = *(const float2*)(h + (size_t)w * 64 + c);
    float2 as = *(const float2*)(a_src + c);
    float2 ad = *(const float2*)(a_dst + c);
    float s = v.x * as.x + v.y * as.y;
    float d = v.x * ad.x + v.y * ad.y;
#pragma unroll
    for (int o = 16; o; o >>= 1) {
        s += __shfl_xor_sync(0xffffffffu, s, o);
        d += __shfl_xor_sync(0xffffffffu, d, o);
    }
    if (lane == 0) { es[w] = s; ed[w] = d; }
}

// ===========================================================================
// agg_gather4: one warp per dst node, register accumulate, fused
// normalize/bias/ELU/bf16-split (proven R7)
// ===========================================================================
__global__ void agg_gather4(const int* __restrict__ rowoff, const int* __restrict__ csrsrc,
                            const float* __restrict__ es, const float* __restrict__ ed,
                            const float* __restrict__ h, const float* __restrict__ b,
                            __nv_bfloat16* __restrict__ Hh, __nv_bfloat16* __restrict__ Hl,
                            int n, int Mp) {
    int w = (blockIdx.x * blockDim.x + threadIdx.x) >> 5;
    int lane = threadIdx.x & 31;
    if (w >= Mp) return;
    const int c0 = lane * 4;
    if (w >= n) {
        *(uint2*)(Hh + (size_t)w * 256 + c0) = make_uint2(0, 0);
        *(uint2*)(Hh + (size_t)w * 256 + c0 + 128) = make_uint2(0, 0);
        *(uint2*)(Hl + (size_t)w * 256 + c0) = make_uint2(0, 0);
        *(uint2*)(Hl + (size_t)w * 256 + c0 + 128) = make_uint2(0, 0);
        return;
    }
    const int myh = lane & 3;
    const int hs = (lane >> 4) & 1;
    float4 ed4 = *(const float4*)(ed + w * 4);
    float edh = sel4(ed4, myh);

    float4 es4 = *(const float4*)(es + w * 4);
    float e = sel4(es4, myh) + edh;
    e = e > 0.f ? e : 0.2f * e;
    float wv = __expf(e);
    float den = wv;
    float al0 = __shfl_sync(0xffffffffu, wv, hs);
    float al1 = __shfl_sync(0xffffffffu, wv, 2 + hs);

    const float* hp = h + (size_t)w * 256;
    float4 a0 = *(const float4*)(hp + c0);
    float4 a1 = *(const float4*)(hp + c0 + 128);
    a0.x *= al0; a0.y *= al0; a0.z *= al0; a0.w *= al0;
    a1.x *= al1; a1.y *= al1; a1.z *= al1; a1.w *= al1;

    int j0 = rowoff[w], j1 = rowoff[w + 1];
    int s = (j0 < j1) ? csrsrc[j0] : 0;
    for (int j = j0; j < j1; j++) {
        int snext = (j + 1 < j1) ? csrsrc[j + 1] : 0;
        float4 e4 = *(const float4*)(es + s * 4);
        float ee = sel4(e4, myh) + edh;
        ee = ee > 0.f ? ee : 0.2f * ee;
        float wj = __expf(ee);
        den += wj;
        float b0 = __shfl_sync(0xffffffffu, wj, hs);
        float b1 = __shfl_sync(0xffffffffu, wj, 2 + hs);
        const float* sp = h + (size_t)s * 256;
        float4 v0 = *(const float4*)(sp + c0);
        float4 v1 = *(const float4*)(sp + c0 + 128);
        a0.x += b0 * v0.x; a0.y += b0 * v0.y; a0.z += b0 * v0.z; a0.w += b0 * v0.w;
        a1.x += b1 * v1.x; a1.y += b1 * v1.y; a1.z += b1 * v1.z; a1.w += b1 * v1.w;
        s = snext;
    }
    float inv0 = __fdividef(1.f, __shfl_sync(0xffffffffu, den, hs));
    float inv1 = __fdividef(1.f, __shfl_sync(0xffffffffu, den, 2 + hs));

    float4 bb0 = *(const float4*)(b + c0);
    float4 bb1 = *(const float4*)(b + c0 + 128);
    float f0[4] = {a0.x * inv0 + bb0.x, a0.y * inv0 + bb0.y,
                   a0.z * inv0 + bb0.z, a0.w * inv0 + bb0.w};
    float f1[4] = {a1.x * inv1 + bb1.x, a1.y * inv1 + bb1.y,
                   a1.z * inv1 + bb1.z, a1.w * inv1 + bb1.w};
#pragma unroll
    for (int k = 0; k < 4; k++) {
        f0[k] = f0[k] > 0.f ? f0[k] : expm1f(f0[k]);
        f1[k] = f1[k] > 0.f ? f1[k] : expm1f(f1[k]);
    }
    uint32_t h0a = bfpack(f0[0], f0[1]), h0b = bfpack(f0[2], f0[3]);
    uint32_t h1a = bfpack(f1[0], f1[1]), h1b = bfpack(f1[2], f1[3]);
    float r0[4], r1[4];
#pragma unroll
    for (int k = 0; k < 4; k++) {
        r0[k] = f0[k] - bfhi(f0[k]);
        r1[k] = f1[k] - bfhi(f1[k]);
    }
    size_t o = (size_t)w * 256 + c0;
    *(uint2*)(Hh + o)       = make_uint2(h0a, h0b);
    *(uint2*)(Hh + o + 128) = make_uint2(h1a, h1b);
    *(uint2*)(Hl + o)       = make_uint2(bfpack(r0[0], r0[1]), bfpack(r0[2], r0[3]));
    *(uint2*)(Hl + o + 128) = make_uint2(bfpack(r1[0], r1[1]), bfpack(r1[2], r1[3]));
}

// ===========================================================================
// agg_gather1 + classifier (proven R7)
// ===========================================================================
__global__ void agg_gather1(const int* __restrict__ rowoff, const int* __restrict__ csrsrc,
                            const float* __restrict__ es, const float* __restrict__ ed,
                            const float* __restrict__ h, const float* __restrict__ b3,
                            const float* __restrict__ Wc, const float* __restrict__ bc,
                            float* __restrict__ out, int n) {
    int w = (blockIdx.x * blockDim.x + threadIdx.x) >> 5;
    int lane = threadIdx.x & 31;
    if (w >= n) return;
    float edw = ed[w];
    float e = es[w] + edw;
    e = e > 0.f ? e : 0.2f * e;
    float wv = __expf(e);
    float den = wv;
    float v0 = h[(size_t)w * 64 + lane] * wv;
    float v1 = h[(size_t)w * 64 + lane + 32] * wv;

    int j0 = rowoff[w], j1 = rowoff[w + 1];
    int s = (j0 < j1) ? csrsrc[j0] : 0;
    for (int j = j0; j < j1; j++) {
        int snext = (j + 1 < j1) ? csrsrc[j + 1] : 0;
        float ee = es[s] + edw;
        ee = ee > 0.f ? ee : 0.2f * ee;
        float wj = __expf(ee);
        den += wj;
        v0 += wj * h[(size_t)s * 64 + lane];
        v1 += wj * h[(size_t)s * 64 + lane + 32];
        s = snext;
    }
    float inv = __fdividef(1.f, den);
    v0 = v0 * inv + b3[lane];
    v0 = v0 > 0.f ? v0 : expm1f(v0);
    v1 = v1 * inv + b3[lane + 32];
    v1 = v1 > 0.f ? v1 : expm1f(v1);
#pragma unroll
    for (int j = 0; j < 3; j++) {
        float p = v0 * Wc[lane * 3 + j] + v1 * Wc[(lane + 32) * 3 + j];
#pragma unroll
        for (int o = 16; o; o >>= 1) p += __shfl_xor_sync(0xffffffffu, p, o);
        if (lane == 0) out[w * 3 + j] = p + bc[j];
    }
}

// ===========================================================================
// W [K,N] fp32 -> hi/lo bf16 [N,Kp]
// ===========================================================================
__global__ void conv_wT(const float* __restrict__ W,
                        __nv_bfloat16* __restrict__ Bh,
                        __nv_bfloat16* __restrict__ Bl,
                        int K, int N, int Kp) {
    int idx = blockIdx.x * blockDim.x + threadIdx.x;
    if (idx >= N * Kp) return;
    int n = idx / Kp, k = idx - n * Kp;
    float v = (k < K) ? W[(size_t)k * N + n] : 0.f;
    __nv_bfloat16 h = __float2bfloat16_rn(v);
    __nv_bfloat16 l = __float2bfloat16_rn(v - __bfloat162float(h));
    Bh[(size_t)n * Kp + k] = h;
    Bl[(size_t)n * Kp + k] = l;
}

// ===========================================================================
static inline int cdiv(int a, int b) { return (a + b - 1) / b; }

extern "C" void kernel_launch(void* const* d_in, const int* in_sizes, int n_in,
                              void* d_out, int out_size) {
    const float* x    = (const float*)d_in[0];
    const float* W1   = (const float*)d_in[1];
    const float* a1s  = (const float*)d_in[2];
    const float* a1d  = (const float*)d_in[3];
    const float* b1   = (const float*)d_in[4];
    const float* W2   = (const float*)d_in[5];
    const float* a2s  = (const float*)d_in[6];
    const float* a2d  = (const float*)d_in[7];
    const float* b2   = (const float*)d_in[8];
    const float* W3   = (const float*)d_in[9];
    const float* a3s  = (const float*)d_in[10];
    const float* a3d  = (const float*)d_in[11];
    const float* b3   = (const float*)d_in[12];
    const float* Wc   = (const float*)d_in[13];
    const float* bc   = (const float*)d_in[14];
    const int*   ei   = (const int*)d_in[15];
    float* out = (float*)d_out;

    const int N = GAT_N, E = GAT_E, Mp = GAT_Mp;
    const int* src = ei;
    const int* dst = ei + E;

    float *hA, *h3, *es, *ed;
    int *rowoff, *cursor, *csrsrc;
    __nv_bfloat16 *Ahp, *Alp, *Bhp, *Blp;
    cudaGetSymbolAddress((void**)&hA,     g_hA);
    cudaGetSymbolAddress((void**)&h3,     g_h3);
    cudaGetSymbolAddress((void**)&es,     g_es);
    cudaGetSymbolAddress((void**)&ed,     g_ed);
    cudaGetSymbolAddress((void**)&rowoff, g_rowoff);
    cudaGetSymbolAddress((void**)&cursor, g_cursor);
    cudaGetSymbolAddress((void**)&csrsrc, g_csrsrc);
    cudaGetSymbolAddress((void**)&Ahp,    g_Ah);
    cudaGetSymbolAddress((void**)&Alp,    g_Al);
    cudaGetSymbolAddress((void**)&Bhp,    g_Bh);
    cudaGetSymbolAddress((void**)&Blp,    g_Bl);

    const int SMF   = 114688;                          // AF 32K + AHL 32K + BHL 48K
    const int SM128 = 2 * (2 * 8192 + 2 * 128 * 64);
    const int SM64  = 2 * (2 * 8192 + 2 * 64 * 64);
    cudaFuncSetAttribute(gemm_fused,    cudaFuncAttributeMaxDynamicSharedMemorySize, SMF);
    cudaFuncSetAttribute(gemm_mma<128>, cudaFuncAttributeMaxDynamicSharedMemorySize, SM128);
    cudaFuncSetAttribute(gemm_mma<64>,  cudaFuncAttributeMaxDynamicSharedMemorySize, SM64);

    const int TB = 256;
    const int MT = Mp / 128;               // 235
    const int NPB = cdiv(N * 32, TB);      // warp-per-node blocks
    const int GPB = cdiv(Mp * 32, TB);     // warp-per-padded-node blocks

    // ---------------- CSR build ----------------
    csr_zero<<<cdiv(N, TB), TB>>>(cursor, N);
    csr_hist<<<cdiv(E, TB), TB>>>(dst, cursor, E);
    csr_scan<<<1, 1024>>>(cursor, rowoff, N);
    csr_fill<<<cdiv(E, TB), TB>>>(src, dst, cursor, csrsrc, E);

    // ---------------- layer 1 (H=4, K=5000) ----------------
    conv_wT<<<cdiv(256 * GAT_K1P, TB), TB>>>(W1, Bhp, Blp, GAT_DIN, 256, GAT_K1P);
    gemm_fused<<<dim3(2, MT), 256, SMF>>>(x, Bhp, Blp, hA, N, GAT_DIN, GAT_K1P);
    es_ed4<<<NPB, TB>>>(hA, a1s, a1d, es, ed, N);
    agg_gather4<<<GPB, TB>>>(rowoff, csrsrc, es, ed, hA, b1, Ahp, Alp, N, Mp);

    // ---------------- layer 2 (H=4, K=256) ----------------
    conv_wT<<<cdiv(256 * 256, TB), TB>>>(W2, Bhp, Blp, 256, 256, 256);
    gemm_mma<128><<<dim3(2, MT), 256, SM128>>>(Ahp, Alp, Bhp, Blp, hA, N, 256, 256);
    es_ed4<<<NPB, TB>>>(hA, a2s, a2d, es, ed, N);
    agg_gather4<<<GPB, TB>>>(rowoff, csrsrc, es, ed, hA, b2, Ahp, Alp, N, Mp);

    // ---------------- layer 3 (H=1, K=256, N=64) ----------------
    conv_wT<<<cdiv(64 * 256, TB), TB>>>(W3, Bhp, Blp, 256, 64, 256);
    gemm_mma<64><<<dim3(1, MT), 256, SM64>>>(Ahp, Alp, Bhp, Blp, h3, N, 64, 256);
    es_ed1<<<NPB, TB>>>(h3, a3s, a3d, es, ed, N);
    agg_gather1<<<NPB, TB>>>(rowoff, csrsrc, es, ed, h3, b3, Wc, bc, out, N);
}

// round 12
// speedup vs baseline: 1.6074x; 1.3570x over previous
#include <cuda_runtime.h>
#include <cuda_bf16.h>
#include <cuda_fp16.h>
#include <cstdint>

// ---------------------------------------------------------------------------
// SentimentGAT on GB300 (sm_103 baseline PTX):
//  layer 1: fp16 2-product GEMM (A=fp16(X), B=W1 split fp16 hi/lo)
//  layers 2/3: bf16x3 mma.sync GEMMs (proven)
//  CSR-gather attention with fused normalize/bias/ELU/split epilogues.
// ---------------------------------------------------------------------------

#define GAT_N   30000
#define GAT_Mp  30080               // 235 * 128
#define GAT_E   480000
#define GAT_DIN 5000
#define GAT_K1P 5056                // 79 * 64 (padded K stride for W1^T)

// ---- fp32 scratch ----
__device__ float g_hA[GAT_N * 256];
__device__ float g_h3[GAT_N * 64];
__device__ float g_es[GAT_N * 4];
__device__ float g_ed[GAT_N * 4];

// ---- CSR ----
__device__ int g_rowoff[GAT_N + 1];
__device__ int g_cursor[GAT_N];
__device__ int g_csrsrc[GAT_E];

// ---- bf16 hi/lo scratch (layers 2/3 A+B) ----
__device__ __align__(128) __nv_bfloat16 g_Ah[(size_t)GAT_Mp * 256];
__device__ __align__(128) __nv_bfloat16 g_Al[(size_t)GAT_Mp * 256];
__device__ __align__(128) __nv_bfloat16 g_Bh[256 * GAT_K1P];
__device__ __align__(128) __nv_bfloat16 g_Bl[256 * GAT_K1P];
// ---- fp16 hi/lo W1 (layer 1 B); aliases onto the same budget is fine ----
__device__ __align__(128) __half g_W1h[256 * GAT_K1P];
__device__ __align__(128) __half g_W1l[256 * GAT_K1P];

// ===========================================================================
// low-level helpers
// ===========================================================================
#define SWZ(o) ((o) ^ (((o) >> 3) & 0x70))

__device__ __forceinline__ uint32_t smem_u32(const void* p) {
    uint32_t a;
    asm("{ .reg .u64 t; cvta.to.shared.u64 t, %1; cvt.u32.u64 %0, t; }"
        : "=r"(a) : "l"(p));
    return a;
}
__device__ __forceinline__ void cp16(uint32_t d, const void* s) {
    asm volatile("cp.async.cg.shared.global [%0], [%1], 16;" :: "r"(d), "l"(s));
}
__device__ __forceinline__ void cp16z(uint32_t d, const void* s, bool pred) {
    int sz = pred ? 16 : 0;
    asm volatile("cp.async.cg.shared.global [%0], [%1], 16, %2;"
                 :: "r"(d), "l"(s), "r"(sz));
}
__device__ __forceinline__ void cp_commit() {
    asm volatile("cp.async.commit_group;" ::: "memory");
}
template <int Ng>
__device__ __forceinline__ void cp_wait() {
    asm volatile("cp.async.wait_group %0;" :: "n"(Ng) : "memory");
}
__device__ __forceinline__ void ldsm4(uint32_t (&r)[4], uint32_t addr) {
    asm volatile("ldmatrix.sync.aligned.m8n8.x4.shared.b16 {%0,%1,%2,%3}, [%4];"
                 : "=r"(r[0]), "=r"(r[1]), "=r"(r[2]), "=r"(r[3]) : "r"(addr));
}
__device__ __forceinline__ void mma16816(float (&d)[4], const uint32_t (&a)[4],
                                         uint32_t b0, uint32_t b1) {
    asm volatile("mma.sync.aligned.m16n8k16.row.col.f32.bf16.bf16.f32 "
                 "{%0,%1,%2,%3}, {%4,%5,%6,%7}, {%8,%9}, {%0,%1,%2,%3};"
                 : "+f"(d[0]), "+f"(d[1]), "+f"(d[2]), "+f"(d[3])
                 : "r"(a[0]), "r"(a[1]), "r"(a[2]), "r"(a[3]), "r"(b0), "r"(b1));
}
__device__ __forceinline__ void mma16816h(float (&d)[4], const uint32_t (&a)[4],
                                          uint32_t b0, uint32_t b1) {
    asm volatile("mma.sync.aligned.m16n8k16.row.col.f32.f16.f16.f32 "
                 "{%0,%1,%2,%3}, {%4,%5,%6,%7}, {%8,%9}, {%0,%1,%2,%3};"
                 : "+f"(d[0]), "+f"(d[1]), "+f"(d[2]), "+f"(d[3])
                 : "r"(a[0]), "r"(a[1]), "r"(a[2]), "r"(a[3]), "r"(b0), "r"(b1));
}
__device__ __forceinline__ uint32_t bfpack(float a, float b) {
    return (uint32_t)__bfloat16_as_ushort(__float2bfloat16_rn(a)) |
           ((uint32_t)__bfloat16_as_ushort(__float2bfloat16_rn(b)) << 16);
}
__device__ __forceinline__ uint32_t hpack(float a, float b) {
    return (uint32_t)__half_as_ushort(__float2half_rn(a)) |
           ((uint32_t)__half_as_ushort(__float2half_rn(b)) << 16);
}
__device__ __forceinline__ float bfhi(float x) {
    return __bfloat162float(__float2bfloat16_rn(x));
}
__device__ __forceinline__ float sel4(float4 v, int i) {
    float a = (i & 1) ? v.y : v.x;
    float b = (i & 1) ? v.w : v.z;
    return (i & 2) ? b : a;
}

// ===========================================================================
// CSR build
// ===========================================================================
__global__ void csr_zero(int* cur, int n) {
    int i = blockIdx.x * blockDim.x + threadIdx.x;
    if (i < n) cur[i] = 0;
}
__global__ void csr_hist(const int* __restrict__ dst, int* cur, int E_) {
    int i = blockIdx.x * blockDim.x + threadIdx.x;
    if (i < E_) atomicAdd(&cur[dst[i]], 1);
}
__global__ void csr_scan(int* degcur, int* rowoff, int n) {
    __shared__ int sh[1024];
    __shared__ int carry_s;
    int tid = threadIdx.x;
    if (tid == 0) carry_s = 0;
    __syncthreads();
    for (int base = 0; base < n; base += 1024) {
        int i = base + tid;
        int v = (i < n) ? degcur[i] : 0;
        sh[tid] = v;
        __syncthreads();
#pragma unroll
        for (int o = 1; o < 1024; o <<= 1) {
            int t = (tid >= o) ? sh[tid - o] : 0;
            __syncthreads();
            sh[tid] += t;
            __syncthreads();
        }
        int excl = sh[tid] - v + carry_s;
        if (i < n) { rowoff[i] = excl; degcur[i] = excl; }
        __syncthreads();
        if (tid == 1023) carry_s += sh[1023];
        __syncthreads();
    }
    if (tid == 0) rowoff[n] = carry_s;
}
__global__ void csr_fill(const int* __restrict__ src, const int* __restrict__ dst,
                         int* cur, int* csrsrc, int E_) {
    int i = blockIdx.x * blockDim.x + threadIdx.x;
    if (i < E_) {
        int p = atomicAdd(&cur[dst[i]], 1);
        csrsrc[p] = src[i];
    }
}

// ===========================================================================
// FUSED layer-1 GEMM (fp16, 2 products): C = fp16(X) @ (W1h + W1l)^T
// BK=32 single-barrier pipeline, self-consistent convert (fp32->fp16, hi only).
// smem: AF 0..32K (x2 ring 16K) | AH 32K..48K (x2 ring 8K) | BHL 48K..96K (x3 16K)
// 96 KB/CTA -> 2 CTAs/SM.
// ===========================================================================
__global__ __launch_bounds__(256)
void gemm_fused(const float* __restrict__ X,
                const __half* __restrict__ Bh, const __half* __restrict__ Bl,
                float* __restrict__ C, int M, int K, int KpB) {
    extern __shared__ char smem[];
    const uint32_t sb = smem_u32(smem);

    const int tid = threadIdx.x;
    const int wid = tid >> 5, lane = tid & 31;
    const int wm = wid & 3, wn = wid >> 2;
    const int bm0 = blockIdx.y * 128;
    const int bn0 = blockIdx.x * 128;

    float acc[2][8][4];
#pragma unroll
    for (int i = 0; i < 2; i++)
#pragma unroll
        for (int j = 0; j < 8; j++)
#pragma unroll
            for (int k = 0; k < 4; k++) acc[i][j][k] = 0.f;

    const int NC = (K + 31) >> 5;

    auto load_tile = [&](int c) {   // A -> AF[c%2], B -> BHL[c%3]
        const uint32_t af = sb + (c & 1) * 16384;
        const uint32_t bb = sb + 49152 + (c % 3) * 16384;
        const int k0 = c * 32;
#pragma unroll
        for (int t = 0; t < 4; t++) {
            int i = tid + t * 256;
            int row = i >> 3, q = i & 7;
            int gm = bm0 + row, gk = k0 + q * 4;
            bool p = (gm < M) && (gk < K);
            cp16z(af + row * 128 + q * 16, X + (p ? ((size_t)gm * K + gk) : 0), p);
        }
#pragma unroll
        for (int t = 0; t < 4; t++) {
            int i = tid + t * 256;
            int half_ = i >> 9;
            int rem = i & 511;
            int row = rem >> 2, ch = rem & 3;
            const __half* src =
                (half_ ? Bl : Bh) + (size_t)(bn0 + row) * KpB + k0 + ch * 8;
            cp16(bb + half_ * 8192 + SWZ(row * 64 + ch * 16), src);
        }
    };

    auto convert = [&](int c) {     // AF[c%2] -> AH[c%2] (fp16, hi only), own data
        const int s2 = c & 1;
        const char* afp = smem + s2 * 16384;
        char* ahp = smem + 32768 + s2 * 8192;
#pragma unroll
        for (int t = 0; t < 4; t++) {
            int i = tid + t * 256;
            int row = i >> 3, q = i & 7;
            float4 v = *(const float4*)(afp + row * 128 + q * 16);
            uint32_t h0 = hpack(v.x, v.y);
            uint32_t h1 = hpack(v.z, v.w);
            uint32_t off = SWZ(row * 64 + (q & 6) * 8) + (q & 1) * 8;
            *(uint2*)(ahp + off) = make_uint2(h0, h1);
        }
    };

    const int a_row = wm * 32 + (lane & 15);
    const int a_chb = lane >> 4;
    const int b_row = wn * 64 + ((lane >> 4) & 1) * 8 + (lane & 7);
    const int b_chb = (lane >> 3) & 1;

    // prologue
    load_tile(0); cp_commit();
    if (NC > 1) { load_tile(1); cp_commit(); }
    cp_wait<1>();
    convert(0);

    for (int c = 0; c < NC; c++) {
        __syncthreads();     // publish convert(c) to all warps

        const uint32_t aH = sb + 32768 + (c & 1) * 8192;
        const uint32_t bH = sb + 49152 + (c % 3) * 16384;
        const uint32_t bL = bH + 8192;
#pragma unroll
        for (int ks = 0; ks < 2; ks++) {
            uint32_t ah[2][4];
#pragma unroll
            for (int mf = 0; mf < 2; mf++) {
                uint32_t off = SWZ((a_row + mf * 16) * 64 + (ks * 2 + a_chb) * 16);
                ldsm4(ah[mf], aH + off);
            }
            uint32_t bh[4][4], bl[4][4];
#pragma unroll
            for (int p = 0; p < 4; p++) {
                uint32_t off = SWZ((b_row + p * 16) * 64 + (ks * 2 + b_chb) * 16);
                ldsm4(bh[p], bH + off);
                ldsm4(bl[p], bL + off);
            }
            // 2 passes of 16 independent fp16 MMAs; per-acc order hh,hl
#pragma unroll
            for (int mf = 0; mf < 2; mf++)
#pragma unroll
                for (int p = 0; p < 4; p++) {
                    mma16816h(acc[mf][2 * p],     ah[mf], bh[p][0], bh[p][1]);
                    mma16816h(acc[mf][2 * p + 1], ah[mf], bh[p][2], bh[p][3]);
                }
#pragma unroll
            for (int mf = 0; mf < 2; mf++)
#pragma unroll
                for (int p = 0; p < 4; p++) {
                    mma16816h(acc[mf][2 * p],     ah[mf], bl[p][0], bl[p][1]);
                    mma16816h(acc[mf][2 * p + 1], ah[mf], bl[p][2], bl[p][3]);
                }
        }

        if (c + 1 < NC) {
            cp_wait<0>();
            convert(c + 1);
        }
        if (c + 2 < NC) {
            load_tile(c + 2);
            cp_commit();
        }
    }

#pragma unroll
    for (int mf = 0; mf < 2; mf++) {
        int r0 = bm0 + wm * 32 + mf * 16 + (lane >> 2);
#pragma unroll
        for (int nf = 0; nf < 8; nf++) {
            int col = bn0 + wn * 64 + nf * 8 + (lane & 3) * 2;
            if (r0 < M)
                *(float2*)(C + (size_t)r0 * 256 + col) =
                    make_float2(acc[mf][nf][0], acc[mf][nf][1]);
            if (r0 + 8 < M)
                *(float2*)(C + (size_t)(r0 + 8) * 256 + col) =
                    make_float2(acc[mf][nf][2], acc[mf][nf][3]);
        }
    }
}

// ===========================================================================
// pre-split bf16x3 GEMM for layers 2/3 (proven)
// ===========================================================================
template <int BN>
__global__ __launch_bounds__(256)
void gemm_mma(const __nv_bfloat16* __restrict__ Ah, const __nv_bfloat16* __restrict__ Al,
              const __nv_bfloat16* __restrict__ Bh, const __nv_bfloat16* __restrict__ Bl,
              float* __restrict__ C, int M, int N, int Kp) {
    constexpr int WNCOL = BN / 2;
    constexpr int NFRAG = WNCOL / 8;
    constexpr int NPAIR = NFRAG / 2;
    constexpr int ABH = 8192;
    constexpr int BBH = BN * 64;
    constexpr int STAGE = 2 * ABH + 2 * BBH;

    extern __shared__ char smem[];
    const uint32_t sb = smem_u32(smem);

    const int tid = threadIdx.x;
    const int wid = tid >> 5, lane = tid & 31;
    const int wm = wid & 3, wn = wid >> 2;
    const int bm0 = blockIdx.y * 128;
    const int bn0 = blockIdx.x * BN;

    float acc[2][NFRAG][4];
#pragma unroll
    for (int i = 0; i < 2; i++)
#pragma unroll
        for (int j = 0; j < NFRAG; j++)
#pragma unroll
            for (int k = 0; k < 4; k++) acc[i][j][k] = 0.f;

    const int NC = Kp >> 5;

    auto load_stage = [&](int c, int stg) {
        const uint32_t base = sb + stg * STAGE;
        const size_t koff = (size_t)c * 32;
#pragma unroll
        for (int t = 0; t < 4; t++) {
            int i = tid + t * 256;
            int half = i >> 9;
            int rem = i & 511;
            int row = rem >> 2, ch = rem & 3;
            const __nv_bfloat16* src =
                (half ? Al : Ah) + (size_t)(bm0 + row) * Kp + koff + ch * 8;
            cp16(base + half * ABH + SWZ(row * 64 + ch * 16), src);
        }
#pragma unroll
        for (int t = 0; t < BN / 32; t++) {
            int i = tid + t * 256;
            int half = i / (BN * 4);
            int rem = i % (BN * 4);
            int row = rem >> 2, ch = rem & 3;
            const __nv_bfloat16* src =
                (half ? Bl : Bh) + (size_t)(bn0 + row) * Kp + koff + ch * 8;
            cp16(base + 2 * ABH + half * BBH + SWZ(row * 64 + ch * 16), src);
        }
    };

    const int a_row = wm * 32 + (lane & 15);
    const int a_chb = lane >> 4;
    const int b_row = wn * WNCOL + ((lane >> 4) & 1) * 8 + (lane & 7);
    const int b_chb = (lane >> 3) & 1;

    load_stage(0, 0);
    cp_commit();

    for (int c = 0; c < NC; c++) {
        if (c + 1 < NC) {
            load_stage(c + 1, (c + 1) & 1);
            cp_commit();
            cp_wait<1>();
        } else {
            cp_wait<0>();
        }
        __syncthreads();

        const uint32_t base = sb + (c & 1) * STAGE;
        const uint32_t aH = base, aL = base + ABH;
        const uint32_t bH = base + 2 * ABH, bL = bH + BBH;

#pragma unroll
        for (int ks = 0; ks < 2; ks++) {
            uint32_t ah[2][4], al[2][4];
#pragma unroll
            for (int mf = 0; mf < 2; mf++) {
                uint32_t off = SWZ((a_row + mf * 16) * 64 + (ks * 2 + a_chb) * 16);
                ldsm4(ah[mf], aH + off);
                ldsm4(al[mf], aL + off);
            }
            uint32_t bh[NPAIR][4], bl[NPAIR][4];
#pragma unroll
            for (int p = 0; p < NPAIR; p++) {
                uint32_t off = SWZ((b_row + p * 16) * 64 + (ks * 2 + b_chb) * 16);
                ldsm4(bh[p], bH + off);
                ldsm4(bl[p], bL + off);
            }
#pragma unroll
            for (int mf = 0; mf < 2; mf++)
#pragma unroll
                for (int p = 0; p < NPAIR; p++) {
                    mma16816(acc[mf][2 * p],     ah[mf], bh[p][0], bh[p][1]);
                    mma16816(acc[mf][2 * p + 1], ah[mf], bh[p][2], bh[p][3]);
                }
#pragma unroll
            for (int mf = 0; mf < 2; mf++)
#pragma unroll
                for (int p = 0; p < NPAIR; p++) {
                    mma16816(acc[mf][2 * p],     ah[mf], bl[p][0], bl[p][1]);
                    mma16816(acc[mf][2 * p + 1], ah[mf], bl[p][2], bl[p][3]);
                }
#pragma unroll
            for (int mf = 0; mf < 2; mf++)
#pragma unroll
                for (int p = 0; p < NPAIR; p++) {
                    mma16816(acc[mf][2 * p],     al[mf], bh[p][0], bh[p][1]);
                    mma16816(acc[mf][2 * p + 1], al[mf], bh[p][2], bh[p][3]);
                }
        }
        __syncthreads();
    }

#pragma unroll
    for (int mf = 0; mf < 2; mf++) {
        int r0 = bm0 + wm * 32 + mf * 16 + (lane >> 2);
#pragma unroll
        for (int nf = 0; nf < NFRAG; nf++) {
            int col = bn0 + wn * WNCOL + nf * 8 + (lane & 3) * 2;
            if (r0 < M)
                *(float2*)(C + (size_t)r0 * N + col) =
                    make_float2(acc[mf][nf][0], acc[mf][nf][1]);
            if (r0 + 8 < M)
                *(float2*)(C + (size_t)(r0 + 8) * N + col) =
                    make_float2(acc[mf][nf][2], acc[mf][nf][3]);
        }
    }
}

// ===========================================================================
// es/ed logits (one warp per node)
// ===========================================================================
__global__ void es_ed4(const float* __restrict__ h,
                       const float* __restrict__ a_src,
                       const float* __restrict__ a_dst,
                       float* __restrict__ es, float* __restrict__ ed, int n) {
    int w = (blockIdx.x * blockDim.x + threadIdx.x) >> 5;
    int lane = threadIdx.x & 31;
    if (w >= n) return;
    int c = lane * 8;
    const float* hp = h + (size_t)w * 256 + c;
    float4 v0 = *(const float4*)(hp);
    float4 v1 = *(const float4*)(hp + 4);
    float4 as0 = *(const float4*)(a_src + c);
    float4 as1 = *(const float4*)(a_src + c + 4);
    float4 ad0 = *(const float4*)(a_dst + c);
    float4 ad1 = *(const float4*)(a_dst + c + 4);
    float s = v0.x * as0.x + v0.y * as0.y + v0.z * as0.z + v0.w * as0.w +
              v1.x * as1.x + v1.y * as1.y + v1.z * as1.z + v1.w * as1.w;
    float d = v0.x * ad0.x + v0.y * ad0.y + v0.z * ad0.z + v0.w * ad0.w +
              v1.x * ad1.x + v1.y * ad1.y + v1.z * ad1.z + v1.w * ad1.w;
#pragma unroll
    for (int o = 4; o; o >>= 1) {
        s += __shfl_xor_sync(0xffffffffu, s, o);
        d += __shfl_xor_sync(0xffffffffu, d, o);
    }
    if ((lane & 7) == 0) {
        int head = lane >> 3;
        es[w * 4 + head] = s;
        ed[w * 4 + head] = d;
    }
}

__global__ void es_ed1(const float* __restrict__ h,
                       const float* __restrict__ a_src,
                       const float* __restrict__ a_dst,
                       float* __restrict__ es, float* __restrict__ ed, int n) {
    int w = (blockIdx.x * blockDim.x + threadIdx.x) >> 5;
    int lane = threadIdx.x & 31;
    if (w >= n) return;
    int c = lane * 2;
    float2 v = *(const float2*)(h + (size_t)w * 64 + c);
    float2 as = *(const float2*)(a_src + c);
    float2 ad = *(const float2*)(a_dst + c);
    float s = v.x * as.x + v.y * as.y;
    float d = v.x * ad.x + v.y * ad.y;
#pragma unroll
    for (int o = 16; o; o >>= 1) {
        s += __shfl_xor_sync(0xffffffffu, s, o);
        d += __shfl_xor_sync(0xffffffffu, d, o);
    }
    if (lane == 0) { es[w] = s; ed[w] = d; }
}

// ===========================================================================
// agg_gather4 (proven R7)
// ===========================================================================
__global__ void agg_gather4(const int* __restrict__ rowoff, const int* __restrict__ csrsrc,
                            const float* __restrict__ es, const float* __restrict__ ed,
                            const float* __restrict__ h, const float* __restrict__ b,
                            __nv_bfloat16* __restrict__ Hh, __nv_bfloat16* __restrict__ Hl,
                            int n, int Mp) {
    int w = (blockIdx.x * blockDim.x + threadIdx.x) >> 5;
    int lane = threadIdx.x & 31;
    if (w >= Mp) return;
    const int c0 = lane * 4;
    if (w >= n) {
        *(uint2*)(Hh + (size_t)w * 256 + c0) = make_uint2(0, 0);
        *(uint2*)(Hh + (size_t)w * 256 + c0 + 128) = make_uint2(0, 0);
        *(uint2*)(Hl + (size_t)w * 256 + c0) = make_uint2(0, 0);
        *(uint2*)(Hl + (size_t)w * 256 + c0 + 128) = make_uint2(0, 0);
        return;
    }
    const int myh = lane & 3;
    const int hs = (lane >> 4) & 1;
    float4 ed4 = *(const float4*)(ed + w * 4);
    float edh = sel4(ed4, myh);

    float4 es4 = *(const float4*)(es + w * 4);
    float e = sel4(es4, myh) + edh;
    e = e > 0.f ? e : 0.2f * e;
    float wv = __expf(e);
    float den = wv;
    float al0 = __shfl_sync(0xffffffffu, wv, hs);
    float al1 = __shfl_sync(0xffffffffu, wv, 2 + hs);

    const float* hp = h + (size_t)w * 256;
    float4 a0 = *(const float4*)(hp + c0);
    float4 a1 = *(const float4*)(hp + c0 + 128);
    a0.x *= al0; a0.y *= al0; a0.z *= al0; a0.w *= al0;
    a1.x *= al1; a1.y *= al1; a1.z *= al1; a1.w *= al1;

    int j0 = rowoff[w], j1 = rowoff[w + 1];
    int s = (j0 < j1) ? csrsrc[j0] : 0;
    for (int j = j0; j < j1; j++) {
        int snext = (j + 1 < j1) ? csrsrc[j + 1] : 0;
        float4 e4 = *(const float4*)(es + s * 4);
        float ee = sel4(e4, myh) + edh;
        ee = ee > 0.f ? ee : 0.2f * ee;
        float wj = __expf(ee);
        den += wj;
        float b0 = __shfl_sync(0xffffffffu, wj, hs);
        float b1 = __shfl_sync(0xffffffffu, wj, 2 + hs);
        const float* sp = h + (size_t)s * 256;
        float4 v0 = *(const float4*)(sp + c0);
        float4 v1 = *(const float4*)(sp + c0 + 128);
        a0.x += b0 * v0.x; a0.y += b0 * v0.y; a0.z += b0 * v0.z; a0.w += b0 * v0.w;
        a1.x += b1 * v1.x; a1.y += b1 * v1.y; a1.z += b1 * v1.z; a1.w += b1 * v1.w;
        s = snext;
    }
    float inv0 = __fdividef(1.f, __shfl_sync(0xffffffffu, den, hs));
    float inv1 = __fdividef(1.f, __shfl_sync(0xffffffffu, den, 2 + hs));

    float4 bb0 = *(const float4*)(b + c0);
    float4 bb1 = *(const float4*)(b + c0 + 128);
    float f0[4] = {a0.x * inv0 + bb0.x, a0.y * inv0 + bb0.y,
                   a0.z * inv0 + bb0.z, a0.w * inv0 + bb0.w};
    float f1[4] = {a1.x * inv1 + bb1.x, a1.y * inv1 + bb1.y,
                   a1.z * inv1 + bb1.z, a1.w * inv1 + bb1.w};
#pragma unroll
    for (int k = 0; k < 4; k++) {
        f0[k] = f0[k] > 0.f ? f0[k] : expm1f(f0[k]);
        f1[k] = f1[k] > 0.f ? f1[k] : expm1f(f1[k]);
    }
    uint32_t h0a = bfpack(f0[0], f0[1]), h0b = bfpack(f0[2], f0[3]);
    uint32_t h1a = bfpack(f1[0], f1[1]), h1b = bfpack(f1[2], f1[3]);
    float r0[4], r1[4];
#pragma unroll
    for (int k = 0; k < 4; k++) {
        r0[k] = f0[k] - bfhi(f0[k]);
        r1[k] = f1[k] - bfhi(f1[k]);
    }
    size_t o = (size_t)w * 256 + c0;
    *(uint2*)(Hh + o)       = make_uint2(h0a, h0b);
    *(uint2*)(Hh + o + 128) = make_uint2(h1a, h1b);
    *(uint2*)(Hl + o)       = make_uint2(bfpack(r0[0], r0[1]), bfpack(r0[2], r0[3]));
    *(uint2*)(Hl + o + 128) = make_uint2(bfpack(r1[0], r1[1]), bfpack(r1[2], r1[3]));
}

// ===========================================================================
// agg_gather1 + classifier (proven R7)
// ===========================================================================
__global__ void agg_gather1(const int* __restrict__ rowoff, const int* __restrict__ csrsrc,
                            const float* __restrict__ es, const float* __restrict__ ed,
                            const float* __restrict__ h, const float* __restrict__ b3,
                            const float* __restrict__ Wc, const float* __restrict__ bc,
                            float* __restrict__ out, int n) {
    int w = (blockIdx.x * blockDim.x + threadIdx.x) >> 5;
    int lane = threadIdx.x & 31;
    if (w >= n) return;
    float edw = ed[w];
    float e = es[w] + edw;
    e = e > 0.f ? e : 0.2f * e;
    float wv = __expf(e);
    float den = wv;
    float v0 = h[(size_t)w * 64 + lane] * wv;
    float v1 = h[(size_t)w * 64 + lane + 32] * wv;

    int j0 = rowoff[w], j1 = rowoff[w + 1];
    int s = (j0 < j1) ? csrsrc[j0] : 0;
    for (int j = j0; j < j1; j++) {
        int snext = (j + 1 < j1) ? csrsrc[j + 1] : 0;
        float ee = es[s] + edw;
        ee = ee > 0.f ? ee : 0.2f * ee;
        float wj = __expf(ee);
        den += wj;
        v0 += wj * h[(size_t)s * 64 + lane];
        v1 += wj * h[(size_t)s * 64 + lane + 32];
        s = snext;
    }
    float inv = __fdividef(1.f, den);
    v0 = v0 * inv + b3[lane];
    v0 = v0 > 0.f ? v0 : expm1f(v0);
    v1 = v1 * inv + b3[lane + 32];
    v1 = v1 > 0.f ? v1 : expm1f(v1);
#pragma unroll
    for (int j = 0; j < 3; j++) {
        float p = v0 * Wc[lane * 3 + j] + v1 * Wc[(lane + 32) * 3 + j];
#pragma unroll
        for (int o = 16; o; o >>= 1) p += __shfl_xor_sync(0xffffffffu, p, o);
        if (lane == 0) out[w * 3 + j] = p + bc[j];
    }
}

// ===========================================================================
// weight converters
// ===========================================================================
// W [K,N] fp32 -> hi/lo bf16 [N,Kp]
__global__ void conv_wT(const float* __restrict__ W,
                        __nv_bfloat16* __restrict__ Bh,
                        __nv_bfloat16* __restrict__ Bl,
                        int K, int N, int Kp) {
    int idx = blockIdx.x * blockDim.x + threadIdx.x;
    if (idx >= N * Kp) return;
    int n = idx / Kp, k = idx - n * Kp;
    float v = (k < K) ? W[(size_t)k * N + n] : 0.f;
    __nv_bfloat16 h = __float2bfloat16_rn(v);
    __nv_bfloat16 l = __float2bfloat16_rn(v - __bfloat162float(h));
    Bh[(size_t)n * Kp + k] = h;
    Bl[(size_t)n * Kp + k] = l;
}
// W [K,N] fp32 -> hi/lo fp16 [N,Kp]
__global__ void conv_wT_h(const float* __restrict__ W,
                          __half* __restrict__ Bh, __half* __restrict__ Bl,
                          int K, int N, int Kp) {
    int idx = blockIdx.x * blockDim.x + threadIdx.x;
    if (idx >= N * Kp) return;
    int n = idx / Kp, k = idx - n * Kp;
    float v = (k < K) ? W[(size_t)k * N + n] : 0.f;
    __half h = __float2half_rn(v);
    __half l = __float2half_rn(v - __half2float(h));
    Bh[(size_t)n * Kp + k] = h;
    Bl[(size_t)n * Kp + k] = l;
}

// ===========================================================================
static inline int cdiv(int a, int b) { return (a + b - 1) / b; }

extern "C" void kernel_launch(void* const* d_in, const int* in_sizes, int n_in,
                              void* d_out, int out_size) {
    const float* x    = (const float*)d_in[0];
    const float* W1   = (const float*)d_in[1];
    const float* a1s  = (const float*)d_in[2];
    const float* a1d  = (const float*)d_in[3];
    const float* b1   = (const float*)d_in[4];
    const float* W2   = (const float*)d_in[5];
    const float* a2s  = (const float*)d_in[6];
    const float* a2d  = (const float*)d_in[7];
    const float* b2   = (const float*)d_in[8];
    const float* W3   = (const float*)d_in[9];
    const float* a3s  = (const float*)d_in[10];
    const float* a3d  = (const float*)d_in[11];
    const float* b3   = (const float*)d_in[12];
    const float* Wc   = (const float*)d_in[13];
    const float* bc   = (const float*)d_in[14];
    const int*   ei   = (const int*)d_in[15];
    float* out = (float*)d_out;

    const int N = GAT_N, E = GAT_E, Mp = GAT_Mp;
    const int* src = ei;
    const int* dst = ei + E;

    float *hA, *h3, *es, *ed;
    int *rowoff, *cursor, *csrsrc;
    __nv_bfloat16 *Ahp, *Alp, *Bhp, *Blp;
    __half *W1hp, *W1lp;
    cudaGetSymbolAddress((void**)&hA,     g_hA);
    cudaGetSymbolAddress((void**)&h3,     g_h3);
    cudaGetSymbolAddress((void**)&es,     g_es);
    cudaGetSymbolAddress((void**)&ed,     g_ed);
    cudaGetSymbolAddress((void**)&rowoff, g_rowoff);
    cudaGetSymbolAddress((void**)&cursor, g_cursor);
    cudaGetSymbolAddress((void**)&csrsrc, g_csrsrc);
    cudaGetSymbolAddress((void**)&Ahp,    g_Ah);
    cudaGetSymbolAddress((void**)&Alp,    g_Al);
    cudaGetSymbolAddress((void**)&Bhp,    g_Bh);
    cudaGetSymbolAddress((void**)&Blp,    g_Bl);
    cudaGetSymbolAddress((void**)&W1hp,   g_W1h);
    cudaGetSymbolAddress((void**)&W1lp,   g_W1l);

    const int SMF   = 98304;                           // AF 32K + AH 16K + BHL 48K
    const int SM128 = 2 * (2 * 8192 + 2 * 128 * 64);
    const int SM64  = 2 * (2 * 8192 + 2 * 64 * 64);
    cudaFuncSetAttribute(gemm_fused,    cudaFuncAttributeMaxDynamicSharedMemorySize, SMF);
    cudaFuncSetAttribute(gemm_mma<128>, cudaFuncAttributeMaxDynamicSharedMemorySize, SM128);
    cudaFuncSetAttribute(gemm_mma<64>,  cudaFuncAttributeMaxDynamicSharedMemorySize, SM64);

    const int TB = 256;
    const int MT = Mp / 128;               // 235
    const int NPB = cdiv(N * 32, TB);
    const int GPB = cdiv(Mp * 32, TB);

    // ---------------- CSR build ----------------
    csr_zero<<<cdiv(N, TB), TB>>>(cursor, N);
    csr_hist<<<cdiv(E, TB), TB>>>(dst, cursor, E);
    csr_scan<<<1, 1024>>>(cursor, rowoff, N);
    csr_fill<<<cdiv(E, TB), TB>>>(src, dst, cursor, csrsrc, E);

    // ---------------- layer 1 (H=4, K=5000, fp16 2-product) ----------------
    conv_wT_h<<<cdiv(256 * GAT_K1P, TB), TB>>>(W1, W1hp, W1lp, GAT_DIN, 256, GAT_K1P);
    gemm_fused<<<dim3(2, MT), 256, SMF>>>(x, W1hp, W1lp, hA, N, GAT_DIN, GAT_K1P);
    es_ed4<<<NPB, TB>>>(hA, a1s, a1d, es, ed, N);
    agg_gather4<<<GPB, TB>>>(rowoff, csrsrc, es, ed, hA, b1, Ahp, Alp, N, Mp);

    // ---------------- layer 2 (H=4, K=256, bf16x3) ----------------
    conv_wT<<<cdiv(256 * 256, TB), TB>>>(W2, Bhp, Blp, 256, 256, 256);
    gemm_mma<128><<<dim3(2, MT), 256, SM128>>>(Ahp, Alp, Bhp, Blp, hA, N, 256, 256);
    es_ed4<<<NPB, TB>>>(hA, a2s, a2d, es, ed, N);
    agg_gather4<<<GPB, TB>>>(rowoff, csrsrc, es, ed, hA, b2, Ahp, Alp, N, Mp);

    // ---------------- layer 3 (H=1, K=256, N=64, bf16x3) ----------------
    conv_wT<<<cdiv(64 * 256, TB), TB>>>(W3, Bhp, Blp, 256, 64, 256);
    gemm_mma<64><<<dim3(1, MT), 256, SM64>>>(Ahp, Alp, Bhp, Blp, h3, N, 64, 256);
    es_ed1<<<NPB, TB>>>(h3, a3s, a3d, es, ed, N);
    agg_gather1<<<NPB, TB>>>(rowoff, csrsrc, es, ed, h3, b3, Wc, bc, out, N);
}

// round 13
// speedup vs baseline: 1.8944x; 1.1785x over previous
#include <cuda_runtime.h>
#include <cuda_bf16.h>
#include <cuda_fp16.h>
#include <cstdint>

// ---------------------------------------------------------------------------
// SentimentGAT on GB300 (sm_103 baseline PTX):
//  layer 1: single-product fp16 GEMM (A=fp16(X), B=fp16(W1)), fp32 accumulate
//  layers 2/3: bf16x3 mma.sync GEMMs (proven)
//  CSR-gather attention with fused normalize/bias/ELU/split epilogues.
// ---------------------------------------------------------------------------

#define GAT_N   30000
#define GAT_Mp  30080               // 235 * 128
#define GAT_E   480000
#define GAT_DIN 5000
#define GAT_K1P 5056                // 79 * 64 (padded K stride for W1^T)

// ---- fp32 scratch ----
__device__ float g_hA[GAT_N * 256];
__device__ float g_h3[GAT_N * 64];
__device__ float g_es[GAT_N * 4];
__device__ float g_ed[GAT_N * 4];

// ---- CSR ----
__device__ int g_rowoff[GAT_N + 1];
__device__ int g_cursor[GAT_N];
__device__ int g_csrsrc[GAT_E];

// ---- bf16 hi/lo scratch (layers 2/3) ----
__device__ __align__(128) __nv_bfloat16 g_Ah[(size_t)GAT_Mp * 256];
__device__ __align__(128) __nv_bfloat16 g_Al[(size_t)GAT_Mp * 256];
__device__ __align__(128) __nv_bfloat16 g_Bh[256 * GAT_K1P];
__device__ __align__(128) __nv_bfloat16 g_Bl[256 * GAT_K1P];
// ---- fp16 W1 (layer 1 B) ----
__device__ __align__(128) __half g_W1h[256 * GAT_K1P];

// ===========================================================================
// low-level helpers
// ===========================================================================
#define SWZ(o) ((o) ^ (((o) >> 3) & 0x70))

__device__ __forceinline__ uint32_t smem_u32(const void* p) {
    uint32_t a;
    asm("{ .reg .u64 t; cvta.to.shared.u64 t, %1; cvt.u32.u64 %0, t; }"
        : "=r"(a) : "l"(p));
    return a;
}
__device__ __forceinline__ void cp16(uint32_t d, const void* s) {
    asm volatile("cp.async.cg.shared.global [%0], [%1], 16;" :: "r"(d), "l"(s));
}
__device__ __forceinline__ void cp16z(uint32_t d, const void* s, bool pred) {
    int sz = pred ? 16 : 0;
    asm volatile("cp.async.cg.shared.global [%0], [%1], 16, %2;"
                 :: "r"(d), "l"(s), "r"(sz));
}
__device__ __forceinline__ void cp_commit() {
    asm volatile("cp.async.commit_group;" ::: "memory");
}
template <int Ng>
__device__ __forceinline__ void cp_wait() {
    asm volatile("cp.async.wait_group %0;" :: "n"(Ng) : "memory");
}
__device__ __forceinline__ void ldsm4(uint32_t (&r)[4], uint32_t addr) {
    asm volatile("ldmatrix.sync.aligned.m8n8.x4.shared.b16 {%0,%1,%2,%3}, [%4];"
                 : "=r"(r[0]), "=r"(r[1]), "=r"(r[2]), "=r"(r[3]) : "r"(addr));
}
__device__ __forceinline__ void mma16816(float (&d)[4], const uint32_t (&a)[4],
                                         uint32_t b0, uint32_t b1) {
    asm volatile("mma.sync.aligned.m16n8k16.row.col.f32.bf16.bf16.f32 "
                 "{%0,%1,%2,%3}, {%4,%5,%6,%7}, {%8,%9}, {%0,%1,%2,%3};"
                 : "+f"(d[0]), "+f"(d[1]), "+f"(d[2]), "+f"(d[3])
                 : "r"(a[0]), "r"(a[1]), "r"(a[2]), "r"(a[3]), "r"(b0), "r"(b1));
}
__device__ __forceinline__ void mma16816h(float (&d)[4], const uint32_t (&a)[4],
                                          uint32_t b0, uint32_t b1) {
    asm volatile("mma.sync.aligned.m16n8k16.row.col.f32.f16.f16.f32 "
                 "{%0,%1,%2,%3}, {%4,%5,%6,%7}, {%8,%9}, {%0,%1,%2,%3};"
                 : "+f"(d[0]), "+f"(d[1]), "+f"(d[2]), "+f"(d[3])
                 : "r"(a[0]), "r"(a[1]), "r"(a[2]), "r"(a[3]), "r"(b0), "r"(b1));
}
__device__ __forceinline__ uint32_t bfpack(float a, float b) {
    return (uint32_t)__bfloat16_as_ushort(__float2bfloat16_rn(a)) |
           ((uint32_t)__bfloat16_as_ushort(__float2bfloat16_rn(b)) << 16);
}
__device__ __forceinline__ uint32_t hpack(float a, float b) {
    return (uint32_t)__half_as_ushort(__float2half_rn(a)) |
           ((uint32_t)__half_as_ushort(__float2half_rn(b)) << 16);
}
__device__ __forceinline__ float bfhi(float x) {
    return __bfloat162float(__float2bfloat16_rn(x));
}
__device__ __forceinline__ float sel4(float4 v, int i) {
    float a = (i & 1) ? v.y : v.x;
    float b = (i & 1) ? v.w : v.z;
    return (i & 2) ? b : a;
}

// ===========================================================================
// CSR build
// ===========================================================================
__global__ void csr_zero(int* cur, int n) {
    int i = blockIdx.x * blockDim.x + threadIdx.x;
    if (i < n) cur[i] = 0;
}
__global__ void csr_hist(const int* __restrict__ dst, int* cur, int E_) {
    int i = blockIdx.x * blockDim.x + threadIdx.x;
    if (i < E_) atomicAdd(&cur[dst[i]], 1);
}
__global__ void csr_scan(int* degcur, int* rowoff, int n) {
    __shared__ int sh[1024];
    __shared__ int carry_s;
    int tid = threadIdx.x;
    if (tid == 0) carry_s = 0;
    __syncthreads();
    for (int base = 0; base < n; base += 1024) {
        int i = base + tid;
        int v = (i < n) ? degcur[i] : 0;
        sh[tid] = v;
        __syncthreads();
#pragma unroll
        for (int o = 1; o < 1024; o <<= 1) {
            int t = (tid >= o) ? sh[tid - o] : 0;
            __syncthreads();
            sh[tid] += t;
            __syncthreads();
        }
        int excl = sh[tid] - v + carry_s;
        if (i < n) { rowoff[i] = excl; degcur[i] = excl; }
        __syncthreads();
        if (tid == 1023) carry_s += sh[1023];
        __syncthreads();
    }
    if (tid == 0) rowoff[n] = carry_s;
}
__global__ void csr_fill(const int* __restrict__ src, const int* __restrict__ dst,
                         int* cur, int* csrsrc, int E_) {
    int i = blockIdx.x * blockDim.x + threadIdx.x;
    if (i < E_) {
        int p = atomicAdd(&cur[dst[i]], 1);
        csrsrc[p] = src[i];
    }
}

// ===========================================================================
// FUSED layer-1 GEMM (fp16 single product): C = fp16(X) @ fp16(W1)^T
// BK=32 single-barrier pipeline, self-consistent convert (fp32->fp16).
// smem: AF 0..32K (x2 16K) | AH 32K..48K (x2 8K) | B 48K..72K (x3 8K)
// 72 KB/CTA -> 2+ CTAs/SM.
// ===========================================================================
__global__ __launch_bounds__(256)
void gemm_fused(const float* __restrict__ X, const __half* __restrict__ Bh,
                float* __restrict__ C, int M, int K, int KpB) {
    extern __shared__ char smem[];
    const uint32_t sb = smem_u32(smem);

    const int tid = threadIdx.x;
    const int wid = tid >> 5, lane = tid & 31;
    const int wm = wid & 3, wn = wid >> 2;
    const int bm0 = blockIdx.y * 128;
    const int bn0 = blockIdx.x * 128;

    float acc[2][8][4];
#pragma unroll
    for (int i = 0; i < 2; i++)
#pragma unroll
        for (int j = 0; j < 8; j++)
#pragma unroll
            for (int k = 0; k < 4; k++) acc[i][j][k] = 0.f;

    const int NC = (K + 31) >> 5;

    auto load_tile = [&](int c) {   // A -> AF[c%2], B -> B[c%3]
        const uint32_t af = sb + (c & 1) * 16384;
        const uint32_t bb = sb + 49152 + (c % 3) * 8192;
        const int k0 = c * 32;
#pragma unroll
        for (int t = 0; t < 4; t++) {
            int i = tid + t * 256;
            int row = i >> 3, q = i & 7;
            int gm = bm0 + row, gk = k0 + q * 4;
            bool p = (gm < M) && (gk < K);
            cp16z(af + row * 128 + q * 16, X + (p ? ((size_t)gm * K + gk) : 0), p);
        }
#pragma unroll
        for (int t = 0; t < 2; t++) {
            int i = tid + t * 256;
            int row = i >> 2, ch = i & 3;
            const __half* src = Bh + (size_t)(bn0 + row) * KpB + k0 + ch * 8;
            cp16(bb + SWZ(row * 64 + ch * 16), src);
        }
    };

    auto convert = [&](int c) {     // AF[c%2] -> AH[c%2] (fp16), own data
        const int s2 = c & 1;
        const char* afp = smem + s2 * 16384;
        char* ahp = smem + 32768 + s2 * 8192;
#pragma unroll
        for (int t = 0; t < 4; t++) {
            int i = tid + t * 256;
            int row = i >> 3, q = i & 7;
            float4 v = *(const float4*)(afp + row * 128 + q * 16);
            uint32_t h0 = hpack(v.x, v.y);
            uint32_t h1 = hpack(v.z, v.w);
            uint32_t off = SWZ(row * 64 + (q & 6) * 8) + (q & 1) * 8;
            *(uint2*)(ahp + off) = make_uint2(h0, h1);
        }
    };

    const int a_row = wm * 32 + (lane & 15);
    const int a_chb = lane >> 4;
    const int b_row = wn * 64 + ((lane >> 4) & 1) * 8 + (lane & 7);
    const int b_chb = (lane >> 3) & 1;

    // prologue
    load_tile(0); cp_commit();
    if (NC > 1) { load_tile(1); cp_commit(); }
    cp_wait<1>();
    convert(0);

    for (int c = 0; c < NC; c++) {
        __syncthreads();     // publish convert(c) to all warps

        const uint32_t aH = sb + 32768 + (c & 1) * 8192;
        const uint32_t bB = sb + 49152 + (c % 3) * 8192;
#pragma unroll
        for (int ks = 0; ks < 2; ks++) {
            uint32_t ah[2][4];
#pragma unroll
            for (int mf = 0; mf < 2; mf++) {
                uint32_t off = SWZ((a_row + mf * 16) * 64 + (ks * 2 + a_chb) * 16);
                ldsm4(ah[mf], aH + off);
            }
            uint32_t bh[4][4];
#pragma unroll
            for (int p = 0; p < 4; p++) {
                uint32_t off = SWZ((b_row + p * 16) * 64 + (ks * 2 + b_chb) * 16);
                ldsm4(bh[p], bB + off);
            }
#pragma unroll
            for (int mf = 0; mf < 2; mf++)
#pragma unroll
                for (int p = 0; p < 4; p++) {
                    mma16816h(acc[mf][2 * p],     ah[mf], bh[p][0], bh[p][1]);
                    mma16816h(acc[mf][2 * p + 1], ah[mf], bh[p][2], bh[p][3]);
                }
        }

        if (c + 1 < NC) {
            cp_wait<0>();
            convert(c + 1);
        }
        if (c + 2 < NC) {
            load_tile(c + 2);
            cp_commit();
        }
    }

#pragma unroll
    for (int mf = 0; mf < 2; mf++) {
        int r0 = bm0 + wm * 32 + mf * 16 + (lane >> 2);
#pragma unroll
        for (int nf = 0; nf < 8; nf++) {
            int col = bn0 + wn * 64 + nf * 8 + (lane & 3) * 2;
            if (r0 < M)
                *(float2*)(C + (size_t)r0 * 256 + col) =
                    make_float2(acc[mf][nf][0], acc[mf][nf][1]);
            if (r0 + 8 < M)
                *(float2*)(C + (size_t)(r0 + 8) * 256 + col) =
                    make_float2(acc[mf][nf][2], acc[mf][nf][3]);
        }
    }
}

// ===========================================================================
// pre-split bf16x3 GEMM for layers 2/3 (proven)
// ===========================================================================
template <int BN>
__global__ __launch_bounds__(256)
void gemm_mma(const __nv_bfloat16* __restrict__ Ah, const __nv_bfloat16* __restrict__ Al,
              const __nv_bfloat16* __restrict__ Bh, const __nv_bfloat16* __restrict__ Bl,
              float* __restrict__ C, int M, int N, int Kp) {
    constexpr int WNCOL = BN / 2;
    constexpr int NFRAG = WNCOL / 8;
    constexpr int NPAIR = NFRAG / 2;
    constexpr int ABH = 8192;
    constexpr int BBH = BN * 64;
    constexpr int STAGE = 2 * ABH + 2 * BBH;

    extern __shared__ char smem[];
    const uint32_t sb = smem_u32(smem);

    const int tid = threadIdx.x;
    const int wid = tid >> 5, lane = tid & 31;
    const int wm = wid & 3, wn = wid >> 2;
    const int bm0 = blockIdx.y * 128;
    const int bn0 = blockIdx.x * BN;

    float acc[2][NFRAG][4];
#pragma unroll
    for (int i = 0; i < 2; i++)
#pragma unroll
        for (int j = 0; j < NFRAG; j++)
#pragma unroll
            for (int k = 0; k < 4; k++) acc[i][j][k] = 0.f;

    const int NC = Kp >> 5;

    auto load_stage = [&](int c, int stg) {
        const uint32_t base = sb + stg * STAGE;
        const size_t koff = (size_t)c * 32;
#pragma unroll
        for (int t = 0; t < 4; t++) {
            int i = tid + t * 256;
            int half = i >> 9;
            int rem = i & 511;
            int row = rem >> 2, ch = rem & 3;
            const __nv_bfloat16* src =
                (half ? Al : Ah) + (size_t)(bm0 + row) * Kp + koff + ch * 8;
            cp16(base + half * ABH + SWZ(row * 64 + ch * 16), src);
        }
#pragma unroll
        for (int t = 0; t < BN / 32; t++) {
            int i = tid + t * 256;
            int half = i / (BN * 4);
            int rem = i % (BN * 4);
            int row = rem >> 2, ch = rem & 3;
            const __nv_bfloat16* src =
                (half ? Bl : Bh) + (size_t)(bn0 + row) * Kp + koff + ch * 8;
            cp16(base + 2 * ABH + half * BBH + SWZ(row * 64 + ch * 16), src);
        }
    };

    const int a_row = wm * 32 + (lane & 15);
    const int a_chb = lane >> 4;
    const int b_row = wn * WNCOL + ((lane >> 4) & 1) * 8 + (lane & 7);
    const int b_chb = (lane >> 3) & 1;

    load_stage(0, 0);
    cp_commit();

    for (int c = 0; c < NC; c++) {
        if (c + 1 < NC) {
            load_stage(c + 1, (c + 1) & 1);
            cp_commit();
            cp_wait<1>();
        } else {
            cp_wait<0>();
        }
        __syncthreads();

        const uint32_t base = sb + (c & 1) * STAGE;
        const uint32_t aH = base, aL = base + ABH;
        const uint32_t bH = base + 2 * ABH, bL = bH + BBH;

#pragma unroll
        for (int ks = 0; ks < 2; ks++) {
            uint32_t ah[2][4], al[2][4];
#pragma unroll
            for (int mf = 0; mf < 2; mf++) {
                uint32_t off = SWZ((a_row + mf * 16) * 64 + (ks * 2 + a_chb) * 16);
                ldsm4(ah[mf], aH + off);
                ldsm4(al[mf], aL + off);
            }
            uint32_t bh[NPAIR][4], bl[NPAIR][4];
#pragma unroll
            for (int p = 0; p < NPAIR; p++) {
                uint32_t off = SWZ((b_row + p * 16) * 64 + (ks * 2 + b_chb) * 16);
                ldsm4(bh[p], bH + off);
                ldsm4(bl[p], bL + off);
            }
#pragma unroll
            for (int mf = 0; mf < 2; mf++)
#pragma unroll
                for (int p = 0; p < NPAIR; p++) {
                    mma16816(acc[mf][2 * p],     ah[mf], bh[p][0], bh[p][1]);
                    mma16816(acc[mf][2 * p + 1], ah[mf], bh[p][2], bh[p][3]);
                }
#pragma unroll
            for (int mf = 0; mf < 2; mf++)
#pragma unroll
                for (int p = 0; p < NPAIR; p++) {
                    mma16816(acc[mf][2 * p],     ah[mf], bl[p][0], bl[p][1]);
                    mma16816(acc[mf][2 * p + 1], ah[mf], bl[p][2], bl[p][3]);
                }
#pragma unroll
            for (int mf = 0; mf < 2; mf++)
#pragma unroll
                for (int p = 0; p < NPAIR; p++) {
                    mma16816(acc[mf][2 * p],     al[mf], bh[p][0], bh[p][1]);
                    mma16816(acc[mf][2 * p + 1], al[mf], bh[p][2], bh[p][3]);
                }
        }
        __syncthreads();
    }

#pragma unroll
    for (int mf = 0; mf < 2; mf++) {
        int r0 = bm0 + wm * 32 + mf * 16 + (lane >> 2);
#pragma unroll
        for (int nf = 0; nf < NFRAG; nf++) {
            int col = bn0 + wn * WNCOL + nf * 8 + (lane & 3) * 2;
            if (r0 < M)
                *(float2*)(C + (size_t)r0 * N + col) =
                    make_float2(acc[mf][nf][0], acc[mf][nf][1]);
            if (r0 + 8 < M)
                *(float2*)(C + (size_t)(r0 + 8) * N + col) =
                    make_float2(acc[mf][nf][2], acc[mf][nf][3]);
        }
    }
}

// ===========================================================================
// es/ed logits (one warp per node)
// ===========================================================================
__global__ void es_ed4(const float* __restrict__ h,
                       const float* __restrict__ a_src,
                       const float* __restrict__ a_dst,
                       float* __restrict__ es, float* __restrict__ ed, int n) {
    int w = (blockIdx.x * blockDim.x + threadIdx.x) >> 5;
    int lane = threadIdx.x & 31;
    if (w >= n) return;
    int c = lane * 8;
    const float* hp = h + (size_t)w * 256 + c;
    float4 v0 = *(const float4*)(hp);
    float4 v1 = *(const float4*)(hp + 4);
    float4 as0 = *(const float4*)(a_src + c);
    float4 as1 = *(const float4*)(a_src + c + 4);
    float4 ad0 = *(const float4*)(a_dst + c);
    float4 ad1 = *(const float4*)(a_dst + c + 4);
    float s = v0.x * as0.x + v0.y * as0.y + v0.z * as0.z + v0.w * as0.w +
              v1.x * as1.x + v1.y * as1.y + v1.z * as1.z + v1.w * as1.w;
    float d = v0.x * ad0.x + v0.y * ad0.y + v0.z * ad0.z + v0.w * ad0.w +
              v1.x * ad1.x + v1.y * ad1.y + v1.z * ad1.z + v1.w * ad1.w;
#pragma unroll
    for (int o = 4; o; o >>= 1) {
        s += __shfl_xor_sync(0xffffffffu, s, o);
        d += __shfl_xor_sync(0xffffffffu, d, o);
    }
    if ((lane & 7) == 0) {
        int head = lane >> 3;
        es[w * 4 + head] = s;
        ed[w * 4 + head] = d;
    }
}

__global__ void es_ed1(const float* __restrict__ h,
                       const float* __restrict__ a_src,
                       const float* __restrict__ a_dst,
                       float* __restrict__ es, float* __restrict__ ed, int n) {
    int w = (blockIdx.x * blockDim.x + threadIdx.x) >> 5;
    int lane = threadIdx.x & 31;
    if (w >= n) return;
    int c = lane * 2;
    float2 v = *(const float2*)(h + (size_t)w * 64 + c);
    float2 as = *(const float2*)(a_src + c);
    float2 ad = *(const float2*)(a_dst + c);
    float s = v.x * as.x + v.y * as.y;
    float d = v.x * ad.x + v.y * ad.y;
#pragma unroll
    for (int o = 16; o; o >>= 1) {
        s += __shfl_xor_sync(0xffffffffu, s, o);
        d += __shfl_xor_sync(0xffffffffu, d, o);
    }
    if (lane == 0) { es[w] = s; ed[w] = d; }
}

// ===========================================================================
// agg_gather4 (proven R7)
// ===========================================================================
__global__ void agg_gather4(const int* __restrict__ rowoff, const int* __restrict__ csrsrc,
                            const float* __restrict__ es, const float* __restrict__ ed,
                            const float* __restrict__ h, const float* __restrict__ b,
                            __nv_bfloat16* __restrict__ Hh, __nv_bfloat16* __restrict__ Hl,
                            int n, int Mp) {
    int w = (blockIdx.x * blockDim.x + threadIdx.x) >> 5;
    int lane = threadIdx.x & 31;
    if (w >= Mp) return;
    const int c0 = lane * 4;
    if (w >= n) {
        *(uint2*)(Hh + (size_t)w * 256 + c0) = make_uint2(0, 0);
        *(uint2*)(Hh + (size_t)w * 256 + c0 + 128) = make_uint2(0, 0);
        *(uint2*)(Hl + (size_t)w * 256 + c0) = make_uint2(0, 0);
        *(uint2*)(Hl + (size_t)w * 256 + c0 + 128) = make_uint2(0, 0);
        return;
    }
    const int myh = lane & 3;
    const int hs = (lane >> 4) & 1;
    float4 ed4 = *(const float4*)(ed + w * 4);
    float edh = sel4(ed4, myh);

    float4 es4 = *(const float4*)(es + w * 4);
    float e = sel4(es4, myh) + edh;
    e = e > 0.f ? e : 0.2f * e;
    float wv = __expf(e);
    float den = wv;
    float al0 = __shfl_sync(0xffffffffu, wv, hs);
    float al1 = __shfl_sync(0xffffffffu, wv, 2 + hs);

    const float* hp = h + (size_t)w * 256;
    float4 a0 = *(const float4*)(hp + c0);
    float4 a1 = *(const float4*)(hp + c0 + 128);
    a0.x *= al0; a0.y *= al0; a0.z *= al0; a0.w *= al0;
    a1.x *= al1; a1.y *= al1; a1.z *= al1; a1.w *= al1;

    int j0 = rowoff[w], j1 = rowoff[w + 1];
    int s = (j0 < j1) ? csrsrc[j0] : 0;
    for (int j = j0; j < j1; j++) {
        int snext = (j + 1 < j1) ? csrsrc[j + 1] : 0;
        float4 e4 = *(const float4*)(es + s * 4);
        float ee = sel4(e4, myh) + edh;
        ee = ee > 0.f ? ee : 0.2f * ee;
        float wj = __expf(ee);
        den += wj;
        float b0 = __shfl_sync(0xffffffffu, wj, hs);
        float b1 = __shfl_sync(0xffffffffu, wj, 2 + hs);
        const float* sp = h + (size_t)s * 256;
        float4 v0 = *(const float4*)(sp + c0);
        float4 v1 = *(const float4*)(sp + c0 + 128);
        a0.x += b0 * v0.x; a0.y += b0 * v0.y; a0.z += b0 * v0.z; a0.w += b0 * v0.w;
        a1.x += b1 * v1.x; a1.y += b1 * v1.y; a1.z += b1 * v1.z; a1.w += b1 * v1.w;
        s = snext;
    }
    float inv0 = __fdividef(1.f, __shfl_sync(0xffffffffu, den, hs));
    float inv1 = __fdividef(1.f, __shfl_sync(0xffffffffu, den, 2 + hs));

    float4 bb0 = *(const float4*)(b + c0);
    float4 bb1 = *(const float4*)(b + c0 + 128);
    float f0[4] = {a0.x * inv0 + bb0.x, a0.y * inv0 + bb0.y,
                   a0.z * inv0 + bb0.z, a0.w * inv0 + bb0.w};
    float f1[4] = {a1.x * inv1 + bb1.x, a1.y * inv1 + bb1.y,
                   a1.z * inv1 + bb1.z, a1.w * inv1 + bb1.w};
#pragma unroll
    for (int k = 0; k < 4; k++) {
        f0[k] = f0[k] > 0.f ? f0[k] : expm1f(f0[k]);
        f1[k] = f1[k] > 0.f ? f1[k] : expm1f(f1[k]);
    }
    uint32_t h0a = bfpack(f0[0], f0[1]), h0b = bfpack(f0[2], f0[3]);
    uint32_t h1a = bfpack(f1[0], f1[1]), h1b = bfpack(f1[2], f1[3]);
    float r0[4], r1[4];
#pragma unroll
    for (int k = 0; k < 4; k++) {
        r0[k] = f0[k] - bfhi(f0[k]);
        r1[k] = f1[k] - bfhi(f1[k]);
    }
    size_t o = (size_t)w * 256 + c0;
    *(uint2*)(Hh + o)       = make_uint2(h0a, h0b);
    *(uint2*)(Hh + o + 128) = make_uint2(h1a, h1b);
    *(uint2*)(Hl + o)       = make_uint2(bfpack(r0[0], r0[1]), bfpack(r0[2], r0[3]));
    *(uint2*)(Hl + o + 128) = make_uint2(bfpack(r1[0], r1[1]), bfpack(r1[2], r1[3]));
}

// ===========================================================================
// agg_gather1 + classifier (proven R7)
// ===========================================================================
__global__ void agg_gather1(const int* __restrict__ rowoff, const int* __restrict__ csrsrc,
                            const float* __restrict__ es, const float* __restrict__ ed,
                            const float* __restrict__ h, const float* __restrict__ b3,
                            const float* __restrict__ Wc, const float* __restrict__ bc,
                            float* __restrict__ out, int n) {
    int w = (blockIdx.x * blockDim.x + threadIdx.x) >> 5;
    int lane = threadIdx.x & 31;
    if (w >= n) return;
    float edw = ed[w];
    float e = es[w] + edw;
    e = e > 0.f ? e : 0.2f * e;
    float wv = __expf(e);
    float den = wv;
    float v0 = h[(size_t)w * 64 + lane] * wv;
    float v1 = h[(size_t)w * 64 + lane + 32] * wv;

    int j0 = rowoff[w], j1 = rowoff[w + 1];
    int s = (j0 < j1) ? csrsrc[j0] : 0;
    for (int j = j0; j < j1; j++) {
        int snext = (j + 1 < j1) ? csrsrc[j + 1] : 0;
        float ee = es[s] + edw;
        ee = ee > 0.f ? ee : 0.2f * ee;
        float wj = __expf(ee);
        den += wj;
        v0 += wj * h[(size_t)s * 64 + lane];
        v1 += wj * h[(size_t)s * 64 + lane + 32];
        s = snext;
    }
    float inv = __fdividef(1.f, den);
    v0 = v0 * inv + b3[lane];
    v0 = v0 > 0.f ? v0 : expm1f(v0);
    v1 = v1 * inv + b3[lane + 32];
    v1 = v1 > 0.f ? v1 : expm1f(v1);
#pragma unroll
    for (int j = 0; j < 3; j++) {
        float p = v0 * Wc[lane * 3 + j] + v1 * Wc[(lane + 32) * 3 + j];
#pragma unroll
        for (int o = 16; o; o >>= 1) p += __shfl_xor_sync(0xffffffffu, p, o);
        if (lane == 0) out[w * 3 + j] = p + bc[j];
    }
}

// ===========================================================================
// weight converters
// ===========================================================================
__global__ void conv_wT(const float* __restrict__ W,
                        __nv_bfloat16* __restrict__ Bh,
                        __nv_bfloat16* __restrict__ Bl,
                        int K, int N, int Kp) {
    int idx = blockIdx.x * blockDim.x + threadIdx.x;
    if (idx >= N * Kp) return;
    int n = idx / Kp, k = idx - n * Kp;
    float v = (k < K) ? W[(size_t)k * N + n] : 0.f;
    __nv_bfloat16 h = __float2bfloat16_rn(v);
    __nv_bfloat16 l = __float2bfloat16_rn(v - __bfloat162float(h));
    Bh[(size_t)n * Kp + k] = h;
    Bl[(size_t)n * Kp + k] = l;
}
// W [K,N] fp32 -> fp16 [N,Kp] (single precision level)
__global__ void conv_wT_h(const float* __restrict__ W,
                          __half* __restrict__ Bh, int K, int N, int Kp) {
    int idx = blockIdx.x * blockDim.x + threadIdx.x;
    if (idx >= N * Kp) return;
    int n = idx / Kp, k = idx - n * Kp;
    float v = (k < K) ? W[(size_t)k * N + n] : 0.f;
    Bh[(size_t)n * Kp + k] = __float2half_rn(v);
}

// ===========================================================================
static inline int cdiv(int a, int b) { return (a + b - 1) / b; }

extern "C" void kernel_launch(void* const* d_in, const int* in_sizes, int n_in,
                              void* d_out, int out_size) {
    const float* x    = (const float*)d_in[0];
    const float* W1   = (const float*)d_in[1];
    const float* a1s  = (const float*)d_in[2];
    const float* a1d  = (const float*)d_in[3];
    const float* b1   = (const float*)d_in[4];
    const float* W2   = (const float*)d_in[5];
    const float* a2s  = (const float*)d_in[6];
    const float* a2d  = (const float*)d_in[7];
    const float* b2   = (const float*)d_in[8];
    const float* W3   = (const float*)d_in[9];
    const float* a3s  = (const float*)d_in[10];
    const float* a3d  = (const float*)d_in[11];
    const float* b3   = (const float*)d_in[12];
    const float* Wc   = (const float*)d_in[13];
    const float* bc   = (const float*)d_in[14];
    const int*   ei   = (const int*)d_in[15];
    float* out = (float*)d_out;

    const int N = GAT_N, E = GAT_E, Mp = GAT_Mp;
    const int* src = ei;
    const int* dst = ei + E;

    float *hA, *h3, *es, *ed;
    int *rowoff, *cursor, *csrsrc;
    __nv_bfloat16 *Ahp, *Alp, *Bhp, *Blp;
    __half *W1hp;
    cudaGetSymbolAddress((void**)&hA,     g_hA);
    cudaGetSymbolAddress((void**)&h3,     g_h3);
    cudaGetSymbolAddress((void**)&es,     g_es);
    cudaGetSymbolAddress((void**)&ed,     g_ed);
    cudaGetSymbolAddress((void**)&rowoff, g_rowoff);
    cudaGetSymbolAddress((void**)&cursor, g_cursor);
    cudaGetSymbolAddress((void**)&csrsrc, g_csrsrc);
    cudaGetSymbolAddress((void**)&Ahp,    g_Ah);
    cudaGetSymbolAddress((void**)&Alp,    g_Al);
    cudaGetSymbolAddress((void**)&Bhp,    g_Bh);
    cudaGetSymbolAddress((void**)&Blp,    g_Bl);
    cudaGetSymbolAddress((void**)&W1hp,   g_W1h);

    const int SMF   = 73728;                           // AF 32K + AH 16K + B 24K
    const int SM128 = 2 * (2 * 8192 + 2 * 128 * 64);
    const int SM64  = 2 * (2 * 8192 + 2 * 64 * 64);
    cudaFuncSetAttribute(gemm_fused,    cudaFuncAttributeMaxDynamicSharedMemorySize, SMF);
    cudaFuncSetAttribute(gemm_mma<128>, cudaFuncAttributeMaxDynamicSharedMemorySize, SM128);
    cudaFuncSetAttribute(gemm_mma<64>,  cudaFuncAttributeMaxDynamicSharedMemorySize, SM64);

    const int TB = 256;
    const int MT = Mp / 128;               // 235
    const int NPB = cdiv(N * 32, TB);
    const int GPB = cdiv(Mp * 32, TB);

    // ---------------- CSR build ----------------
    csr_zero<<<cdiv(N, TB), TB>>>(cursor, N);
    csr_hist<<<cdiv(E, TB), TB>>>(dst, cursor, E);
    csr_scan<<<1, 1024>>>(cursor, rowoff, N);
    csr_fill<<<cdiv(E, TB), TB>>>(src, dst, cursor, csrsrc, E);

    // ---------------- layer 1 (H=4, K=5000, fp16 single product) ----------------
    conv_wT_h<<<cdiv(256 * GAT_K1P, TB), TB>>>(W1, W1hp, GAT_DIN, 256, GAT_K1P);
    gemm_fused<<<dim3(2, MT), 256, SMF>>>(x, W1hp, hA, N, GAT_DIN, GAT_K1P);
    es_ed4<<<NPB, TB>>>(hA, a1s, a1d, es, ed, N);
    agg_gather4<<<GPB, TB>>>(rowoff, csrsrc, es, ed, hA, b1, Ahp, Alp, N, Mp);

    // ---------------- layer 2 (H=4, K=256, bf16x3) ----------------
    conv_wT<<<cdiv(256 * 256, TB), TB>>>(W2, Bhp, Blp, 256, 256, 256);
    gemm_mma<128><<<dim3(2, MT), 256, SM128>>>(Ahp, Alp, Bhp, Blp, hA, N, 256, 256);
    es_ed4<<<NPB, TB>>>(hA, a2s, a2d, es, ed, N);
    agg_gather4<<<GPB, TB>>>(rowoff, csrsrc, es, ed, hA, b2, Ahp, Alp, N, Mp);

    // ---------------- layer 3 (H=1, K=256, N=64, bf16x3) ----------------
    conv_wT<<<cdiv(64 * 256, TB), TB>>>(W3, Bhp, Blp, 256, 64, 256);
    gemm_mma<64><<<dim3(1, MT), 256, SM64>>>(Ahp, Alp, Bhp, Blp, h3, N, 64, 256);
    es_ed1<<<NPB, TB>>>(h3, a3s, a3d, es, ed, N);
    agg_gather1<<<NPB, TB>>>(rowoff, csrsrc, es, ed, h3, b3, Wc, bc, out, N);
}

// round 14
// speedup vs baseline: 2.0209x; 1.0668x over previous
#include <cuda_runtime.h>
#include <cuda_bf16.h>
#include <cuda_fp16.h>
#include <cstdint>

// ---------------------------------------------------------------------------
// SentimentGAT on GB300 (sm_103 baseline PTX):
//  all 3 layers: single-product fp16 mma.sync GEMMs, fp32 accumulate
//  CSR-gather attention with fused normalize/bias/ELU/fp16-convert epilogues.
// ---------------------------------------------------------------------------

#define GAT_N   30000
#define GAT_Mp  30080               // 235 * 128
#define GAT_E   480000
#define GAT_DIN 5000
#define GAT_K1P 5056                // 79 * 64 (padded K stride for W1^T)

// ---- fp32 scratch ----
__device__ float g_hA[GAT_N * 256];
__device__ float g_h3[GAT_N * 64];
__device__ float g_es[GAT_N * 4];
__device__ float g_ed[GAT_N * 4];

// ---- CSR ----
__device__ int g_rowoff[GAT_N + 1];
__device__ int g_cursor[GAT_N];
__device__ int g_csrsrc[GAT_E];

// ---- fp16 operands ----
__device__ __align__(128) __half g_Af[(size_t)GAT_Mp * 256];   // A for layers 2/3
__device__ __align__(128) __half g_W1h[256 * GAT_K1P];
__device__ __align__(128) __half g_W2h[256 * 256];
__device__ __align__(128) __half g_W3h[64 * 256];

// ===========================================================================
// low-level helpers
// ===========================================================================
#define SWZ(o) ((o) ^ (((o) >> 3) & 0x70))

__device__ __forceinline__ uint32_t smem_u32(const void* p) {
    uint32_t a;
    asm("{ .reg .u64 t; cvta.to.shared.u64 t, %1; cvt.u32.u64 %0, t; }"
        : "=r"(a) : "l"(p));
    return a;
}
__device__ __forceinline__ void cp16(uint32_t d, const void* s) {
    asm volatile("cp.async.cg.shared.global [%0], [%1], 16;" :: "r"(d), "l"(s));
}
__device__ __forceinline__ void cp16z(uint32_t d, const void* s, bool pred) {
    int sz = pred ? 16 : 0;
    asm volatile("cp.async.cg.shared.global [%0], [%1], 16, %2;"
                 :: "r"(d), "l"(s), "r"(sz));
}
__device__ __forceinline__ void cp_commit() {
    asm volatile("cp.async.commit_group;" ::: "memory");
}
template <int Ng>
__device__ __forceinline__ void cp_wait() {
    asm volatile("cp.async.wait_group %0;" :: "n"(Ng) : "memory");
}
__device__ __forceinline__ void ldsm4(uint32_t (&r)[4], uint32_t addr) {
    asm volatile("ldmatrix.sync.aligned.m8n8.x4.shared.b16 {%0,%1,%2,%3}, [%4];"
                 : "=r"(r[0]), "=r"(r[1]), "=r"(r[2]), "=r"(r[3]) : "r"(addr));
}
__device__ __forceinline__ void mma16816h(float (&d)[4], const uint32_t (&a)[4],
                                          uint32_t b0, uint32_t b1) {
    asm volatile("mma.sync.aligned.m16n8k16.row.col.f32.f16.f16.f32 "
                 "{%0,%1,%2,%3}, {%4,%5,%6,%7}, {%8,%9}, {%0,%1,%2,%3};"
                 : "+f"(d[0]), "+f"(d[1]), "+f"(d[2]), "+f"(d[3])
                 : "r"(a[0]), "r"(a[1]), "r"(a[2]), "r"(a[3]), "r"(b0), "r"(b1));
}
__device__ __forceinline__ uint32_t hpack(float a, float b) {
    return (uint32_t)__half_as_ushort(__float2half_rn(a)) |
           ((uint32_t)__half_as_ushort(__float2half_rn(b)) << 16);
}
__device__ __forceinline__ float sel4(float4 v, int i) {
    float a = (i & 1) ? v.y : v.x;
    float b = (i & 1) ? v.w : v.z;
    return (i & 2) ? b : a;
}

// ===========================================================================
// CSR build
// ===========================================================================
__global__ void csr_zero(int* cur, int n) {
    int i = blockIdx.x * blockDim.x + threadIdx.x;
    if (i < n) cur[i] = 0;
}
__global__ void csr_hist(const int* __restrict__ dst, int* cur, int E_) {
    int i = blockIdx.x * blockDim.x + threadIdx.x;
    if (i < E_) atomicAdd(&cur[dst[i]], 1);
}
__global__ void csr_scan(int* degcur, int* rowoff, int n) {
    __shared__ int sh[1024];
    __shared__ int carry_s;
    int tid = threadIdx.x;
    if (tid == 0) carry_s = 0;
    __syncthreads();
    for (int base = 0; base < n; base += 1024) {
        int i = base + tid;
        int v = (i < n) ? degcur[i] : 0;
        sh[tid] = v;
        __syncthreads();
#pragma unroll
        for (int o = 1; o < 1024; o <<= 1) {
            int t = (tid >= o) ? sh[tid - o] : 0;
            __syncthreads();
            sh[tid] += t;
            __syncthreads();
        }
        int excl = sh[tid] - v + carry_s;
        if (i < n) { rowoff[i] = excl; degcur[i] = excl; }
        __syncthreads();
        if (tid == 1023) carry_s += sh[1023];
        __syncthreads();
    }
    if (tid == 0) rowoff[n] = carry_s;
}
__global__ void csr_fill(const int* __restrict__ src, const int* __restrict__ dst,
                         int* cur, int* csrsrc, int E_) {
    int i = blockIdx.x * blockDim.x + threadIdx.x;
    if (i < E_) {
        int p = atomicAdd(&cur[dst[i]], 1);
        csrsrc[p] = src[i];
    }
}

// ===========================================================================
// FUSED layer-1 GEMM (fp16 single product): C = fp16(X) @ fp16(W1)^T
// BK=32 single-barrier pipeline, self-consistent convert (R13-proven).
// smem: AF 0..32K (x2 16K) | AH 32K..48K (x2 8K) | B 48K..72K (x3 8K)
// ===========================================================================
__global__ __launch_bounds__(256)
void gemm_fused(const float* __restrict__ X, const __half* __restrict__ Bh,
                float* __restrict__ C, int M, int K, int KpB) {
    extern __shared__ char smem[];
    const uint32_t sb = smem_u32(smem);

    const int tid = threadIdx.x;
    const int wid = tid >> 5, lane = tid & 31;
    const int wm = wid & 3, wn = wid >> 2;
    const int bm0 = blockIdx.y * 128;
    const int bn0 = blockIdx.x * 128;

    float acc[2][8][4];
#pragma unroll
    for (int i = 0; i < 2; i++)
#pragma unroll
        for (int j = 0; j < 8; j++)
#pragma unroll
            for (int k = 0; k < 4; k++) acc[i][j][k] = 0.f;

    const int NC = (K + 31) >> 5;

    auto load_tile = [&](int c) {
        const uint32_t af = sb + (c & 1) * 16384;
        const uint32_t bb = sb + 49152 + (c % 3) * 8192;
        const int k0 = c * 32;
#pragma unroll
        for (int t = 0; t < 4; t++) {
            int i = tid + t * 256;
            int row = i >> 3, q = i & 7;
            int gm = bm0 + row, gk = k0 + q * 4;
            bool p = (gm < M) && (gk < K);
            cp16z(af + row * 128 + q * 16, X + (p ? ((size_t)gm * K + gk) : 0), p);
        }
#pragma unroll
        for (int t = 0; t < 2; t++) {
            int i = tid + t * 256;
            int row = i >> 2, ch = i & 3;
            const __half* src = Bh + (size_t)(bn0 + row) * KpB + k0 + ch * 8;
            cp16(bb + SWZ(row * 64 + ch * 16), src);
        }
    };

    auto convert = [&](int c) {
        const int s2 = c & 1;
        const char* afp = smem + s2 * 16384;
        char* ahp = smem + 32768 + s2 * 8192;
#pragma unroll
        for (int t = 0; t < 4; t++) {
            int i = tid + t * 256;
            int row = i >> 3, q = i & 7;
            float4 v = *(const float4*)(afp + row * 128 + q * 16);
            uint32_t h0 = hpack(v.x, v.y);
            uint32_t h1 = hpack(v.z, v.w);
            uint32_t off = SWZ(row * 64 + (q & 6) * 8) + (q & 1) * 8;
            *(uint2*)(ahp + off) = make_uint2(h0, h1);
        }
    };

    const int a_row = wm * 32 + (lane & 15);
    const int a_chb = lane >> 4;
    const int b_row = wn * 64 + ((lane >> 4) & 1) * 8 + (lane & 7);
    const int b_chb = (lane >> 3) & 1;

    load_tile(0); cp_commit();
    if (NC > 1) { load_tile(1); cp_commit(); }
    cp_wait<1>();
    convert(0);

    for (int c = 0; c < NC; c++) {
        __syncthreads();

        const uint32_t aH = sb + 32768 + (c & 1) * 8192;
        const uint32_t bB = sb + 49152 + (c % 3) * 8192;
#pragma unroll
        for (int ks = 0; ks < 2; ks++) {
            uint32_t ah[2][4];
#pragma unroll
            for (int mf = 0; mf < 2; mf++) {
                uint32_t off = SWZ((a_row + mf * 16) * 64 + (ks * 2 + a_chb) * 16);
                ldsm4(ah[mf], aH + off);
            }
            uint32_t bh[4][4];
#pragma unroll
            for (int p = 0; p < 4; p++) {
                uint32_t off = SWZ((b_row + p * 16) * 64 + (ks * 2 + b_chb) * 16);
                ldsm4(bh[p], bB + off);
            }
#pragma unroll
            for (int mf = 0; mf < 2; mf++)
#pragma unroll
                for (int p = 0; p < 4; p++) {
                    mma16816h(acc[mf][2 * p],     ah[mf], bh[p][0], bh[p][1]);
                    mma16816h(acc[mf][2 * p + 1], ah[mf], bh[p][2], bh[p][3]);
                }
        }

        if (c + 1 < NC) {
            cp_wait<0>();
            convert(c + 1);
        }
        if (c + 2 < NC) {
            load_tile(c + 2);
            cp_commit();
        }
    }

#pragma unroll
    for (int mf = 0; mf < 2; mf++) {
        int r0 = bm0 + wm * 32 + mf * 16 + (lane >> 2);
#pragma unroll
        for (int nf = 0; nf < 8; nf++) {
            int col = bn0 + wn * 64 + nf * 8 + (lane & 3) * 2;
            if (r0 < M)
                *(float2*)(C + (size_t)r0 * 256 + col) =
                    make_float2(acc[mf][nf][0], acc[mf][nf][1]);
            if (r0 + 8 < M)
                *(float2*)(C + (size_t)(r0 + 8) * 256 + col) =
                    make_float2(acc[mf][nf][2], acc[mf][nf][3]);
        }
    }
}

// ===========================================================================
// fp16 single-product GEMM for layers 2/3: C[M,N] = A @ B^T
// A: [Mp,Kp] fp16 row-major; B: [N,Kp] fp16 row-major. BK=32, 2-stage.
// ===========================================================================
template <int BN>
__global__ __launch_bounds__(256)
void gemm_h(const __half* __restrict__ A, const __half* __restrict__ B,
            float* __restrict__ C, int M, int N, int Kp) {
    constexpr int WNCOL = BN / 2;
    constexpr int NFRAG = WNCOL / 8;
    constexpr int NPAIR = NFRAG / 2;
    constexpr int ABYTES = 8192;          // 128 rows x 64B
    constexpr int BBYTES = BN * 64;
    constexpr int STAGE = ABYTES + BBYTES;

    extern __shared__ char smem[];
    const uint32_t sb = smem_u32(smem);

    const int tid = threadIdx.x;
    const int wid = tid >> 5, lane = tid & 31;
    const int wm = wid & 3, wn = wid >> 2;
    const int bm0 = blockIdx.y * 128;
    const int bn0 = blockIdx.x * BN;

    float acc[2][NFRAG][4];
#pragma unroll
    for (int i = 0; i < 2; i++)
#pragma unroll
        for (int j = 0; j < NFRAG; j++)
#pragma unroll
            for (int k = 0; k < 4; k++) acc[i][j][k] = 0.f;

    const int NC = Kp >> 5;

    auto load_stage = [&](int c, int stg) {
        const uint32_t base = sb + stg * STAGE;
        const size_t koff = (size_t)c * 32;
#pragma unroll
        for (int t = 0; t < 2; t++) {
            int i = tid + t * 256;
            int row = i >> 2, ch = i & 3;
            const __half* src = A + (size_t)(bm0 + row) * Kp + koff + ch * 8;
            cp16(base + SWZ(row * 64 + ch * 16), src);
        }
#pragma unroll
        for (int t = 0; t < BN / 64; t++) {
            int i = tid + t * 256;
            int row = i >> 2, ch = i & 3;
            const __half* src = B + (size_t)(bn0 + row) * Kp + koff + ch * 8;
            cp16(base + ABYTES + SWZ(row * 64 + ch * 16), src);
        }
    };

    const int a_row = wm * 32 + (lane & 15);
    const int a_chb = lane >> 4;
    const int b_row = wn * WNCOL + ((lane >> 4) & 1) * 8 + (lane & 7);
    const int b_chb = (lane >> 3) & 1;

    load_stage(0, 0);
    cp_commit();

    for (int c = 0; c < NC; c++) {
        if (c + 1 < NC) {
            load_stage(c + 1, (c + 1) & 1);
            cp_commit();
            cp_wait<1>();
        } else {
            cp_wait<0>();
        }
        __syncthreads();

        const uint32_t base = sb + (c & 1) * STAGE;
        const uint32_t aB = base, bB = base + ABYTES;

#pragma unroll
        for (int ks = 0; ks < 2; ks++) {
            uint32_t ah[2][4];
#pragma unroll
            for (int mf = 0; mf < 2; mf++) {
                uint32_t off = SWZ((a_row + mf * 16) * 64 + (ks * 2 + a_chb) * 16);
                ldsm4(ah[mf], aB + off);
            }
            uint32_t bh[NPAIR][4];
#pragma unroll
            for (int p = 0; p < NPAIR; p++) {
                uint32_t off = SWZ((b_row + p * 16) * 64 + (ks * 2 + b_chb) * 16);
                ldsm4(bh[p], bB + off);
            }
#pragma unroll
            for (int mf = 0; mf < 2; mf++)
#pragma unroll
                for (int p = 0; p < NPAIR; p++) {
                    mma16816h(acc[mf][2 * p],     ah[mf], bh[p][0], bh[p][1]);
                    mma16816h(acc[mf][2 * p + 1], ah[mf], bh[p][2], bh[p][3]);
                }
        }
        __syncthreads();
    }

#pragma unroll
    for (int mf = 0; mf < 2; mf++) {
        int r0 = bm0 + wm * 32 + mf * 16 + (lane >> 2);
#pragma unroll
        for (int nf = 0; nf < NFRAG; nf++) {
            int col = bn0 + wn * WNCOL + nf * 8 + (lane & 3) * 2;
            if (r0 < M)
                *(float2*)(C + (size_t)r0 * N + col) =
                    make_float2(acc[mf][nf][0], acc[mf][nf][1]);
            if (r0 + 8 < M)
                *(float2*)(C + (size_t)(r0 + 8) * N + col) =
                    make_float2(acc[mf][nf][2], acc[mf][nf][3]);
        }
    }
}

// ===========================================================================
// es/ed logits (one warp per node)
// ===========================================================================
__global__ void es_ed4(const float* __restrict__ h,
                       const float* __restrict__ a_src,
                       const float* __restrict__ a_dst,
                       float* __restrict__ es, float* __restrict__ ed, int n) {
    int w = (blockIdx.x * blockDim.x + threadIdx.x) >> 5;
    int lane = threadIdx.x & 31;
    if (w >= n) return;
    int c = lane * 8;
    const float* hp = h + (size_t)w * 256 + c;
    float4 v0 = *(const float4*)(hp);
    float4 v1 = *(const float4*)(hp + 4);
    float4 as0 = *(const float4*)(a_src + c);
    float4 as1 = *(const float4*)(a_src + c + 4);
    float4 ad0 = *(const float4*)(a_dst + c);
    float4 ad1 = *(const float4*)(a_dst + c + 4);
    float s = v0.x * as0.x + v0.y * as0.y + v0.z * as0.z + v0.w * as0.w +
              v1.x * as1.x + v1.y * as1.y + v1.z * as1.z + v1.w * as1.w;
    float d = v0.x * ad0.x + v0.y * ad0.y + v0.z * ad0.z + v0.w * ad0.w +
              v1.x * ad1.x + v1.y * ad1.y + v1.z * ad1.z + v1.w * ad1.w;
#pragma unroll
    for (int o = 4; o; o >>= 1) {
        s += __shfl_xor_sync(0xffffffffu, s, o);
        d += __shfl_xor_sync(0xffffffffu, d, o);
    }
    if ((lane & 7) == 0) {
        int head = lane >> 3;
        es[w * 4 + head] = s;
        ed[w * 4 + head] = d;
    }
}

__global__ void es_ed1(const float* __restrict__ h,
                       const float* __restrict__ a_src,
                       const float* __restrict__ a_dst,
                       float* __restrict__ es, float* __restrict__ ed, int n) {
    int w = (blockIdx.x * blockDim.x + threadIdx.x) >> 5;
    int lane = threadIdx.x & 31;
    if (w >= n) return;
    int c = lane * 2;
    float2 v = *(const float2*)(h + (size_t)w * 64 + c);
    float2 as = *(const float2*)(a_src + c);
    float2 ad = *(const float2*)(a_dst + c);
    float s = v.x * as.x + v.y * as.y;
    float d = v.x * ad.x + v.y * ad.y;
#pragma unroll
    for (int o = 16; o; o >>= 1) {
        s += __shfl_xor_sync(0xffffffffu, s, o);
        d += __shfl_xor_sync(0xffffffffu, d, o);
    }
    if (lane == 0) { es[w] = s; ed[w] = d; }
}

// ===========================================================================
// agg_gather4: one warp per dst node, register accumulate, fused
// normalize/bias/ELU/fp16-convert -> next GEMM A operand.
// ===========================================================================
__global__ void agg_gather4(const int* __restrict__ rowoff, const int* __restrict__ csrsrc,
                            const float* __restrict__ es, const float* __restrict__ ed,
                            const float* __restrict__ h, const float* __restrict__ b,
                            __half* __restrict__ Hf, int n, int Mp) {
    int w = (blockIdx.x * blockDim.x + threadIdx.x) >> 5;
    int lane = threadIdx.x & 31;
    if (w >= Mp) return;
    const int c0 = lane * 4;
    if (w >= n) {
        *(uint2*)(Hf + (size_t)w * 256 + c0) = make_uint2(0, 0);
        *(uint2*)(Hf + (size_t)w * 256 + c0 + 128) = make_uint2(0, 0);
        return;
    }
    const int myh = lane & 3;
    const int hs = (lane >> 4) & 1;
    float4 ed4 = *(const float4*)(ed + w * 4);
    float edh = sel4(ed4, myh);

    float4 es4 = *(const float4*)(es + w * 4);
    float e = sel4(es4, myh) + edh;
    e = e > 0.f ? e : 0.2f * e;
    float wv = __expf(e);
    float den = wv;
    float al0 = __shfl_sync(0xffffffffu, wv, hs);
    float al1 = __shfl_sync(0xffffffffu, wv, 2 + hs);

    const float* hp = h + (size_t)w * 256;
    float4 a0 = *(const float4*)(hp + c0);
    float4 a1 = *(const float4*)(hp + c0 + 128);
    a0.x *= al0; a0.y *= al0; a0.z *= al0; a0.w *= al0;
    a1.x *= al1; a1.y *= al1; a1.z *= al1; a1.w *= al1;

    int j0 = rowoff[w], j1 = rowoff[w + 1];
    int s = (j0 < j1) ? csrsrc[j0] : 0;
    for (int j = j0; j < j1; j++) {
        int snext = (j + 1 < j1) ? csrsrc[j + 1] : 0;
        float4 e4 = *(const float4*)(es + s * 4);
        float ee = sel4(e4, myh) + edh;
        ee = ee > 0.f ? ee : 0.2f * ee;
        float wj = __expf(ee);
        den += wj;
        float b0 = __shfl_sync(0xffffffffu, wj, hs);
        float b1 = __shfl_sync(0xffffffffu, wj, 2 + hs);
        const float* sp = h + (size_t)s * 256;
        float4 v0 = *(const float4*)(sp + c0);
        float4 v1 = *(const float4*)(sp + c0 + 128);
        a0.x += b0 * v0.x; a0.y += b0 * v0.y; a0.z += b0 * v0.z; a0.w += b0 * v0.w;
        a1.x += b1 * v1.x; a1.y += b1 * v1.y; a1.z += b1 * v1.z; a1.w += b1 * v1.w;
        s = snext;
    }
    float inv0 = __fdividef(1.f, __shfl_sync(0xffffffffu, den, hs));
    float inv1 = __fdividef(1.f, __shfl_sync(0xffffffffu, den, 2 + hs));

    float4 bb0 = *(const float4*)(b + c0);
    float4 bb1 = *(const float4*)(b + c0 + 128);
    float f0[4] = {a0.x * inv0 + bb0.x, a0.y * inv0 + bb0.y,
                   a0.z * inv0 + bb0.z, a0.w * inv0 + bb0.w};
    float f1[4] = {a1.x * inv1 + bb1.x, a1.y * inv1 + bb1.y,
                   a1.z * inv1 + bb1.z, a1.w * inv1 + bb1.w};
#pragma unroll
    for (int k = 0; k < 4; k++) {
        f0[k] = f0[k] > 0.f ? f0[k] : expm1f(f0[k]);
        f1[k] = f1[k] > 0.f ? f1[k] : expm1f(f1[k]);
    }
    size_t o = (size_t)w * 256 + c0;
    *(uint2*)(Hf + o)       = make_uint2(hpack(f0[0], f0[1]), hpack(f0[2], f0[3]));
    *(uint2*)(Hf + o + 128) = make_uint2(hpack(f1[0], f1[1]), hpack(f1[2], f1[3]));
}

// ===========================================================================
// agg_gather1 + classifier (proven R7)
// ===========================================================================
__global__ void agg_gather1(const int* __restrict__ rowoff, const int* __restrict__ csrsrc,
                            const float* __restrict__ es, const float* __restrict__ ed,
                            const float* __restrict__ h, const float* __restrict__ b3,
                            const float* __restrict__ Wc, const float* __restrict__ bc,
                            float* __restrict__ out, int n) {
    int w = (blockIdx.x * blockDim.x + threadIdx.x) >> 5;
    int lane = threadIdx.x & 31;
    if (w >= n) return;
    float edw = ed[w];
    float e = es[w] + edw;
    e = e > 0.f ? e : 0.2f * e;
    float wv = __expf(e);
    float den = wv;
    float v0 = h[(size_t)w * 64 + lane] * wv;
    float v1 = h[(size_t)w * 64 + lane + 32] * wv;

    int j0 = rowoff[w], j1 = rowoff[w + 1];
    int s = (j0 < j1) ? csrsrc[j0] : 0;
    for (int j = j0; j < j1; j++) {
        int snext = (j + 1 < j1) ? csrsrc[j + 1] : 0;
        float ee = es[s] + edw;
        ee = ee > 0.f ? ee : 0.2f * ee;
        float wj = __expf(ee);
        den += wj;
        v0 += wj * h[(size_t)s * 64 + lane];
        v1 += wj * h[(size_t)s * 64 + lane + 32];
        s = snext;
    }
    float inv = __fdividef(1.f, den);
    v0 = v0 * inv + b3[lane];
    v0 = v0 > 0.f ? v0 : expm1f(v0);
    v1 = v1 * inv + b3[lane + 32];
    v1 = v1 > 0.f ? v1 : expm1f(v1);
#pragma unroll
    for (int j = 0; j < 3; j++) {
        float p = v0 * Wc[lane * 3 + j] + v1 * Wc[(lane + 32) * 3 + j];
#pragma unroll
        for (int o = 16; o; o >>= 1) p += __shfl_xor_sync(0xffffffffu, p, o);
        if (lane == 0) out[w * 3 + j] = p + bc[j];
    }
}

// ===========================================================================
// W [K,N] fp32 -> fp16 [N,Kp]
// ===========================================================================
__global__ void conv_wT_h(const float* __restrict__ W,
                          __half* __restrict__ Bh, int K, int N, int Kp) {
    int idx = blockIdx.x * blockDim.x + threadIdx.x;
    if (idx >= N * Kp) return;
    int n = idx / Kp, k = idx - n * Kp;
    float v = (k < K) ? W[(size_t)k * N + n] : 0.f;
    Bh[(size_t)n * Kp + k] = __float2half_rn(v);
}

// ===========================================================================
static inline int cdiv(int a, int b) { return (a + b - 1) / b; }

extern "C" void kernel_launch(void* const* d_in, const int* in_sizes, int n_in,
                              void* d_out, int out_size) {
    const float* x    = (const float*)d_in[0];
    const float* W1   = (const float*)d_in[1];
    const float* a1s  = (const float*)d_in[2];
    const float* a1d  = (const float*)d_in[3];
    const float* b1   = (const float*)d_in[4];
    const float* W2   = (const float*)d_in[5];
    const float* a2s  = (const float*)d_in[6];
    const float* a2d  = (const float*)d_in[7];
    const float* b2   = (const float*)d_in[8];
    const float* W3   = (const float*)d_in[9];
    const float* a3s  = (const float*)d_in[10];
    const float* a3d  = (const float*)d_in[11];
    const float* b3   = (const float*)d_in[12];
    const float* Wc   = (const float*)d_in[13];
    const float* bc   = (const float*)d_in[14];
    const int*   ei   = (const int*)d_in[15];
    float* out = (float*)d_out;

    const int N = GAT_N, E = GAT_E, Mp = GAT_Mp;
    const int* src = ei;
    const int* dst = ei + E;

    float *hA, *h3, *es, *ed;
    int *rowoff, *cursor, *csrsrc;
    __half *Afp, *W1hp, *W2hp, *W3hp;
    cudaGetSymbolAddress((void**)&hA,     g_hA);
    cudaGetSymbolAddress((void**)&h3,     g_h3);
    cudaGetSymbolAddress((void**)&es,     g_es);
    cudaGetSymbolAddress((void**)&ed,     g_ed);
    cudaGetSymbolAddress((void**)&rowoff, g_rowoff);
    cudaGetSymbolAddress((void**)&cursor, g_cursor);
    cudaGetSymbolAddress((void**)&csrsrc, g_csrsrc);
    cudaGetSymbolAddress((void**)&Afp,    g_Af);
    cudaGetSymbolAddress((void**)&W1hp,   g_W1h);
    cudaGetSymbolAddress((void**)&W2hp,   g_W2h);
    cudaGetSymbolAddress((void**)&W3hp,   g_W3h);

    const int SMF   = 73728;                       // AF 32K + AH 16K + B 24K
    const int SM128 = 2 * (8192 + 128 * 64);       // 32768
    const int SM64  = 2 * (8192 + 64 * 64);        // 24576
    cudaFuncSetAttribute(gemm_fused, cudaFuncAttributeMaxDynamicSharedMemorySize, SMF);
    cudaFuncSetAttribute(gemm_h<128>, cudaFuncAttributeMaxDynamicSharedMemorySize, SM128);
    cudaFuncSetAttribute(gemm_h<64>,  cudaFuncAttributeMaxDynamicSharedMemorySize, SM64);

    const int TB = 256;
    const int MT = Mp / 128;               // 235
    const int NPB = cdiv(N * 32, TB);
    const int GPB = cdiv(Mp * 32, TB);

    // ---------------- CSR build ----------------
    csr_zero<<<cdiv(N, TB), TB>>>(cursor, N);
    csr_hist<<<cdiv(E, TB), TB>>>(dst, cursor, E);
    csr_scan<<<1, 1024>>>(cursor, rowoff, N);
    csr_fill<<<cdiv(E, TB), TB>>>(src, dst, cursor, csrsrc, E);

    // ---------------- layer 1 (H=4, K=5000) ----------------
    conv_wT_h<<<cdiv(256 * GAT_K1P, TB), TB>>>(W1, W1hp, GAT_DIN, 256, GAT_K1P);
    gemm_fused<<<dim3(2, MT), 256, SMF>>>(x, W1hp, hA, N, GAT_DIN, GAT_K1P);
    es_ed4<<<NPB, TB>>>(hA, a1s, a1d, es, ed, N);
    agg_gather4<<<GPB, TB>>>(rowoff, csrsrc, es, ed, hA, b1, Afp, N, Mp);

    // ---------------- layer 2 (H=4, K=256) ----------------
    conv_wT_h<<<cdiv(256 * 256, TB), TB>>>(W2, W2hp, 256, 256, 256);
    gemm_h<128><<<dim3(2, MT), 256, SM128>>>(Afp, W2hp, hA, N, 256, 256);
    es_ed4<<<NPB, TB>>>(hA, a2s, a2d, es, ed, N);
    agg_gather4<<<GPB, TB>>>(rowoff, csrsrc, es, ed, hA, b2, Afp, N, Mp);

    // ---------------- layer 3 (H=1, K=256, N=64) ----------------
    conv_wT_h<<<cdiv(64 * 256, TB), TB>>>(W3, W3hp, 256, 64, 256);
    gemm_h<64><<<dim3(1, MT), 256, SM64>>>(Afp, W3hp, h3, N, 64, 256);
    es_ed1<<<NPB, TB>>>(h3, a3s, a3d, es, ed, N);
    agg_gather1<<<NPB, TB>>>(rowoff, csrsrc, es, ed, h3, b3, Wc, bc, out, N);
}

// round 15
// speedup vs baseline: 2.0645x; 1.0216x over previous
#include <cuda_runtime.h>
#include <cuda_bf16.h>
#include <cuda_fp16.h>
#include <cstdint>

// ---------------------------------------------------------------------------
// SentimentGAT on GB300 (sm_103 baseline PTX):
//  all 3 layers: single-product fp16 mma.sync GEMMs, fp32 accumulate,
//  fp16 feature maps end-to-end; CSR-gather attention, fused epilogues.
// ---------------------------------------------------------------------------

#define GAT_N   30000
#define GAT_Mp  30080               // 235 * 128
#define GAT_E   480000
#define GAT_DIN 5000
#define GAT_K1P 5056                // 79 * 64 (padded K stride for W1^T)

// ---- scratch ----
__device__ __align__(128) __half g_hA[(size_t)GAT_N * 256];   // GEMM outputs (fp16)
__device__ __align__(128) __half g_h3[GAT_N * 64];
__device__ float g_es[GAT_N * 4];
__device__ float g_ed[GAT_N * 4];

// ---- CSR ----
__device__ int g_rowoff[GAT_N + 1];
__device__ int g_cursor[GAT_N];
__device__ int g_csrsrc[GAT_E];

// ---- fp16 GEMM operands ----
__device__ __align__(128) __half g_Af[(size_t)GAT_Mp * 256];  // A for layers 2/3
__device__ __align__(128) __half g_W1h[256 * GAT_K1P];
__device__ __align__(128) __half g_W2h[256 * 256];
__device__ __align__(128) __half g_W3h[64 * 256];

// ===========================================================================
// low-level helpers
// ===========================================================================
#define SWZ(o) ((o) ^ (((o) >> 3) & 0x70))

__device__ __forceinline__ uint32_t smem_u32(const void* p) {
    uint32_t a;
    asm("{ .reg .u64 t; cvta.to.shared.u64 t, %1; cvt.u32.u64 %0, t; }"
        : "=r"(a) : "l"(p));
    return a;
}
__device__ __forceinline__ void cp16(uint32_t d, const void* s) {
    asm volatile("cp.async.cg.shared.global [%0], [%1], 16;" :: "r"(d), "l"(s));
}
__device__ __forceinline__ void cp16z(uint32_t d, const void* s, bool pred) {
    int sz = pred ? 16 : 0;
    asm volatile("cp.async.cg.shared.global [%0], [%1], 16, %2;"
                 :: "r"(d), "l"(s), "r"(sz));
}
__device__ __forceinline__ void cp_commit() {
    asm volatile("cp.async.commit_group;" ::: "memory");
}
template <int Ng>
__device__ __forceinline__ void cp_wait() {
    asm volatile("cp.async.wait_group %0;" :: "n"(Ng) : "memory");
}
__device__ __forceinline__ void ldsm4(uint32_t (&r)[4], uint32_t addr) {
    asm volatile("ldmatrix.sync.aligned.m8n8.x4.shared.b16 {%0,%1,%2,%3}, [%4];"
                 : "=r"(r[0]), "=r"(r[1]), "=r"(r[2]), "=r"(r[3]) : "r"(addr));
}
__device__ __forceinline__ void mma16816h(float (&d)[4], const uint32_t (&a)[4],
                                          uint32_t b0, uint32_t b1) {
    asm volatile("mma.sync.aligned.m16n8k16.row.col.f32.f16.f16.f32 "
                 "{%0,%1,%2,%3}, {%4,%5,%6,%7}, {%8,%9}, {%0,%1,%2,%3};"
                 : "+f"(d[0]), "+f"(d[1]), "+f"(d[2]), "+f"(d[3])
                 : "r"(a[0]), "r"(a[1]), "r"(a[2]), "r"(a[3]), "r"(b0), "r"(b1));
}
__device__ __forceinline__ uint32_t hpack(float a, float b) {
    return (uint32_t)__half_as_ushort(__float2half_rn(a)) |
           ((uint32_t)__half_as_ushort(__float2half_rn(b)) << 16);
}
__device__ __forceinline__ float2 h2f(uint32_t u) {
    return __half22float2(*(__half2*)&u);
}
__device__ __forceinline__ float sel4(float4 v, int i) {
    float a = (i & 1) ? v.y : v.x;
    float b = (i & 1) ? v.w : v.z;
    return (i & 2) ? b : a;
}

// ===========================================================================
// CSR build
// ===========================================================================
__global__ void csr_zero(int* cur, int n) {
    int i = blockIdx.x * blockDim.x + threadIdx.x;
    if (i < n) cur[i] = 0;
}
__global__ void csr_hist(const int* __restrict__ dst, int* cur, int E_) {
    int i = blockIdx.x * blockDim.x + threadIdx.x;
    if (i < E_) atomicAdd(&cur[dst[i]], 1);
}
__global__ void csr_scan(int* degcur, int* rowoff, int n) {
    __shared__ int sh[1024];
    __shared__ int carry_s;
    int tid = threadIdx.x;
    if (tid == 0) carry_s = 0;
    __syncthreads();
    for (int base = 0; base < n; base += 1024) {
        int i = base + tid;
        int v = (i < n) ? degcur[i] : 0;
        sh[tid] = v;
        __syncthreads();
#pragma unroll
        for (int o = 1; o < 1024; o <<= 1) {
            int t = (tid >= o) ? sh[tid - o] : 0;
            __syncthreads();
            sh[tid] += t;
            __syncthreads();
        }
        int excl = sh[tid] - v + carry_s;
        if (i < n) { rowoff[i] = excl; degcur[i] = excl; }
        __syncthreads();
        if (tid == 1023) carry_s += sh[1023];
        __syncthreads();
    }
    if (tid == 0) rowoff[n] = carry_s;
}
__global__ void csr_fill(const int* __restrict__ src, const int* __restrict__ dst,
                         int* cur, int* csrsrc, int E_) {
    int i = blockIdx.x * blockDim.x + threadIdx.x;
    if (i < E_) {
        int p = atomicAdd(&cur[dst[i]], 1);
        csrsrc[p] = src[i];
    }
}

// ===========================================================================
// FUSED layer-1 GEMM (fp16 single product): C16 = fp16(X) @ fp16(W1)^T
// BK=32 single-barrier pipeline, self-consistent convert (R13-proven).
// smem: AF 0..32K (x2 16K) | AH 32K..48K (x2 8K) | B 48K..72K (x3 8K)
// ===========================================================================
__global__ __launch_bounds__(256)
void gemm_fused(const float* __restrict__ X, const __half* __restrict__ Bh,
                __half* __restrict__ C, int M, int K, int KpB) {
    extern __shared__ char smem[];
    const uint32_t sb = smem_u32(smem);

    const int tid = threadIdx.x;
    const int wid = tid >> 5, lane = tid & 31;
    const int wm = wid & 3, wn = wid >> 2;
    const int bm0 = blockIdx.y * 128;
    const int bn0 = blockIdx.x * 128;

    float acc[2][8][4];
#pragma unroll
    for (int i = 0; i < 2; i++)
#pragma unroll
        for (int j = 0; j < 8; j++)
#pragma unroll
            for (int k = 0; k < 4; k++) acc[i][j][k] = 0.f;

    const int NC = (K + 31) >> 5;

    auto load_tile = [&](int c) {
        const uint32_t af = sb + (c & 1) * 16384;
        const uint32_t bb = sb + 49152 + (c % 3) * 8192;
        const int k0 = c * 32;
#pragma unroll
        for (int t = 0; t < 4; t++) {
            int i = tid + t * 256;
            int row = i >> 3, q = i & 7;
            int gm = bm0 + row, gk = k0 + q * 4;
            bool p = (gm < M) && (gk < K);
            cp16z(af + row * 128 + q * 16, X + (p ? ((size_t)gm * K + gk) : 0), p);
        }
#pragma unroll
        for (int t = 0; t < 2; t++) {
            int i = tid + t * 256;
            int row = i >> 2, ch = i & 3;
            const __half* src = Bh + (size_t)(bn0 + row) * KpB + k0 + ch * 8;
            cp16(bb + SWZ(row * 64 + ch * 16), src);
        }
    };

    auto convert = [&](int c) {
        const int s2 = c & 1;
        const char* afp = smem + s2 * 16384;
        char* ahp = smem + 32768 + s2 * 8192;
#pragma unroll
        for (int t = 0; t < 4; t++) {
            int i = tid + t * 256;
            int row = i >> 3, q = i & 7;
            float4 v = *(const float4*)(afp + row * 128 + q * 16);
            uint32_t h0 = hpack(v.x, v.y);
            uint32_t h1 = hpack(v.z, v.w);
            uint32_t off = SWZ(row * 64 + (q & 6) * 8) + (q & 1) * 8;
            *(uint2*)(ahp + off) = make_uint2(h0, h1);
        }
    };

    const int a_row = wm * 32 + (lane & 15);
    const int a_chb = lane >> 4;
    const int b_row = wn * 64 + ((lane >> 4) & 1) * 8 + (lane & 7);
    const int b_chb = (lane >> 3) & 1;

    load_tile(0); cp_commit();
    if (NC > 1) { load_tile(1); cp_commit(); }
    cp_wait<1>();
    convert(0);

    for (int c = 0; c < NC; c++) {
        __syncthreads();

        const uint32_t aH = sb + 32768 + (c & 1) * 8192;
        const uint32_t bB = sb + 49152 + (c % 3) * 8192;
#pragma unroll
        for (int ks = 0; ks < 2; ks++) {
            uint32_t ah[2][4];
#pragma unroll
            for (int mf = 0; mf < 2; mf++) {
                uint32_t off = SWZ((a_row + mf * 16) * 64 + (ks * 2 + a_chb) * 16);
                ldsm4(ah[mf], aH + off);
            }
            uint32_t bh[4][4];
#pragma unroll
            for (int p = 0; p < 4; p++) {
                uint32_t off = SWZ((b_row + p * 16) * 64 + (ks * 2 + b_chb) * 16);
                ldsm4(bh[p], bB + off);
            }
#pragma unroll
            for (int mf = 0; mf < 2; mf++)
#pragma unroll
                for (int p = 0; p < 4; p++) {
                    mma16816h(acc[mf][2 * p],     ah[mf], bh[p][0], bh[p][1]);
                    mma16816h(acc[mf][2 * p + 1], ah[mf], bh[p][2], bh[p][3]);
                }
        }

        if (c + 1 < NC) {
            cp_wait<0>();
            convert(c + 1);
        }
        if (c + 2 < NC) {
            load_tile(c + 2);
            cp_commit();
        }
    }

#pragma unroll
    for (int mf = 0; mf < 2; mf++) {
        int r0 = bm0 + wm * 32 + mf * 16 + (lane >> 2);
#pragma unroll
        for (int nf = 0; nf < 8; nf++) {
            int col = bn0 + wn * 64 + nf * 8 + (lane & 3) * 2;
            if (r0 < M)
                *(uint32_t*)(C + (size_t)r0 * 256 + col) =
                    hpack(acc[mf][nf][0], acc[mf][nf][1]);
            if (r0 + 8 < M)
                *(uint32_t*)(C + (size_t)(r0 + 8) * 256 + col) =
                    hpack(acc[mf][nf][2], acc[mf][nf][3]);
        }
    }
}

// ===========================================================================
// fp16 single-product GEMM for layers 2/3: C16[M,N] = A @ B^T
// ===========================================================================
template <int BN>
__global__ __launch_bounds__(256)
void gemm_h(const __half* __restrict__ A, const __half* __restrict__ B,
            __half* __restrict__ C, int M, int N, int Kp) {
    constexpr int WNCOL = BN / 2;
    constexpr int NFRAG = WNCOL / 8;
    constexpr int NPAIR = NFRAG / 2;
    constexpr int ABYTES = 8192;
    constexpr int BBYTES = BN * 64;
    constexpr int STAGE = ABYTES + BBYTES;

    extern __shared__ char smem[];
    const uint32_t sb = smem_u32(smem);

    const int tid = threadIdx.x;
    const int wid = tid >> 5, lane = tid & 31;
    const int wm = wid & 3, wn = wid >> 2;
    const int bm0 = blockIdx.y * 128;
    const int bn0 = blockIdx.x * BN;

    float acc[2][NFRAG][4];
#pragma unroll
    for (int i = 0; i < 2; i++)
#pragma unroll
        for (int j = 0; j < NFRAG; j++)
#pragma unroll
            for (int k = 0; k < 4; k++) acc[i][j][k] = 0.f;

    const int NC = Kp >> 5;

    auto load_stage = [&](int c, int stg) {
        const uint32_t base = sb + stg * STAGE;
        const size_t koff = (size_t)c * 32;
#pragma unroll
        for (int t = 0; t < 2; t++) {
            int i = tid + t * 256;
            int row = i >> 2, ch = i & 3;
            const __half* src = A + (size_t)(bm0 + row) * Kp + koff + ch * 8;
            cp16(base + SWZ(row * 64 + ch * 16), src);
        }
#pragma unroll
        for (int t = 0; t < BN / 64; t++) {
            int i = tid + t * 256;
            int row = i >> 2, ch = i & 3;
            const __half* src = B + (size_t)(bn0 + row) * Kp + koff + ch * 8;
            cp16(base + ABYTES + SWZ(row * 64 + ch * 16), src);
        }
    };

    const int a_row = wm * 32 + (lane & 15);
    const int a_chb = lane >> 4;
    const int b_row = wn * WNCOL + ((lane >> 4) & 1) * 8 + (lane & 7);
    const int b_chb = (lane >> 3) & 1;

    load_stage(0, 0);
    cp_commit();

    for (int c = 0; c < NC; c++) {
        if (c + 1 < NC) {
            load_stage(c + 1, (c + 1) & 1);
            cp_commit();
            cp_wait<1>();
        } else {
            cp_wait<0>();
        }
        __syncthreads();

        const uint32_t base = sb + (c & 1) * STAGE;
        const uint32_t aB = base, bB = base + ABYTES;

#pragma unroll
        for (int ks = 0; ks < 2; ks++) {
            uint32_t ah[2][4];
#pragma unroll
            for (int mf = 0; mf < 2; mf++) {
                uint32_t off = SWZ((a_row + mf * 16) * 64 + (ks * 2 + a_chb) * 16);
                ldsm4(ah[mf], aB + off);
            }
            uint32_t bh[NPAIR][4];
#pragma unroll
            for (int p = 0; p < NPAIR; p++) {
                uint32_t off = SWZ((b_row + p * 16) * 64 + (ks * 2 + b_chb) * 16);
                ldsm4(bh[p], bB + off);
            }
#pragma unroll
            for (int mf = 0; mf < 2; mf++)
#pragma unroll
                for (int p = 0; p < NPAIR; p++) {
                    mma16816h(acc[mf][2 * p],     ah[mf], bh[p][0], bh[p][1]);
                    mma16816h(acc[mf][2 * p + 1], ah[mf], bh[p][2], bh[p][3]);
                }
        }
        __syncthreads();
    }

#pragma unroll
    for (int mf = 0; mf < 2; mf++) {
        int r0 = bm0 + wm * 32 + mf * 16 + (lane >> 2);
#pragma unroll
        for (int nf = 0; nf < NFRAG; nf++) {
            int col = bn0 + wn * WNCOL + nf * 8 + (lane & 3) * 2;
            if (r0 < M)
                *(uint32_t*)(C + (size_t)r0 * N + col) =
                    hpack(acc[mf][nf][0], acc[mf][nf][1]);
            if (r0 + 8 < M)
                *(uint32_t*)(C + (size_t)(r0 + 8) * N + col) =
                    hpack(acc[mf][nf][2], acc[mf][nf][3]);
        }
    }
}

// ===========================================================================
// es/ed logits (one warp per node), fp16 h
// ===========================================================================
__global__ void es_ed4(const __half* __restrict__ h,
                       const float* __restrict__ a_src,
                       const float* __restrict__ a_dst,
                       float* __restrict__ es, float* __restrict__ ed, int n) {
    int w = (blockIdx.x * blockDim.x + threadIdx.x) >> 5;
    int lane = threadIdx.x & 31;
    if (w >= n) return;
    int c = lane * 8;
    uint4 raw = *(const uint4*)(h + (size_t)w * 256 + c);
    float2 f0 = h2f(raw.x), f1 = h2f(raw.y), f2 = h2f(raw.z), f3 = h2f(raw.w);
    float4 as0 = *(const float4*)(a_src + c);
    float4 as1 = *(const float4*)(a_src + c + 4);
    float4 ad0 = *(const float4*)(a_dst + c);
    float4 ad1 = *(const float4*)(a_dst + c + 4);
    float s = f0.x * as0.x + f0.y * as0.y + f1.x * as0.z + f1.y * as0.w +
              f2.x * as1.x + f2.y * as1.y + f3.x * as1.z + f3.y * as1.w;
    float d = f0.x * ad0.x + f0.y * ad0.y + f1.x * ad0.z + f1.y * ad0.w +
              f2.x * ad1.x + f2.y * ad1.y + f3.x * ad1.z + f3.y * ad1.w;
#pragma unroll
    for (int o = 4; o; o >>= 1) {
        s += __shfl_xor_sync(0xffffffffu, s, o);
        d += __shfl_xor_sync(0xffffffffu, d, o);
    }
    if ((lane & 7) == 0) {
        int head = lane >> 3;
        es[w * 4 + head] = s;
        ed[w * 4 + head] = d;
    }
}

__global__ void es_ed1(const __half* __restrict__ h,
                       const float* __restrict__ a_src,
                       const float* __restrict__ a_dst,
                       float* __restrict__ es, float* __restrict__ ed, int n) {
    int w = (blockIdx.x * blockDim.x + threadIdx.x) >> 5;
    int lane = threadIdx.x & 31;
    if (w >= n) return;
    int c = lane * 2;
    float2 v = h2f(*(const uint32_t*)(h + (size_t)w * 64 + c));
    float2 as = *(const float2*)(a_src + c);
    float2 ad = *(const float2*)(a_dst + c);
    float s = v.x * as.x + v.y * as.y;
    float d = v.x * ad.x + v.y * ad.y;
#pragma unroll
    for (int o = 16; o; o >>= 1) {
        s += __shfl_xor_sync(0xffffffffu, s, o);
        d += __shfl_xor_sync(0xffffffffu, d, o);
    }
    if (lane == 0) { es[w] = s; ed[w] = d; }
}

// ===========================================================================
// agg_gather4: one warp per dst node, fp16 h gather, fp32 accumulate,
// fused normalize/bias/ELU/fp16-convert -> next GEMM A operand.
// ===========================================================================
__global__ void agg_gather4(const int* __restrict__ rowoff, const int* __restrict__ csrsrc,
                            const float* __restrict__ es, const float* __restrict__ ed,
                            const __half* __restrict__ h, const float* __restrict__ b,
                            __half* __restrict__ Hf, int n, int Mp) {
    int w = (blockIdx.x * blockDim.x + threadIdx.x) >> 5;
    int lane = threadIdx.x & 31;
    if (w >= Mp) return;
    const int c0 = lane * 4;
    if (w >= n) {
        *(uint2*)(Hf + (size_t)w * 256 + c0) = make_uint2(0, 0);
        *(uint2*)(Hf + (size_t)w * 256 + c0 + 128) = make_uint2(0, 0);
        return;
    }
    const int myh = lane & 3;
    const int hs = (lane >> 4) & 1;
    float4 ed4 = *(const float4*)(ed + w * 4);
    float edh = sel4(ed4, myh);

    float4 es4 = *(const float4*)(es + w * 4);
    float e = sel4(es4, myh) + edh;
    e = e > 0.f ? e : 0.2f * e;
    float wv = __expf(e);
    float den = wv;
    float al0 = __shfl_sync(0xffffffffu, wv, hs);
    float al1 = __shfl_sync(0xffffffffu, wv, 2 + hs);

    const __half* hp = h + (size_t)w * 256;
    uint2 r0v = *(const uint2*)(hp + c0);
    uint2 r1v = *(const uint2*)(hp + c0 + 128);
    float2 g0 = h2f(r0v.x), g1 = h2f(r0v.y), g2 = h2f(r1v.x), g3 = h2f(r1v.y);
    float4 a0 = make_float4(g0.x * al0, g0.y * al0, g1.x * al0, g1.y * al0);
    float4 a1 = make_float4(g2.x * al1, g2.y * al1, g3.x * al1, g3.y * al1);

    int j0 = rowoff[w], j1 = rowoff[w + 1];
    int s = (j0 < j1) ? csrsrc[j0] : 0;
    for (int j = j0; j < j1; j++) {
        int snext = (j + 1 < j1) ? csrsrc[j + 1] : 0;
        float4 e4 = *(const float4*)(es + s * 4);
        float ee = sel4(e4, myh) + edh;
        ee = ee > 0.f ? ee : 0.2f * ee;
        float wj = __expf(ee);
        den += wj;
        float b0 = __shfl_sync(0xffffffffu, wj, hs);
        float b1 = __shfl_sync(0xffffffffu, wj, 2 + hs);
        const __half* sp = h + (size_t)s * 256;
        uint2 v0 = *(const uint2*)(sp + c0);
        uint2 v1 = *(const uint2*)(sp + c0 + 128);
        float2 p0 = h2f(v0.x), p1 = h2f(v0.y), p2 = h2f(v1.x), p3 = h2f(v1.y);
        a0.x += b0 * p0.x; a0.y += b0 * p0.y; a0.z += b0 * p1.x; a0.w += b0 * p1.y;
        a1.x += b1 * p2.x; a1.y += b1 * p2.y; a1.z += b1 * p3.x; a1.w += b1 * p3.y;
        s = snext;
    }
    float inv0 = __fdividef(1.f, __shfl_sync(0xffffffffu, den, hs));
    float inv1 = __fdividef(1.f, __shfl_sync(0xffffffffu, den, 2 + hs));

    float4 bb0 = *(const float4*)(b + c0);
    float4 bb1 = *(const float4*)(b + c0 + 128);
    float f0[4] = {a0.x * inv0 + bb0.x, a0.y * inv0 + bb0.y,
                   a0.z * inv0 + bb0.z, a0.w * inv0 + bb0.w};
    float f1[4] = {a1.x * inv1 + bb1.x, a1.y * inv1 + bb1.y,
                   a1.z * inv1 + bb1.z, a1.w * inv1 + bb1.w};
#pragma unroll
    for (int k = 0; k < 4; k++) {
        f0[k] = f0[k] > 0.f ? f0[k] : expm1f(f0[k]);
        f1[k] = f1[k] > 0.f ? f1[k] : expm1f(f1[k]);
    }
    size_t o = (size_t)w * 256 + c0;
    *(uint2*)(Hf + o)       = make_uint2(hpack(f0[0], f0[1]), hpack(f0[2], f0[3]));
    *(uint2*)(Hf + o + 128) = make_uint2(hpack(f1[0], f1[1]), hpack(f1[2], f1[3]));
}

// ===========================================================================
// agg_gather1 + classifier, fp16 h3
// ===========================================================================
__global__ void agg_gather1(const int* __restrict__ rowoff, const int* __restrict__ csrsrc,
                            const float* __restrict__ es, const float* __restrict__ ed,
                            const __half* __restrict__ h, const float* __restrict__ b3,
                            const float* __restrict__ Wc, const float* __restrict__ bc,
                            float* __restrict__ out, int n) {
    int w = (blockIdx.x * blockDim.x + threadIdx.x) >> 5;
    int lane = threadIdx.x & 31;
    if (w >= n) return;
    float edw = ed[w];
    float e = es[w] + edw;
    e = e > 0.f ? e : 0.2f * e;
    float wv = __expf(e);
    float den = wv;
    float2 hv = h2f(*(const uint32_t*)(h + (size_t)w * 64 + lane * 2));
    float v0 = hv.x * wv;
    float v1 = hv.y * wv;

    int j0 = rowoff[w], j1 = rowoff[w + 1];
    int s = (j0 < j1) ? csrsrc[j0] : 0;
    for (int j = j0; j < j1; j++) {
        int snext = (j + 1 < j1) ? csrsrc[j + 1] : 0;
        float ee = es[s] + edw;
        ee = ee > 0.f ? ee : 0.2f * ee;
        float wj = __expf(ee);
        den += wj;
        float2 sv = h2f(*(const uint32_t*)(h + (size_t)s * 64 + lane * 2));
        v0 += wj * sv.x;
        v1 += wj * sv.y;
        s = snext;
    }
    float inv = __fdividef(1.f, den);
    v0 = v0 * inv + b3[lane * 2];
    v0 = v0 > 0.f ? v0 : expm1f(v0);
    v1 = v1 * inv + b3[lane * 2 + 1];
    v1 = v1 > 0.f ? v1 : expm1f(v1);
#pragma unroll
    for (int j = 0; j < 3; j++) {
        float p = v0 * Wc[(lane * 2) * 3 + j] + v1 * Wc[(lane * 2 + 1) * 3 + j];
#pragma unroll
        for (int o = 16; o; o >>= 1) p += __shfl_xor_sync(0xffffffffu, p, o);
        if (lane == 0) out[w * 3 + j] = p + bc[j];
    }
}

// ===========================================================================
// W [K,N] fp32 -> fp16 [N,Kp]
// ===========================================================================
__global__ void conv_wT_h(const float* __restrict__ W,
                          __half* __restrict__ Bh, int K, int N, int Kp) {
    int idx = blockIdx.x * blockDim.x + threadIdx.x;
    if (idx >= N * Kp) return;
    int n = idx / Kp, k = idx - n * Kp;
    float v = (k < K) ? W[(size_t)k * N + n] : 0.f;
    Bh[(size_t)n * Kp + k] = __float2half_rn(v);
}

// ===========================================================================
static inline int cdiv(int a, int b) { return (a + b - 1) / b; }

extern "C" void kernel_launch(void* const* d_in, const int* in_sizes, int n_in,
                              void* d_out, int out_size) {
    const float* x    = (const float*)d_in[0];
    const float* W1   = (const float*)d_in[1];
    const float* a1s  = (const float*)d_in[2];
    const float* a1d  = (const float*)d_in[3];
    const float* b1   = (const float*)d_in[4];
    const float* W2   = (const float*)d_in[5];
    const float* a2s  = (const float*)d_in[6];
    const float* a2d  = (const float*)d_in[7];
    const float* b2   = (const float*)d_in[8];
    const float* W3   = (const float*)d_in[9];
    const float* a3s  = (const float*)d_in[10];
    const float* a3d  = (const float*)d_in[11];
    const float* b3   = (const float*)d_in[12];
    const float* Wc   = (const float*)d_in[13];
    const float* bc   = (const float*)d_in[14];
    const int*   ei   = (const int*)d_in[15];
    float* out = (float*)d_out;

    const int N = GAT_N, E = GAT_E, Mp = GAT_Mp;
    const int* src = ei;
    const int* dst = ei + E;

    float *es, *ed;
    int *rowoff, *cursor, *csrsrc;
    __half *hAh, *h3h, *Afp, *W1hp, *W2hp, *W3hp;
    cudaGetSymbolAddress((void**)&hAh,    g_hA);
    cudaGetSymbolAddress((void**)&h3h,    g_h3);
    cudaGetSymbolAddress((void**)&es,     g_es);
    cudaGetSymbolAddress((void**)&ed,     g_ed);
    cudaGetSymbolAddress((void**)&rowoff, g_rowoff);
    cudaGetSymbolAddress((void**)&cursor, g_cursor);
    cudaGetSymbolAddress((void**)&csrsrc, g_csrsrc);
    cudaGetSymbolAddress((void**)&Afp,    g_Af);
    cudaGetSymbolAddress((void**)&W1hp,   g_W1h);
    cudaGetSymbolAddress((void**)&W2hp,   g_W2h);
    cudaGetSymbolAddress((void**)&W3hp,   g_W3h);

    const int SMF   = 73728;
    const int SM128 = 2 * (8192 + 128 * 64);
    const int SM64  = 2 * (8192 + 64 * 64);
    cudaFuncSetAttribute(gemm_fused,  cudaFuncAttributeMaxDynamicSharedMemorySize, SMF);
    cudaFuncSetAttribute(gemm_h<128>, cudaFuncAttributeMaxDynamicSharedMemorySize, SM128);
    cudaFuncSetAttribute(gemm_h<64>,  cudaFuncAttributeMaxDynamicSharedMemorySize, SM64);

    const int TB = 256;
    const int MT = Mp / 128;               // 235
    const int NPB = cdiv(N * 32, TB);
    const int GPB = cdiv(Mp * 32, TB);

    // ---------------- CSR build ----------------
    csr_zero<<<cdiv(N, TB), TB>>>(cursor, N);
    csr_hist<<<cdiv(E, TB), TB>>>(dst, cursor, E);
    csr_scan<<<1, 1024>>>(cursor, rowoff, N);
    csr_fill<<<cdiv(E, TB), TB>>>(src, dst, cursor, csrsrc, E);

    // ---------------- layer 1 (H=4, K=5000) ----------------
    conv_wT_h<<<cdiv(256 * GAT_K1P, TB), TB>>>(W1, W1hp, GAT_DIN, 256, GAT_K1P);
    gemm_fused<<<dim3(2, MT), 256, SMF>>>(x, W1hp, hAh, N, GAT_DIN, GAT_K1P);
    es_ed4<<<NPB, TB>>>(hAh, a1s, a1d, es, ed, N);
    agg_gather4<<<GPB, TB>>>(rowoff, csrsrc, es, ed, hAh, b1, Afp, N, Mp);

    // ---------------- layer 2 (H=4, K=256) ----------------
    conv_wT_h<<<cdiv(256 * 256, TB), TB>>>(W2, W2hp, 256, 256, 256);
    gemm_h<128><<<dim3(2, MT), 256, SM128>>>(Afp, W2hp, hAh, N, 256, 256);
    es_ed4<<<NPB, TB>>>(hAh, a2s, a2d, es, ed, N);
    agg_gather4<<<GPB, TB>>>(rowoff, csrsrc, es, ed, hAh, b2, Afp, N, Mp);

    // ---------------- layer 3 (H=1, K=256, N=64) ----------------
    conv_wT_h<<<cdiv(64 * 256, TB), TB>>>(W3, W3hp, 256, 64, 256);
    gemm_h<64><<<dim3(1, MT), 256, SM64>>>(Afp, W3hp, h3h, N, 64, 256);
    es_ed1<<<NPB, TB>>>(h3h, a3s, a3d, es, ed, N);
    agg_gather1<<<NPB, TB>>>(rowoff, csrsrc, es, ed, h3h, b3, Wc, bc, out, N);
}

// round 16
// speedup vs baseline: 2.1934x; 1.0625x over previous
#include <cuda_runtime.h>
#include <cuda_bf16.h>
#include <cuda_fp16.h>
#include <cstdint>

// ---------------------------------------------------------------------------
// SentimentGAT on GB300 (sm_103 baseline PTX):
//  fp16 single-product mma.sync GEMMs with fused es/ed logit epilogues,
//  fp16 feature maps end-to-end; CSR-gather attention, fused epilogues.
// ---------------------------------------------------------------------------

#define GAT_N   30000
#define GAT_Mp  30080               // 235 * 128
#define GAT_E   480000
#define GAT_DIN 5000
#define GAT_K1P 5056                // 79 * 64 (padded K stride for W1^T)

// ---- scratch ----
__device__ __align__(128) __half g_hA[(size_t)GAT_N * 256];
__device__ __align__(128) __half g_h3[GAT_N * 64];
__device__ float g_es[GAT_N * 4];
__device__ float g_ed[GAT_N * 4];

// ---- CSR ----
__device__ int g_rowoff[GAT_N + 1];
__device__ int g_cursor[GAT_N];
__device__ int g_csrsrc[GAT_E];

// ---- fp16 GEMM operands ----
__device__ __align__(128) __half g_Af[(size_t)GAT_Mp * 256];
__device__ __align__(128) __half g_W1h[256 * GAT_K1P];
__device__ __align__(128) __half g_W2h[256 * 256];
__device__ __align__(128) __half g_W3h[64 * 256];

// ===========================================================================
// low-level helpers
// ===========================================================================
#define SWZ(o) ((o) ^ (((o) >> 3) & 0x70))

__device__ __forceinline__ uint32_t smem_u32(const void* p) {
    uint32_t a;
    asm("{ .reg .u64 t; cvta.to.shared.u64 t, %1; cvt.u32.u64 %0, t; }"
        : "=r"(a) : "l"(p));
    return a;
}
__device__ __forceinline__ void cp16(uint32_t d, const void* s) {
    asm volatile("cp.async.cg.shared.global [%0], [%1], 16;" :: "r"(d), "l"(s));
}
__device__ __forceinline__ void cp16z(uint32_t d, const void* s, bool pred) {
    int sz = pred ? 16 : 0;
    asm volatile("cp.async.cg.shared.global [%0], [%1], 16, %2;"
                 :: "r"(d), "l"(s), "r"(sz));
}
__device__ __forceinline__ void cp_commit() {
    asm volatile("cp.async.commit_group;" ::: "memory");
}
template <int Ng>
__device__ __forceinline__ void cp_wait() {
    asm volatile("cp.async.wait_group %0;" :: "n"(Ng) : "memory");
}
__device__ __forceinline__ void ldsm4(uint32_t (&r)[4], uint32_t addr) {
    asm volatile("ldmatrix.sync.aligned.m8n8.x4.shared.b16 {%0,%1,%2,%3}, [%4];"
                 : "=r"(r[0]), "=r"(r[1]), "=r"(r[2]), "=r"(r[3]) : "r"(addr));
}
__device__ __forceinline__ void mma16816h(float (&d)[4], const uint32_t (&a)[4],
                                          uint32_t b0, uint32_t b1) {
    asm volatile("mma.sync.aligned.m16n8k16.row.col.f32.f16.f16.f32 "
                 "{%0,%1,%2,%3}, {%4,%5,%6,%7}, {%8,%9}, {%0,%1,%2,%3};"
                 : "+f"(d[0]), "+f"(d[1]), "+f"(d[2]), "+f"(d[3])
                 : "r"(a[0]), "r"(a[1]), "r"(a[2]), "r"(a[3]), "r"(b0), "r"(b1));
}
__device__ __forceinline__ uint32_t hpack(float a, float b) {
    return (uint32_t)__half_as_ushort(__float2half_rn(a)) |
           ((uint32_t)__half_as_ushort(__float2half_rn(b)) << 16);
}
__device__ __forceinline__ float2 h2f(uint32_t u) {
    return __half22float2(*(__half2*)&u);
}
__device__ __forceinline__ float sel4(float4 v, int i) {
    float a = (i & 1) ? v.y : v.x;
    float b = (i & 1) ? v.w : v.z;
    return (i & 2) ? b : a;
}

// ===========================================================================
// CSR build
// ===========================================================================
__global__ void csr_zero(int* cur, int n) {
    int i = blockIdx.x * blockDim.x + threadIdx.x;
    if (i < n) cur[i] = 0;
}
__global__ void csr_hist(const int* __restrict__ dst, int* cur, int E_) {
    int i = blockIdx.x * blockDim.x + threadIdx.x;
    if (i < E_) atomicAdd(&cur[dst[i]], 1);
}
// shuffle-based block scan (1024 threads, 3 barriers per chunk)
__global__ void csr_scan(int* degcur, int* rowoff, int n) {
    __shared__ int wsum[32];
    __shared__ int carry_s;
    const int tid = threadIdx.x;
    const int lane = tid & 31, wid = tid >> 5;
    if (tid == 0) carry_s = 0;
    __syncthreads();
    for (int base = 0; base < n; base += 1024) {
        int i = base + tid;
        int v = (i < n) ? degcur[i] : 0;
        int x = v;
#pragma unroll
        for (int o = 1; o < 32; o <<= 1) {
            int t = __shfl_up_sync(0xffffffffu, x, o);
            if (lane >= o) x += t;
        }
        if (lane == 31) wsum[wid] = x;
        __syncthreads();
        if (wid == 0) {
            int y = wsum[lane];
#pragma unroll
            for (int o = 1; o < 32; o <<= 1) {
                int t = __shfl_up_sync(0xffffffffu, y, o);
                if (lane >= o) y += t;
            }
            wsum[lane] = y;
        }
        __syncthreads();
        int woff = (wid > 0) ? wsum[wid - 1] : 0;
        int incl = x + woff + carry_s;
        int excl = incl - v;
        if (i < n) { rowoff[i] = excl; degcur[i] = excl; }
        __syncthreads();
        if (tid == 1023) carry_s = incl;
        __syncthreads();
    }
    if (tid == 0) rowoff[n] = carry_s;
}
__global__ void csr_fill(const int* __restrict__ src, const int* __restrict__ dst,
                         int* cur, int* csrsrc, int E_) {
    int i = blockIdx.x * blockDim.x + threadIdx.x;
    if (i < E_) {
        int p = atomicAdd(&cur[dst[i]], 1);
        csrsrc[p] = src[i];
    }
}

// ===========================================================================
// FUSED layer-1 GEMM + es/ed epilogue: C16 = fp16(X) @ fp16(W1)^T
// BK=32 single-barrier pipeline, self-consistent convert (R13-proven).
// Each warp's 64-col block == one head -> es/ed from fp32 accs.
// ===========================================================================
__global__ __launch_bounds__(256)
void gemm_fused(const float* __restrict__ X, const __half* __restrict__ Bh,
                __half* __restrict__ C,
                const float* __restrict__ a_src, const float* __restrict__ a_dst,
                float* __restrict__ es, float* __restrict__ ed,
                int M, int K, int KpB) {
    extern __shared__ char smem[];
    const uint32_t sb = smem_u32(smem);

    const int tid = threadIdx.x;
    const int wid = tid >> 5, lane = tid & 31;
    const int wm = wid & 3, wn = wid >> 2;
    const int bm0 = blockIdx.y * 128;
    const int bn0 = blockIdx.x * 128;

    float acc[2][8][4];
#pragma unroll
    for (int i = 0; i < 2; i++)
#pragma unroll
        for (int j = 0; j < 8; j++)
#pragma unroll
            for (int k = 0; k < 4; k++) acc[i][j][k] = 0.f;

    const int NC = (K + 31) >> 5;

    auto load_tile = [&](int c) {
        const uint32_t af = sb + (c & 1) * 16384;
        const uint32_t bb = sb + 49152 + (c % 3) * 8192;
        const int k0 = c * 32;
#pragma unroll
        for (int t = 0; t < 4; t++) {
            int i = tid + t * 256;
            int row = i >> 3, q = i & 7;
            int gm = bm0 + row, gk = k0 + q * 4;
            bool p = (gm < M) && (gk < K);
            cp16z(af + row * 128 + q * 16, X + (p ? ((size_t)gm * K + gk) : 0), p);
        }
#pragma unroll
        for (int t = 0; t < 2; t++) {
            int i = tid + t * 256;
            int row = i >> 2, ch = i & 3;
            const __half* src = Bh + (size_t)(bn0 + row) * KpB + k0 + ch * 8;
            cp16(bb + SWZ(row * 64 + ch * 16), src);
        }
    };

    auto convert = [&](int c) {
        const int s2 = c & 1;
        const char* afp = smem + s2 * 16384;
        char* ahp = smem + 32768 + s2 * 8192;
#pragma unroll
        for (int t = 0; t < 4; t++) {
            int i = tid + t * 256;
            int row = i >> 3, q = i & 7;
            float4 v = *(const float4*)(afp + row * 128 + q * 16);
            uint32_t h0 = hpack(v.x, v.y);
            uint32_t h1 = hpack(v.z, v.w);
            uint32_t off = SWZ(row * 64 + (q & 6) * 8) + (q & 1) * 8;
            *(uint2*)(ahp + off) = make_uint2(h0, h1);
        }
    };

    const int a_row = wm * 32 + (lane & 15);
    const int a_chb = lane >> 4;
    const int b_row = wn * 64 + ((lane >> 4) & 1) * 8 + (lane & 7);
    const int b_chb = (lane >> 3) & 1;

    load_tile(0); cp_commit();
    if (NC > 1) { load_tile(1); cp_commit(); }
    cp_wait<1>();
    convert(0);

    for (int c = 0; c < NC; c++) {
        __syncthreads();

        const uint32_t aH = sb + 32768 + (c & 1) * 8192;
        const uint32_t bB = sb + 49152 + (c % 3) * 8192;
#pragma unroll
        for (int ks = 0; ks < 2; ks++) {
            uint32_t ah[2][4];
#pragma unroll
            for (int mf = 0; mf < 2; mf++) {
                uint32_t off = SWZ((a_row + mf * 16) * 64 + (ks * 2 + a_chb) * 16);
                ldsm4(ah[mf], aH + off);
            }
            uint32_t bh[4][4];
#pragma unroll
            for (int p = 0; p < 4; p++) {
                uint32_t off = SWZ((b_row + p * 16) * 64 + (ks * 2 + b_chb) * 16);
                ldsm4(bh[p], bB + off);
            }
#pragma unroll
            for (int mf = 0; mf < 2; mf++)
#pragma unroll
                for (int p = 0; p < 4; p++) {
                    mma16816h(acc[mf][2 * p],     ah[mf], bh[p][0], bh[p][1]);
                    mma16816h(acc[mf][2 * p + 1], ah[mf], bh[p][2], bh[p][3]);
                }
        }

        if (c + 1 < NC) {
            cp_wait<0>();
            convert(c + 1);
        }
        if (c + 2 < NC) {
            load_tile(c + 2);
            cp_commit();
        }
    }

    // ---- epilogue: store C (fp16) + fused es/ed ----
    const int head = blockIdx.x * 2 + wn;
    const float* asrc = a_src + head * 64;
    const float* adst = a_dst + head * 64;
#pragma unroll
    for (int mf = 0; mf < 2; mf++) {
        int r0 = bm0 + wm * 32 + mf * 16 + (lane >> 2);
        float ps0 = 0.f, ps8 = 0.f, pd0 = 0.f, pd8 = 0.f;
#pragma unroll
        for (int nf = 0; nf < 8; nf++) {
            int col = bn0 + wn * 64 + nf * 8 + (lane & 3) * 2;
            if (r0 < M)
                *(uint32_t*)(C + (size_t)r0 * 256 + col) =
                    hpack(acc[mf][nf][0], acc[mf][nf][1]);
            if (r0 + 8 < M)
                *(uint32_t*)(C + (size_t)(r0 + 8) * 256 + col) =
                    hpack(acc[mf][nf][2], acc[mf][nf][3]);
            int ch = nf * 8 + (lane & 3) * 2;
            float2 av = *(const float2*)(asrc + ch);
            float2 dv = *(const float2*)(adst + ch);
            ps0 += acc[mf][nf][0] * av.x + acc[mf][nf][1] * av.y;
            ps8 += acc[mf][nf][2] * av.x + acc[mf][nf][3] * av.y;
            pd0 += acc[mf][nf][0] * dv.x + acc[mf][nf][1] * dv.y;
            pd8 += acc[mf][nf][2] * dv.x + acc[mf][nf][3] * dv.y;
        }
#pragma unroll
        for (int o = 1; o <= 2; o <<= 1) {
            ps0 += __shfl_xor_sync(0xffffffffu, ps0, o);
            ps8 += __shfl_xor_sync(0xffffffffu, ps8, o);
            pd0 += __shfl_xor_sync(0xffffffffu, pd0, o);
            pd8 += __shfl_xor_sync(0xffffffffu, pd8, o);
        }
        if ((lane & 3) == 0) {
            if (r0 < M)     { es[r0 * 4 + head] = ps0; ed[r0 * 4 + head] = pd0; }
            if (r0 + 8 < M) { es[(r0 + 8) * 4 + head] = ps8; ed[(r0 + 8) * 4 + head] = pd8; }
        }
    }
}

// ===========================================================================
// fp16 single-product GEMM, optional fused es/ed epilogue (BN=128 only)
// ===========================================================================
template <int BN, bool FUSE>
__global__ __launch_bounds__(256)
void gemm_h(const __half* __restrict__ A, const __half* __restrict__ B,
            __half* __restrict__ C,
            const float* __restrict__ a_src, const float* __restrict__ a_dst,
            float* __restrict__ es, float* __restrict__ ed,
            int M, int N, int Kp) {
    constexpr int WNCOL = BN / 2;
    constexpr int NFRAG = WNCOL / 8;
    constexpr int NPAIR = NFRAG / 2;
    constexpr int ABYTES = 8192;
    constexpr int BBYTES = BN * 64;
    constexpr int STAGE = ABYTES + BBYTES;

    extern __shared__ char smem[];
    const uint32_t sb = smem_u32(smem);

    const int tid = threadIdx.x;
    const int wid = tid >> 5, lane = tid & 31;
    const int wm = wid & 3, wn = wid >> 2;
    const int bm0 = blockIdx.y * 128;
    const int bn0 = blockIdx.x * BN;

    float acc[2][NFRAG][4];
#pragma unroll
    for (int i = 0; i < 2; i++)
#pragma unroll
        for (int j = 0; j < NFRAG; j++)
#pragma unroll
            for (int k = 0; k < 4; k++) acc[i][j][k] = 0.f;

    const int NC = Kp >> 5;

    auto load_stage = [&](int c, int stg) {
        const uint32_t base = sb + stg * STAGE;
        const size_t koff = (size_t)c * 32;
#pragma unroll
        for (int t = 0; t < 2; t++) {
            int i = tid + t * 256;
            int row = i >> 2, ch = i & 3;
            const __half* src = A + (size_t)(bm0 + row) * Kp + koff + ch * 8;
            cp16(base + SWZ(row * 64 + ch * 16), src);
        }
#pragma unroll
        for (int t = 0; t < BN / 64; t++) {
            int i = tid + t * 256;
            int row = i >> 2, ch = i & 3;
            const __half* src = B + (size_t)(bn0 + row) * Kp + koff + ch * 8;
            cp16(base + ABYTES + SWZ(row * 64 + ch * 16), src);
        }
    };

    const int a_row = wm * 32 + (lane & 15);
    const int a_chb = lane >> 4;
    const int b_row = wn * WNCOL + ((lane >> 4) & 1) * 8 + (lane & 7);
    const int b_chb = (lane >> 3) & 1;

    load_stage(0, 0);
    cp_commit();

    for (int c = 0; c < NC; c++) {
        if (c + 1 < NC) {
            load_stage(c + 1, (c + 1) & 1);
            cp_commit();
            cp_wait<1>();
        } else {
            cp_wait<0>();
        }
        __syncthreads();

        const uint32_t base = sb + (c & 1) * STAGE;
        const uint32_t aB = base, bB = base + ABYTES;

#pragma unroll
        for (int ks = 0; ks < 2; ks++) {
            uint32_t ah[2][4];
#pragma unroll
            for (int mf = 0; mf < 2; mf++) {
                uint32_t off = SWZ((a_row + mf * 16) * 64 + (ks * 2 + a_chb) * 16);
                ldsm4(ah[mf], aB + off);
            }
            uint32_t bh[NPAIR][4];
#pragma unroll
            for (int p = 0; p < NPAIR; p++) {
                uint32_t off = SWZ((b_row + p * 16) * 64 + (ks * 2 + b_chb) * 16);
                ldsm4(bh[p], bB + off);
            }
#pragma unroll
            for (int mf = 0; mf < 2; mf++)
#pragma unroll
                for (int p = 0; p < NPAIR; p++) {
                    mma16816h(acc[mf][2 * p],     ah[mf], bh[p][0], bh[p][1]);
                    mma16816h(acc[mf][2 * p + 1], ah[mf], bh[p][2], bh[p][3]);
                }
        }
        __syncthreads();
    }

#pragma unroll
    for (int mf = 0; mf < 2; mf++) {
        int r0 = bm0 + wm * 32 + mf * 16 + (lane >> 2);
        float ps0 = 0.f, ps8 = 0.f, pd0 = 0.f, pd8 = 0.f;
#pragma unroll
        for (int nf = 0; nf < NFRAG; nf++) {
            int col = bn0 + wn * WNCOL + nf * 8 + (lane & 3) * 2;
            if (r0 < M)
                *(uint32_t*)(C + (size_t)r0 * N + col) =
                    hpack(acc[mf][nf][0], acc[mf][nf][1]);
            if (r0 + 8 < M)
                *(uint32_t*)(C + (size_t)(r0 + 8) * N + col) =
                    hpack(acc[mf][nf][2], acc[mf][nf][3]);
            if (FUSE) {
                const int head = blockIdx.x * 2 + wn;
                int ch = nf * 8 + (lane & 3) * 2;
                float2 av = *(const float2*)(a_src + head * 64 + ch);
                float2 dv = *(const float2*)(a_dst + head * 64 + ch);
                ps0 += acc[mf][nf][0] * av.x + acc[mf][nf][1] * av.y;
                ps8 += acc[mf][nf][2] * av.x + acc[mf][nf][3] * av.y;
                pd0 += acc[mf][nf][0] * dv.x + acc[mf][nf][1] * dv.y;
                pd8 += acc[mf][nf][2] * dv.x + acc[mf][nf][3] * dv.y;
            }
        }
        if (FUSE) {
            const int head = blockIdx.x * 2 + wn;
#pragma unroll
            for (int o = 1; o <= 2; o <<= 1) {
                ps0 += __shfl_xor_sync(0xffffffffu, ps0, o);
                ps8 += __shfl_xor_sync(0xffffffffu, ps8, o);
                pd0 += __shfl_xor_sync(0xffffffffu, pd0, o);
                pd8 += __shfl_xor_sync(0xffffffffu, pd8, o);
            }
            if ((lane & 3) == 0) {
                if (r0 < M)     { es[r0 * 4 + head] = ps0; ed[r0 * 4 + head] = pd0; }
                if (r0 + 8 < M) { es[(r0 + 8) * 4 + head] = ps8; ed[(r0 + 8) * 4 + head] = pd8; }
            }
        }
    }
}

// ===========================================================================
// es/ed logits for layer 3 (one warp per node)
// ===========================================================================
__global__ void es_ed1(const __half* __restrict__ h,
                       const float* __restrict__ a_src,
                       const float* __restrict__ a_dst,
                       float* __restrict__ es, float* __restrict__ ed, int n) {
    int w = (blockIdx.x * blockDim.x + threadIdx.x) >> 5;
    int lane = threadIdx.x & 31;
    if (w >= n) return;
    int c = lane * 2;
    float2 v = h2f(*(const uint32_t*)(h + (size_t)w * 64 + c));
    float2 as = *(const float2*)(a_src + c);
    float2 ad = *(const float2*)(a_dst + c);
    float s = v.x * as.x + v.y * as.y;
    float d = v.x * ad.x + v.y * ad.y;
#pragma unroll
    for (int o = 16; o; o >>= 1) {
        s += __shfl_xor_sync(0xffffffffu, s, o);
        d += __shfl_xor_sync(0xffffffffu, d, o);
    }
    if (lane == 0) { es[w] = s; ed[w] = d; }
}

// ===========================================================================
// agg_gather4: one warp per dst node, fp16 gather, fp32 accumulate,
// fused normalize/bias/ELU/fp16-convert -> next GEMM A operand.
// ===========================================================================
__global__ void agg_gather4(const int* __restrict__ rowoff, const int* __restrict__ csrsrc,
                            const float* __restrict__ es, const float* __restrict__ ed,
                            const __half* __restrict__ h, const float* __restrict__ b,
                            __half* __restrict__ Hf, int n, int Mp) {
    int w = (blockIdx.x * blockDim.x + threadIdx.x) >> 5;
    int lane = threadIdx.x & 31;
    if (w >= Mp) return;
    const int c0 = lane * 4;
    if (w >= n) {
        *(uint2*)(Hf + (size_t)w * 256 + c0) = make_uint2(0, 0);
        *(uint2*)(Hf + (size_t)w * 256 + c0 + 128) = make_uint2(0, 0);
        return;
    }
    const int myh = lane & 3;
    const int hs = (lane >> 4) & 1;
    float4 ed4 = *(const float4*)(ed + w * 4);
    float edh = sel4(ed4, myh);

    float4 es4 = *(const float4*)(es + w * 4);
    float e = sel4(es4, myh) + edh;
    e = e > 0.f ? e : 0.2f * e;
    float wv = __expf(e);
    float den = wv;
    float al0 = __shfl_sync(0xffffffffu, wv, hs);
    float al1 = __shfl_sync(0xffffffffu, wv, 2 + hs);

    const __half* hp = h + (size_t)w * 256;
    uint2 r0v = *(const uint2*)(hp + c0);
    uint2 r1v = *(const uint2*)(hp + c0 + 128);
    float2 g0 = h2f(r0v.x), g1 = h2f(r0v.y), g2 = h2f(r1v.x), g3 = h2f(r1v.y);
    float4 a0 = make_float4(g0.x * al0, g0.y * al0, g1.x * al0, g1.y * al0);
    float4 a1 = make_float4(g2.x * al1, g2.y * al1, g3.x * al1, g3.y * al1);

    int j0 = rowoff[w], j1 = rowoff[w + 1];
    int s = (j0 < j1) ? csrsrc[j0] : 0;
    for (int j = j0; j < j1; j++) {
        int snext = (j + 1 < j1) ? csrsrc[j + 1] : 0;
        float4 e4 = *(const float4*)(es + s * 4);
        float ee = sel4(e4, myh) + edh;
        ee = ee > 0.f ? ee : 0.2f * ee;
        float wj = __expf(ee);
        den += wj;
        float b0 = __shfl_sync(0xffffffffu, wj, hs);
        float b1 = __shfl_sync(0xffffffffu, wj, 2 + hs);
        const __half* sp = h + (size_t)s * 256;
        uint2 v0 = *(const uint2*)(sp + c0);
        uint2 v1 = *(const uint2*)(sp + c0 + 128);
        float2 p0 = h2f(v0.x), p1 = h2f(v0.y), p2 = h2f(v1.x), p3 = h2f(v1.y);
        a0.x += b0 * p0.x; a0.y += b0 * p0.y; a0.z += b0 * p1.x; a0.w += b0 * p1.y;
        a1.x += b1 * p2.x; a1.y += b1 * p2.y; a1.z += b1 * p3.x; a1.w += b1 * p3.y;
        s = snext;
    }
    float inv0 = __fdividef(1.f, __shfl_sync(0xffffffffu, den, hs));
    float inv1 = __fdividef(1.f, __shfl_sync(0xffffffffu, den, 2 + hs));

    float4 bb0 = *(const float4*)(b + c0);
    float4 bb1 = *(const float4*)(b + c0 + 128);
    float f0[4] = {a0.x * inv0 + bb0.x, a0.y * inv0 + bb0.y,
                   a0.z * inv0 + bb0.z, a0.w * inv0 + bb0.w};
    float f1[4] = {a1.x * inv1 + bb1.x, a1.y * inv1 + bb1.y,
                   a1.z * inv1 + bb1.z, a1.w * inv1 + bb1.w};
#pragma unroll
    for (int k = 0; k < 4; k++) {
        f0[k] = f0[k] > 0.f ? f0[k] : expm1f(f0[k]);
        f1[k] = f1[k] > 0.f ? f1[k] : expm1f(f1[k]);
    }
    size_t o = (size_t)w * 256 + c0;
    *(uint2*)(Hf + o)       = make_uint2(hpack(f0[0], f0[1]), hpack(f0[2], f0[3]));
    *(uint2*)(Hf + o + 128) = make_uint2(hpack(f1[0], f1[1]), hpack(f1[2], f1[3]));
}

// ===========================================================================
// agg_gather1 + classifier
// ===========================================================================
__global__ void agg_gather1(const int* __restrict__ rowoff, const int* __restrict__ csrsrc,
                            const float* __restrict__ es, const float* __restrict__ ed,
                            const __half* __restrict__ h, const float* __restrict__ b3,
                            const float* __restrict__ Wc, const float* __restrict__ bc,
                            float* __restrict__ out, int n) {
    int w = (blockIdx.x * blockDim.x + threadIdx.x) >> 5;
    int lane = threadIdx.x & 31;
    if (w >= n) return;
    float edw = ed[w];
    float e = es[w] + edw;
    e = e > 0.f ? e : 0.2f * e;
    float wv = __expf(e);
    float den = wv;
    float2 hv = h2f(*(const uint32_t*)(h + (size_t)w * 64 + lane * 2));
    float v0 = hv.x * wv;
    float v1 = hv.y * wv;

    int j0 = rowoff[w], j1 = rowoff[w + 1];
    int s = (j0 < j1) ? csrsrc[j0] : 0;
    for (int j = j0; j < j1; j++) {
        int snext = (j + 1 < j1) ? csrsrc[j + 1] : 0;
        float ee = es[s] + edw;
        ee = ee > 0.f ? ee : 0.2f * ee;
        float wj = __expf(ee);
        den += wj;
        float2 sv = h2f(*(const uint32_t*)(h + (size_t)s * 64 + lane * 2));
        v0 += wj * sv.x;
        v1 += wj * sv.y;
        s = snext;
    }
    float inv = __fdividef(1.f, den);
    v0 = v0 * inv + b3[lane * 2];
    v0 = v0 > 0.f ? v0 : expm1f(v0);
    v1 = v1 * inv + b3[lane * 2 + 1];
    v1 = v1 > 0.f ? v1 : expm1f(v1);
#pragma unroll
    for (int j = 0; j < 3; j++) {
        float p = v0 * Wc[(lane * 2) * 3 + j] + v1 * Wc[(lane * 2 + 1) * 3 + j];
#pragma unroll
        for (int o = 16; o; o >>= 1) p += __shfl_xor_sync(0xffffffffu, p, o);
        if (lane == 0) out[w * 3 + j] = p + bc[j];
    }
}

// ===========================================================================
// W [K,N] fp32 -> fp16 [N,Kp] via 32x32 smem transpose (coalesced both sides)
// grid: (cdiv(Kp,32), cdiv(N,32)), block (32,8)
// ===========================================================================
__global__ void conv_wT_h(const float* __restrict__ W,
                          __half* __restrict__ Bh, int K, int N, int Kp) {
    __shared__ float tile[32][33];
    const int kb = blockIdx.x * 32, nb = blockIdx.y * 32;
    const int tx = threadIdx.x, ty = threadIdx.y;
#pragma unroll
    for (int j = 0; j < 4; j++) {
        int k = kb + ty + j * 8, nn = nb + tx;
        tile[ty + j * 8][tx] = (k < K && nn < N) ? W[(size_t)k * N + nn] : 0.f;
    }
    __syncthreads();
#pragma unroll
    for (int j = 0; j < 4; j++) {
        int nn = nb + ty + j * 8, k = kb + tx;
        if (nn < N && k < Kp)
            Bh[(size_t)nn * Kp + k] = __float2half_rn(tile[tx][ty + j * 8]);
    }
}

// ===========================================================================
static inline int cdiv(int a, int b) { return (a + b - 1) / b; }

extern "C" void kernel_launch(void* const* d_in, const int* in_sizes, int n_in,
                              void* d_out, int out_size) {
    const float* x    = (const float*)d_in[0];
    const float* W1   = (const float*)d_in[1];
    const float* a1s  = (const float*)d_in[2];
    const float* a1d  = (const float*)d_in[3];
    const float* b1   = (const float*)d_in[4];
    const float* W2   = (const float*)d_in[5];
    const float* a2s  = (const float*)d_in[6];
    const float* a2d  = (const float*)d_in[7];
    const float* b2   = (const float*)d_in[8];
    const float* W3   = (const float*)d_in[9];
    const float* a3s  = (const float*)d_in[10];
    const float* a3d  = (const float*)d_in[11];
    const float* b3   = (const float*)d_in[12];
    const float* Wc   = (const float*)d_in[13];
    const float* bc   = (const float*)d_in[14];
    const int*   ei   = (const int*)d_in[15];
    float* out = (float*)d_out;

    const int N = GAT_N, E = GAT_E, Mp = GAT_Mp;
    const int* src = ei;
    const int* dst = ei + E;

    float *es, *ed;
    int *rowoff, *cursor, *csrsrc;
    __half *hAh, *h3h, *Afp, *W1hp, *W2hp, *W3hp;
    cudaGetSymbolAddress((void**)&hAh,    g_hA);
    cudaGetSymbolAddress((void**)&h3h,    g_h3);
    cudaGetSymbolAddress((void**)&es,     g_es);
    cudaGetSymbolAddress((void**)&ed,     g_ed);
    cudaGetSymbolAddress((void**)&rowoff, g_rowoff);
    cudaGetSymbolAddress((void**)&cursor, g_cursor);
    cudaGetSymbolAddress((void**)&csrsrc, g_csrsrc);
    cudaGetSymbolAddress((void**)&Afp,    g_Af);
    cudaGetSymbolAddress((void**)&W1hp,   g_W1h);
    cudaGetSymbolAddress((void**)&W2hp,   g_W2h);
    cudaGetSymbolAddress((void**)&W3hp,   g_W3h);

    const int SMF   = 73728;
    const int SM128 = 2 * (8192 + 128 * 64);
    const int SM64  = 2 * (8192 + 64 * 64);
    cudaFuncSetAttribute(gemm_fused, cudaFuncAttributeMaxDynamicSharedMemorySize, SMF);
    cudaFuncSetAttribute(gemm_h<128, true>,
                         cudaFuncAttributeMaxDynamicSharedMemorySize, SM128);
    cudaFuncSetAttribute(gemm_h<64, false>,
                         cudaFuncAttributeMaxDynamicSharedMemorySize, SM64);

    const int TB = 256;
    const int MT = Mp / 128;               // 235
    const int NPB = cdiv(N * 32, TB);
    const int GPB = cdiv(Mp * 32, TB);

    // ---------------- CSR build ----------------
    csr_zero<<<cdiv(N, TB), TB>>>(cursor, N);
    csr_hist<<<cdiv(E, TB), TB>>>(dst, cursor, E);
    csr_scan<<<1, 1024>>>(cursor, rowoff, N);
    csr_fill<<<cdiv(E, TB), TB>>>(src, dst, cursor, csrsrc, E);

    // ---------------- layer 1 (H=4, K=5000) ----------------
    conv_wT_h<<<dim3(cdiv(GAT_K1P, 32), 8), dim3(32, 8)>>>(W1, W1hp, GAT_DIN, 256, GAT_K1P);
    gemm_fused<<<dim3(2, MT), 256, SMF>>>(x, W1hp, hAh, a1s, a1d, es, ed,
                                          N, GAT_DIN, GAT_K1P);
    agg_gather4<<<GPB, TB>>>(rowoff, csrsrc, es, ed, hAh, b1, Afp, N, Mp);

    // ---------------- layer 2 (H=4, K=256) ----------------
    conv_wT_h<<<dim3(8, 8), dim3(32, 8)>>>(W2, W2hp, 256, 256, 256);
    gemm_h<128, true><<<dim3(2, MT), 256, SM128>>>(Afp, W2hp, hAh, a2s, a2d, es, ed,
                                                   N, 256, 256);
    agg_gather4<<<GPB, TB>>>(rowoff, csrsrc, es, ed, hAh, b2, Afp, N, Mp);

    // ---------------- layer 3 (H=1, K=256, N=64) ----------------
    conv_wT_h<<<dim3(8, 2), dim3(32, 8)>>>(W3, W3hp, 256, 64, 256);
    gemm_h<64, false><<<dim3(1, MT), 256, SM64>>>(Afp, W3hp, h3h,
                                                  nullptr, nullptr, nullptr, nullptr,
                                                  N, 64, 256);
    es_ed1<<<NPB, TB>>>(h3h, a3s, a3d, es, ed, N);
    agg_gather1<<<NPB, TB>>>(rowoff, csrsrc, es, ed, h3h, b3, Wc, bc, out, N);
}

// round 17
// speedup vs baseline: 2.2025x; 1.0041x over previous
#include <cuda_runtime.h>
#include <cuda_bf16.h>
#include <cuda_fp16.h>
#include <cstdint>

// ---------------------------------------------------------------------------
// SentimentGAT on GB300 (sm_103 baseline PTX):
//  fp16 single-product mma.sync GEMMs with fused es/ed logit epilogues,
//  fp16 feature maps; CSR-gather attention w/ software-pipelined edge loop.
// ---------------------------------------------------------------------------

#define GAT_N   30000
#define GAT_Mp  30080               // 235 * 128
#define GAT_E   480000
#define GAT_DIN 5000
#define GAT_K1P 5056                // 79 * 64 (padded K stride for W1^T)

// ---- scratch ----
__device__ __align__(128) __half g_hA[(size_t)GAT_N * 256];
__device__ __align__(128) __half g_h3[GAT_N * 64];
__device__ float g_es[GAT_N * 4];
__device__ float g_ed[GAT_N * 4];

// ---- CSR ----
__device__ int g_rowoff[GAT_N + 1];
__device__ int g_cursor[GAT_N];
__device__ int g_csrsrc[GAT_E];

// ---- fp16 GEMM operands ----
__device__ __align__(128) __half g_Af[(size_t)GAT_Mp * 256];
__device__ __align__(128) __half g_W1h[256 * GAT_K1P];
__device__ __align__(128) __half g_W2h[256 * 256];
__device__ __align__(128) __half g_W3h[64 * 256];

// ===========================================================================
// low-level helpers
// ===========================================================================
#define SWZ(o) ((o) ^ (((o) >> 3) & 0x70))

__device__ __forceinline__ uint32_t smem_u32(const void* p) {
    uint32_t a;
    asm("{ .reg .u64 t; cvta.to.shared.u64 t, %1; cvt.u32.u64 %0, t; }"
        : "=r"(a) : "l"(p));
    return a;
}
__device__ __forceinline__ void cp16(uint32_t d, const void* s) {
    asm volatile("cp.async.cg.shared.global [%0], [%1], 16;" :: "r"(d), "l"(s));
}
__device__ __forceinline__ void cp16z(uint32_t d, const void* s, bool pred) {
    int sz = pred ? 16 : 0;
    asm volatile("cp.async.cg.shared.global [%0], [%1], 16, %2;"
                 :: "r"(d), "l"(s), "r"(sz));
}
__device__ __forceinline__ void cp_commit() {
    asm volatile("cp.async.commit_group;" ::: "memory");
}
template <int Ng>
__device__ __forceinline__ void cp_wait() {
    asm volatile("cp.async.wait_group %0;" :: "n"(Ng) : "memory");
}
__device__ __forceinline__ void ldsm4(uint32_t (&r)[4], uint32_t addr) {
    asm volatile("ldmatrix.sync.aligned.m8n8.x4.shared.b16 {%0,%1,%2,%3}, [%4];"
                 : "=r"(r[0]), "=r"(r[1]), "=r"(r[2]), "=r"(r[3]) : "r"(addr));
}
__device__ __forceinline__ void mma16816h(float (&d)[4], const uint32_t (&a)[4],
                                          uint32_t b0, uint32_t b1) {
    asm volatile("mma.sync.aligned.m16n8k16.row.col.f32.f16.f16.f32 "
                 "{%0,%1,%2,%3}, {%4,%5,%6,%7}, {%8,%9}, {%0,%1,%2,%3};"
                 : "+f"(d[0]), "+f"(d[1]), "+f"(d[2]), "+f"(d[3])
                 : "r"(a[0]), "r"(a[1]), "r"(a[2]), "r"(a[3]), "r"(b0), "r"(b1));
}
__device__ __forceinline__ uint32_t hpack(float a, float b) {
    return (uint32_t)__half_as_ushort(__float2half_rn(a)) |
           ((uint32_t)__half_as_ushort(__float2half_rn(b)) << 16);
}
__device__ __forceinline__ float2 h2f(uint32_t u) {
    return __half22float2(*(__half2*)&u);
}
__device__ __forceinline__ float sel4(float4 v, int i) {
    float a = (i & 1) ? v.y : v.x;
    float b = (i & 1) ? v.w : v.z;
    return (i & 2) ? b : a;
}

// ===========================================================================
// CSR build (vectorized: 4 elems/thread)
// ===========================================================================
__global__ void csr_zero(int4* cur, int n4) {
    int i = blockIdx.x * blockDim.x + threadIdx.x;
    if (i < n4) cur[i] = make_int4(0, 0, 0, 0);
}
__global__ void csr_hist(const int* __restrict__ dst, int* cur, int E_) {
    int i = (blockIdx.x * blockDim.x + threadIdx.x) * 4;
    if (i >= E_) return;
    int4 d = *(const int4*)(dst + i);   // E_ % 4 == 0
    atomicAdd(&cur[d.x], 1);
    atomicAdd(&cur[d.y], 1);
    atomicAdd(&cur[d.z], 1);
    atomicAdd(&cur[d.w], 1);
}
// shuffle-based block scan (1024 threads, 3 barriers per chunk)
__global__ void csr_scan(int* degcur, int* rowoff, int n) {
    __shared__ int wsum[32];
    __shared__ int carry_s;
    const int tid = threadIdx.x;
    const int lane = tid & 31, wid = tid >> 5;
    if (tid == 0) carry_s = 0;
    __syncthreads();
    for (int base = 0; base < n; base += 1024) {
        int i = base + tid;
        int v = (i < n) ? degcur[i] : 0;
        int x = v;
#pragma unroll
        for (int o = 1; o < 32; o <<= 1) {
            int t = __shfl_up_sync(0xffffffffu, x, o);
            if (lane >= o) x += t;
        }
        if (lane == 31) wsum[wid] = x;
        __syncthreads();
        if (wid == 0) {
            int y = wsum[lane];
#pragma unroll
            for (int o = 1; o < 32; o <<= 1) {
                int t = __shfl_up_sync(0xffffffffu, y, o);
                if (lane >= o) y += t;
            }
            wsum[lane] = y;
        }
        __syncthreads();
        int woff = (wid > 0) ? wsum[wid - 1] : 0;
        int incl = x + woff + carry_s;
        int excl = incl - v;
        if (i < n) { rowoff[i] = excl; degcur[i] = excl; }
        __syncthreads();
        if (tid == 1023) carry_s = incl;
        __syncthreads();
    }
    if (tid == 0) rowoff[n] = carry_s;
}
__global__ void csr_fill(const int* __restrict__ src, const int* __restrict__ dst,
                         int* cur, int* csrsrc, int E_) {
    int i = (blockIdx.x * blockDim.x + threadIdx.x) * 4;
    if (i >= E_) return;
    int4 s = *(const int4*)(src + i);
    int4 d = *(const int4*)(dst + i);
    csrsrc[atomicAdd(&cur[d.x], 1)] = s.x;
    csrsrc[atomicAdd(&cur[d.y], 1)] = s.y;
    csrsrc[atomicAdd(&cur[d.z], 1)] = s.z;
    csrsrc[atomicAdd(&cur[d.w], 1)] = s.w;
}

// ===========================================================================
// FUSED layer-1 GEMM + es/ed epilogue (R16-proven)
// ===========================================================================
__global__ __launch_bounds__(256)
void gemm_fused(const float* __restrict__ X, const __half* __restrict__ Bh,
                __half* __restrict__ C,
                const float* __restrict__ a_src, const float* __restrict__ a_dst,
                float* __restrict__ es, float* __restrict__ ed,
                int M, int K, int KpB) {
    extern __shared__ char smem[];
    const uint32_t sb = smem_u32(smem);

    const int tid = threadIdx.x;
    const int wid = tid >> 5, lane = tid & 31;
    const int wm = wid & 3, wn = wid >> 2;
    const int bm0 = blockIdx.y * 128;
    const int bn0 = blockIdx.x * 128;

    float acc[2][8][4];
#pragma unroll
    for (int i = 0; i < 2; i++)
#pragma unroll
        for (int j = 0; j < 8; j++)
#pragma unroll
            for (int k = 0; k < 4; k++) acc[i][j][k] = 0.f;

    const int NC = (K + 31) >> 5;

    auto load_tile = [&](int c) {
        const uint32_t af = sb + (c & 1) * 16384;
        const uint32_t bb = sb + 49152 + (c % 3) * 8192;
        const int k0 = c * 32;
#pragma unroll
        for (int t = 0; t < 4; t++) {
            int i = tid + t * 256;
            int row = i >> 3, q = i & 7;
            int gm = bm0 + row, gk = k0 + q * 4;
            bool p = (gm < M) && (gk < K);
            cp16z(af + row * 128 + q * 16, X + (p ? ((size_t)gm * K + gk) : 0), p);
        }
#pragma unroll
        for (int t = 0; t < 2; t++) {
            int i = tid + t * 256;
            int row = i >> 2, ch = i & 3;
            const __half* src = Bh + (size_t)(bn0 + row) * KpB + k0 + ch * 8;
            cp16(bb + SWZ(row * 64 + ch * 16), src);
        }
    };

    auto convert = [&](int c) {
        const int s2 = c & 1;
        const char* afp = smem + s2 * 16384;
        char* ahp = smem + 32768 + s2 * 8192;
#pragma unroll
        for (int t = 0; t < 4; t++) {
            int i = tid + t * 256;
            int row = i >> 3, q = i & 7;
            float4 v = *(const float4*)(afp + row * 128 + q * 16);
            uint32_t h0 = hpack(v.x, v.y);
            uint32_t h1 = hpack(v.z, v.w);
            uint32_t off = SWZ(row * 64 + (q & 6) * 8) + (q & 1) * 8;
            *(uint2*)(ahp + off) = make_uint2(h0, h1);
        }
    };

    const int a_row = wm * 32 + (lane & 15);
    const int a_chb = lane >> 4;
    const int b_row = wn * 64 + ((lane >> 4) & 1) * 8 + (lane & 7);
    const int b_chb = (lane >> 3) & 1;

    load_tile(0); cp_commit();
    if (NC > 1) { load_tile(1); cp_commit(); }
    cp_wait<1>();
    convert(0);

    for (int c = 0; c < NC; c++) {
        __syncthreads();

        const uint32_t aH = sb + 32768 + (c & 1) * 8192;
        const uint32_t bB = sb + 49152 + (c % 3) * 8192;
#pragma unroll
        for (int ks = 0; ks < 2; ks++) {
            uint32_t ah[2][4];
#pragma unroll
            for (int mf = 0; mf < 2; mf++) {
                uint32_t off = SWZ((a_row + mf * 16) * 64 + (ks * 2 + a_chb) * 16);
                ldsm4(ah[mf], aH + off);
            }
            uint32_t bh[4][4];
#pragma unroll
            for (int p = 0; p < 4; p++) {
                uint32_t off = SWZ((b_row + p * 16) * 64 + (ks * 2 + b_chb) * 16);
                ldsm4(bh[p], bB + off);
            }
#pragma unroll
            for (int mf = 0; mf < 2; mf++)
#pragma unroll
                for (int p = 0; p < 4; p++) {
                    mma16816h(acc[mf][2 * p],     ah[mf], bh[p][0], bh[p][1]);
                    mma16816h(acc[mf][2 * p + 1], ah[mf], bh[p][2], bh[p][3]);
                }
        }

        if (c + 1 < NC) {
            cp_wait<0>();
            convert(c + 1);
        }
        if (c + 2 < NC) {
            load_tile(c + 2);
            cp_commit();
        }
    }

    const int head = blockIdx.x * 2 + wn;
    const float* asrc = a_src + head * 64;
    const float* adst = a_dst + head * 64;
#pragma unroll
    for (int mf = 0; mf < 2; mf++) {
        int r0 = bm0 + wm * 32 + mf * 16 + (lane >> 2);
        float ps0 = 0.f, ps8 = 0.f, pd0 = 0.f, pd8 = 0.f;
#pragma unroll
        for (int nf = 0; nf < 8; nf++) {
            int col = bn0 + wn * 64 + nf * 8 + (lane & 3) * 2;
            if (r0 < M)
                *(uint32_t*)(C + (size_t)r0 * 256 + col) =
                    hpack(acc[mf][nf][0], acc[mf][nf][1]);
            if (r0 + 8 < M)
                *(uint32_t*)(C + (size_t)(r0 + 8) * 256 + col) =
                    hpack(acc[mf][nf][2], acc[mf][nf][3]);
            int ch = nf * 8 + (lane & 3) * 2;
            float2 av = *(const float2*)(asrc + ch);
            float2 dv = *(const float2*)(adst + ch);
            ps0 += acc[mf][nf][0] * av.x + acc[mf][nf][1] * av.y;
            ps8 += acc[mf][nf][2] * av.x + acc[mf][nf][3] * av.y;
            pd0 += acc[mf][nf][0] * dv.x + acc[mf][nf][1] * dv.y;
            pd8 += acc[mf][nf][2] * dv.x + acc[mf][nf][3] * dv.y;
        }
#pragma unroll
        for (int o = 1; o <= 2; o <<= 1) {
            ps0 += __shfl_xor_sync(0xffffffffu, ps0, o);
            ps8 += __shfl_xor_sync(0xffffffffu, ps8, o);
            pd0 += __shfl_xor_sync(0xffffffffu, pd0, o);
            pd8 += __shfl_xor_sync(0xffffffffu, pd8, o);
        }
        if ((lane & 3) == 0) {
            if (r0 < M)     { es[r0 * 4 + head] = ps0; ed[r0 * 4 + head] = pd0; }
            if (r0 + 8 < M) { es[(r0 + 8) * 4 + head] = ps8; ed[(r0 + 8) * 4 + head] = pd8; }
        }
    }
}

// ===========================================================================
// fp16 single-product GEMM, optional fused es/ed epilogue (R16-proven)
// ===========================================================================
template <int BN, bool FUSE>
__global__ __launch_bounds__(256)
void gemm_h(const __half* __restrict__ A, const __half* __restrict__ B,
            __half* __restrict__ C,
            const float* __restrict__ a_src, const float* __restrict__ a_dst,
            float* __restrict__ es, float* __restrict__ ed,
            int M, int N, int Kp) {
    constexpr int WNCOL = BN / 2;
    constexpr int NFRAG = WNCOL / 8;
    constexpr int NPAIR = NFRAG / 2;
    constexpr int ABYTES = 8192;
    constexpr int BBYTES = BN * 64;
    constexpr int STAGE = ABYTES + BBYTES;

    extern __shared__ char smem[];
    const uint32_t sb = smem_u32(smem);

    const int tid = threadIdx.x;
    const int wid = tid >> 5, lane = tid & 31;
    const int wm = wid & 3, wn = wid >> 2;
    const int bm0 = blockIdx.y * 128;
    const int bn0 = blockIdx.x * BN;

    float acc[2][NFRAG][4];
#pragma unroll
    for (int i = 0; i < 2; i++)
#pragma unroll
        for (int j = 0; j < NFRAG; j++)
#pragma unroll
            for (int k = 0; k < 4; k++) acc[i][j][k] = 0.f;

    const int NC = Kp >> 5;

    auto load_stage = [&](int c, int stg) {
        const uint32_t base = sb + stg * STAGE;
        const size_t koff = (size_t)c * 32;
#pragma unroll
        for (int t = 0; t < 2; t++) {
            int i = tid + t * 256;
            int row = i >> 2, ch = i & 3;
            const __half* src = A + (size_t)(bm0 + row) * Kp + koff + ch * 8;
            cp16(base + SWZ(row * 64 + ch * 16), src);
        }
#pragma unroll
        for (int t = 0; t < BN / 64; t++) {
            int i = tid + t * 256;
            int row = i >> 2, ch = i & 3;
            const __half* src = B + (size_t)(bn0 + row) * Kp + koff + ch * 8;
            cp16(base + ABYTES + SWZ(row * 64 + ch * 16), src);
        }
    };

    const int a_row = wm * 32 + (lane & 15);
    const int a_chb = lane >> 4;
    const int b_row = wn * WNCOL + ((lane >> 4) & 1) * 8 + (lane & 7);
    const int b_chb = (lane >> 3) & 1;

    load_stage(0, 0);
    cp_commit();

    for (int c = 0; c < NC; c++) {
        if (c + 1 < NC) {
            load_stage(c + 1, (c + 1) & 1);
            cp_commit();
            cp_wait<1>();
        } else {
            cp_wait<0>();
        }
        __syncthreads();

        const uint32_t base = sb + (c & 1) * STAGE;
        const uint32_t aB = base, bB = base + ABYTES;

#pragma unroll
        for (int ks = 0; ks < 2; ks++) {
            uint32_t ah[2][4];
#pragma unroll
            for (int mf = 0; mf < 2; mf++) {
                uint32_t off = SWZ((a_row + mf * 16) * 64 + (ks * 2 + a_chb) * 16);
                ldsm4(ah[mf], aB + off);
            }
            uint32_t bh[NPAIR][4];
#pragma unroll
            for (int p = 0; p < NPAIR; p++) {
                uint32_t off = SWZ((b_row + p * 16) * 64 + (ks * 2 + b_chb) * 16);
                ldsm4(bh[p], bB + off);
            }
#pragma unroll
            for (int mf = 0; mf < 2; mf++)
#pragma unroll
                for (int p = 0; p < NPAIR; p++) {
                    mma16816h(acc[mf][2 * p],     ah[mf], bh[p][0], bh[p][1]);
                    mma16816h(acc[mf][2 * p + 1], ah[mf], bh[p][2], bh[p][3]);
                }
        }
        __syncthreads();
    }

#pragma unroll
    for (int mf = 0; mf < 2; mf++) {
        int r0 = bm0 + wm * 32 + mf * 16 + (lane >> 2);
        float ps0 = 0.f, ps8 = 0.f, pd0 = 0.f, pd8 = 0.f;
#pragma unroll
        for (int nf = 0; nf < NFRAG; nf++) {
            int col = bn0 + wn * WNCOL + nf * 8 + (lane & 3) * 2;
            if (r0 < M)
                *(uint32_t*)(C + (size_t)r0 * N + col) =
                    hpack(acc[mf][nf][0], acc[mf][nf][1]);
            if (r0 + 8 < M)
                *(uint32_t*)(C + (size_t)(r0 + 8) * N + col) =
                    hpack(acc[mf][nf][2], acc[mf][nf][3]);
            if (FUSE) {
                const int head = blockIdx.x * 2 + wn;
                int ch = nf * 8 + (lane & 3) * 2;
                float2 av = *(const float2*)(a_src + head * 64 + ch);
                float2 dv = *(const float2*)(a_dst + head * 64 + ch);
                ps0 += acc[mf][nf][0] * av.x + acc[mf][nf][1] * av.y;
                ps8 += acc[mf][nf][2] * av.x + acc[mf][nf][3] * av.y;
                pd0 += acc[mf][nf][0] * dv.x + acc[mf][nf][1] * dv.y;
                pd8 += acc[mf][nf][2] * dv.x + acc[mf][nf][3] * dv.y;
            }
        }
        if (FUSE) {
            const int head = blockIdx.x * 2 + wn;
#pragma unroll
            for (int o = 1; o <= 2; o <<= 1) {
                ps0 += __shfl_xor_sync(0xffffffffu, ps0, o);
                ps8 += __shfl_xor_sync(0xffffffffu, ps8, o);
                pd0 += __shfl_xor_sync(0xffffffffu, pd0, o);
                pd8 += __shfl_xor_sync(0xffffffffu, pd8, o);
            }
            if ((lane & 3) == 0) {
                if (r0 < M)     { es[r0 * 4 + head] = ps0; ed[r0 * 4 + head] = pd0; }
                if (r0 + 8 < M) { es[(r0 + 8) * 4 + head] = ps8; ed[(r0 + 8) * 4 + head] = pd8; }
            }
        }
    }
}

// ===========================================================================
// es/ed logits for layer 3 (one warp per node)
// ===========================================================================
__global__ void es_ed1(const __half* __restrict__ h,
                       const float* __restrict__ a_src,
                       const float* __restrict__ a_dst,
                       float* __restrict__ es, float* __restrict__ ed, int n) {
    int w = (blockIdx.x * blockDim.x + threadIdx.x) >> 5;
    int lane = threadIdx.x & 31;
    if (w >= n) return;
    int c = lane * 2;
    float2 v = h2f(*(const uint32_t*)(h + (size_t)w * 64 + c));
    float2 as = *(const float2*)(a_src + c);
    float2 ad = *(const float2*)(a_dst + c);
    float s = v.x * as.x + v.y * as.y;
    float d = v.x * ad.x + v.y * ad.y;
#pragma unroll
    for (int o = 16; o; o >>= 1) {
        s += __shfl_xor_sync(0xffffffffu, s, o);
        d += __shfl_xor_sync(0xffffffffu, d, o);
    }
    if (lane == 0) { es[w] = s; ed[w] = d; }
}

// ===========================================================================
// agg_gather4: one warp per dst node, depth-1 software-pipelined edge loop,
// fused normalize/bias/ELU/fp16-convert.
// ===========================================================================
__global__ void agg_gather4(const int* __restrict__ rowoff, const int* __restrict__ csrsrc,
                            const float* __restrict__ es, const float* __restrict__ ed,
                            const __half* __restrict__ h, const float* __restrict__ b,
                            __half* __restrict__ Hf, int n, int Mp) {
    int w = (blockIdx.x * blockDim.x + threadIdx.x) >> 5;
    int lane = threadIdx.x & 31;
    if (w >= Mp) return;
    const int c0 = lane * 4;
    if (w >= n) {
        *(uint2*)(Hf + (size_t)w * 256 + c0) = make_uint2(0, 0);
        *(uint2*)(Hf + (size_t)w * 256 + c0 + 128) = make_uint2(0, 0);
        return;
    }
    const int myh = lane & 3;
    const int hs = (lane >> 4) & 1;
    float4 ed4 = *(const float4*)(ed + w * 4);
    float edh = sel4(ed4, myh);

    float4 es4 = *(const float4*)(es + w * 4);
    float e = sel4(es4, myh) + edh;
    e = e > 0.f ? e : 0.2f * e;
    float wv = __expf(e);
    float den = wv;
    float al0 = __shfl_sync(0xffffffffu, wv, hs);
    float al1 = __shfl_sync(0xffffffffu, wv, 2 + hs);

    const __half* hp = h + (size_t)w * 256;
    uint2 r0v = *(const uint2*)(hp + c0);
    uint2 r1v = *(const uint2*)(hp + c0 + 128);
    float2 g0 = h2f(r0v.x), g1 = h2f(r0v.y), g2 = h2f(r1v.x), g3 = h2f(r1v.y);
    float4 a0 = make_float4(g0.x * al0, g0.y * al0, g1.x * al0, g1.y * al0);
    float4 a1 = make_float4(g2.x * al1, g2.y * al1, g3.x * al1, g3.y * al1);

    int j0 = rowoff[w], j1 = rowoff[w + 1];
    // prefetch edge j0 payload
    int sA = (j0 < j1) ? csrsrc[j0] : 0;
    float4 eA = *(const float4*)(es + sA * 4);
    const __half* spA = h + (size_t)sA * 256;
    uint2 vA0 = *(const uint2*)(spA + c0);
    uint2 vA1 = *(const uint2*)(spA + c0 + 128);

    for (int j = j0; j < j1; j++) {
        // issue next edge's loads before this edge's math
        int sB = (j + 1 < j1) ? csrsrc[j + 1] : 0;
        float4 eB = *(const float4*)(es + sB * 4);
        const __half* spB = h + (size_t)sB * 256;
        uint2 vB0 = *(const uint2*)(spB + c0);
        uint2 vB1 = *(const uint2*)(spB + c0 + 128);

        float ee = sel4(eA, myh) + edh;
        ee = ee > 0.f ? ee : 0.2f * ee;
        float wj = __expf(ee);
        den += wj;
        float b0 = __shfl_sync(0xffffffffu, wj, hs);
        float b1 = __shfl_sync(0xffffffffu, wj, 2 + hs);
        float2 p0 = h2f(vA0.x), p1 = h2f(vA0.y), p2 = h2f(vA1.x), p3 = h2f(vA1.y);
        a0.x += b0 * p0.x; a0.y += b0 * p0.y; a0.z += b0 * p1.x; a0.w += b0 * p1.y;
        a1.x += b1 * p2.x; a1.y += b1 * p2.y; a1.z += b1 * p3.x; a1.w += b1 * p3.y;

        eA = eB; vA0 = vB0; vA1 = vB1;
    }
    float inv0 = __fdividef(1.f, __shfl_sync(0xffffffffu, den, hs));
    float inv1 = __fdividef(1.f, __shfl_sync(0xffffffffu, den, 2 + hs));

    float4 bb0 = *(const float4*)(b + c0);
    float4 bb1 = *(const float4*)(b + c0 + 128);
    float f0[4] = {a0.x * inv0 + bb0.x, a0.y * inv0 + bb0.y,
                   a0.z * inv0 + bb0.z, a0.w * inv0 + bb0.w};
    float f1[4] = {a1.x * inv1 + bb1.x, a1.y * inv1 + bb1.y,
                   a1.z * inv1 + bb1.z, a1.w * inv1 + bb1.w};
#pragma unroll
    for (int k = 0; k < 4; k++) {
        f0[k] = f0[k] > 0.f ? f0[k] : expm1f(f0[k]);
        f1[k] = f1[k] > 0.f ? f1[k] : expm1f(f1[k]);
    }
    size_t o = (size_t)w * 256 + c0;
    *(uint2*)(Hf + o)       = make_uint2(hpack(f0[0], f0[1]), hpack(f0[2], f0[3]));
    *(uint2*)(Hf + o + 128) = make_uint2(hpack(f1[0], f1[1]), hpack(f1[2], f1[3]));
}

// ===========================================================================
// agg_gather1 + classifier, depth-1 software-pipelined edge loop
// ===========================================================================
__global__ void agg_gather1(const int* __restrict__ rowoff, const int* __restrict__ csrsrc,
                            const float* __restrict__ es, const float* __restrict__ ed,
                            const __half* __restrict__ h, const float* __restrict__ b3,
                            const float* __restrict__ Wc, const float* __restrict__ bc,
                            float* __restrict__ out, int n) {
    int w = (blockIdx.x * blockDim.x + threadIdx.x) >> 5;
    int lane = threadIdx.x & 31;
    if (w >= n) return;
    float edw = ed[w];
    float e = es[w] + edw;
    e = e > 0.f ? e : 0.2f * e;
    float wv = __expf(e);
    float den = wv;
    float2 hv = h2f(*(const uint32_t*)(h + (size_t)w * 64 + lane * 2));
    float v0 = hv.x * wv;
    float v1 = hv.y * wv;

    int j0 = rowoff[w], j1 = rowoff[w + 1];
    int sA = (j0 < j1) ? csrsrc[j0] : 0;
    float eAs = es[sA];
    uint32_t hA = *(const uint32_t*)(h + (size_t)sA * 64 + lane * 2);
    for (int j = j0; j < j1; j++) {
        int sB = (j + 1 < j1) ? csrsrc[j + 1] : 0;
        float eBs = es[sB];
        uint32_t hB = *(const uint32_t*)(h + (size_t)sB * 64 + lane * 2);

        float ee = eAs + edw;
        ee = ee > 0.f ? ee : 0.2f * ee;
        float wj = __expf(ee);
        den += wj;
        float2 sv = h2f(hA);
        v0 += wj * sv.x;
        v1 += wj * sv.y;

        eAs = eBs; hA = hB;
    }
    float inv = __fdividef(1.f, den);
    v0 = v0 * inv + b3[lane * 2];
    v0 = v0 > 0.f ? v0 : expm1f(v0);
    v1 = v1 * inv + b3[lane * 2 + 1];
    v1 = v1 > 0.f ? v1 : expm1f(v1);
#pragma unroll
    for (int j = 0; j < 3; j++) {
        float p = v0 * Wc[(lane * 2) * 3 + j] + v1 * Wc[(lane * 2 + 1) * 3 + j];
#pragma unroll
        for (int o = 16; o; o >>= 1) p += __shfl_xor_sync(0xffffffffu, p, o);
        if (lane == 0) out[w * 3 + j] = p + bc[j];
    }
}

// ===========================================================================
// W [K,N] fp32 -> fp16 [N,Kp] via 32x32 smem transpose
// ===========================================================================
__global__ void conv_wT_h(const float* __restrict__ W,
                          __half* __restrict__ Bh, int K, int N, int Kp) {
    __shared__ float tile[32][33];
    const int kb = blockIdx.x * 32, nb = blockIdx.y * 32;
    const int tx = threadIdx.x, ty = threadIdx.y;
#pragma unroll
    for (int j = 0; j < 4; j++) {
        int k = kb + ty + j * 8, nn = nb + tx;
        tile[ty + j * 8][tx] = (k < K && nn < N) ? W[(size_t)k * N + nn] : 0.f;
    }
    __syncthreads();
#pragma unroll
    for (int j = 0; j < 4; j++) {
        int nn = nb + ty + j * 8, k = kb + tx;
        if (nn < N && k < Kp)
            Bh[(size_t)nn * Kp + k] = __float2half_rn(tile[tx][ty + j * 8]);
    }
}

// ===========================================================================
static inline int cdiv(int a, int b) { return (a + b - 1) / b; }

extern "C" void kernel_launch(void* const* d_in, const int* in_sizes, int n_in,
                              void* d_out, int out_size) {
    const float* x    = (const float*)d_in[0];
    const float* W1   = (const float*)d_in[1];
    const float* a1s  = (const float*)d_in[2];
    const float* a1d  = (const float*)d_in[3];
    const float* b1   = (const float*)d_in[4];
    const float* W2   = (const float*)d_in[5];
    const float* a2s  = (const float*)d_in[6];
    const float* a2d  = (const float*)d_in[7];
    const float* b2   = (const float*)d_in[8];
    const float* W3   = (const float*)d_in[9];
    const float* a3s  = (const float*)d_in[10];
    const float* a3d  = (const float*)d_in[11];
    const float* b3   = (const float*)d_in[12];
    const float* Wc   = (const float*)d_in[13];
    const float* bc   = (const float*)d_in[14];
    const int*   ei   = (const int*)d_in[15];
    float* out = (float*)d_out;

    const int N = GAT_N, E = GAT_E, Mp = GAT_Mp;
    const int* src = ei;
    const int* dst = ei + E;

    float *es, *ed;
    int *rowoff, *cursor, *csrsrc;
    __half *hAh, *h3h, *Afp, *W1hp, *W2hp, *W3hp;
    cudaGetSymbolAddress((void**)&hAh,    g_hA);
    cudaGetSymbolAddress((void**)&h3h,    g_h3);
    cudaGetSymbolAddress((void**)&es,     g_es);
    cudaGetSymbolAddress((void**)&ed,     g_ed);
    cudaGetSymbolAddress((void**)&rowoff, g_rowoff);
    cudaGetSymbolAddress((void**)&cursor, g_cursor);
    cudaGetSymbolAddress((void**)&csrsrc, g_csrsrc);
    cudaGetSymbolAddress((void**)&Afp,    g_Af);
    cudaGetSymbolAddress((void**)&W1hp,   g_W1h);
    cudaGetSymbolAddress((void**)&W2hp,   g_W2h);
    cudaGetSymbolAddress((void**)&W3hp,   g_W3h);

    const int SMF   = 73728;
    const int SM128 = 2 * (8192 + 128 * 64);
    const int SM64  = 2 * (8192 + 64 * 64);
    cudaFuncSetAttribute(gemm_fused, cudaFuncAttributeMaxDynamicSharedMemorySize, SMF);
    cudaFuncSetAttribute(gemm_h<128, true>,
                         cudaFuncAttributeMaxDynamicSharedMemorySize, SM128);
    cudaFuncSetAttribute(gemm_h<64, false>,
                         cudaFuncAttributeMaxDynamicSharedMemorySize, SM64);

    const int TB = 256;
    const int MT = Mp / 128;               // 235
    const int NPB = cdiv(N * 32, TB);
    const int GPB = cdiv(Mp * 32, TB);

    // ---------------- CSR build (vectorized) ----------------
    csr_zero<<<cdiv(N / 4, TB), TB>>>((int4*)cursor, N / 4);
    csr_hist<<<cdiv(E / 4, TB), TB>>>(dst, cursor, E);
    csr_scan<<<1, 1024>>>(cursor, rowoff, N);
    csr_fill<<<cdiv(E / 4, TB), TB>>>(src, dst, cursor, csrsrc, E);

    // ---------------- layer 1 (H=4, K=5000) ----------------
    conv_wT_h<<<dim3(cdiv(GAT_K1P, 32), 8), dim3(32, 8)>>>(W1, W1hp, GAT_DIN, 256, GAT_K1P);
    gemm_fused<<<dim3(2, MT), 256, SMF>>>(x, W1hp, hAh, a1s, a1d, es, ed,
                                          N, GAT_DIN, GAT_K1P);
    agg_gather4<<<GPB, TB>>>(rowoff, csrsrc, es, ed, hAh, b1, Afp, N, Mp);

    // ---------------- layer 2 (H=4, K=256) ----------------
    conv_wT_h<<<dim3(8, 8), dim3(32, 8)>>>(W2, W2hp, 256, 256, 256);
    gemm_h<128, true><<<dim3(2, MT), 256, SM128>>>(Afp, W2hp, hAh, a2s, a2d, es, ed,
                                                   N, 256, 256);
    agg_gather4<<<GPB, TB>>>(rowoff, csrsrc, es, ed, hAh, b2, Afp, N, Mp);

    // ---------------- layer 3 (H=1, K=256, N=64) ----------------
    conv_wT_h<<<dim3(8, 2), dim3(32, 8)>>>(W3, W3hp, 256, 64, 256);
    gemm_h<64, false><<<dim3(1, MT), 256, SM64>>>(Afp, W3hp, h3h,
                                                  nullptr, nullptr, nullptr, nullptr,
                                                  N, 64, 256);
    es_ed1<<<NPB, TB>>>(h3h, a3s, a3d, es, ed, N);
    agg_gather1<<<NPB, TB>>>(rowoff, csrsrc, es, ed, h3h, b3, Wc, bc, out, N);
}